// round 1
// baseline (speedup 1.0000x reference)
#include <cuda_runtime.h>
#include <math.h>

// Problem constants
#define BQ 2
#define LQ 2048
#define DQ 512
#define DI 1024
#define BL (BQ*LQ)          // 4096 rows
#define DSTATE 16
#define NG 8

// ---------------- device scratch (allocation-free rule: __device__ globals) ---
__device__ float g_u[BL*DQ];                 // LN(LN(x))
__device__ float g_xz[(size_t)BL*2048];      // in_proj output (xm | z)
__device__ float g_xc[(size_t)BL*DI];        // conv+silu
__device__ float g_dbc[BL*64];               // x_proj output (delta_raw|B|C)
__device__ float g_delta[(size_t)BL*DI];     // softplus(dt_proj)
__device__ float g_yfull[(size_t)BL*DI];     // (scan_y + D*xc) * silu(z)
__device__ float g_x2[BL*DQ];                // x + mix (mixer residual)
__device__ float g_k[BL*DQ];                 // LN(LN(x2))
__device__ float g_basis[(size_t)BL*(DQ*NG)];// KAN basis, 64 MB

// ---------------- block reduction helper --------------------------------------
__device__ __forceinline__ float block_sum(float v, float* sbuf) {
    #pragma unroll
    for (int o = 16; o > 0; o >>= 1) v += __shfl_xor_sync(0xffffffffu, v, o);
    int lane = threadIdx.x & 31, w = threadIdx.x >> 5;
    if (lane == 0) sbuf[w] = v;
    __syncthreads();
    if (w == 0) {
        v = (lane < ((int)blockDim.x >> 5)) ? sbuf[lane] : 0.f;
        #pragma unroll
        for (int o = 8; o > 0; o >>= 1) v += __shfl_xor_sync(0xffffffffu, v, o);
        if (lane == 0) sbuf[0] = v;
    }
    __syncthreads();
    v = sbuf[0];
    __syncthreads();
    return v;
}

// ---------------- double layernorm (LN then LN), row length 512 ---------------
__global__ void ln2_kernel(const float* __restrict__ x,
                           const float* __restrict__ w1, const float* __restrict__ b1,
                           const float* __restrict__ w2, const float* __restrict__ b2,
                           float* __restrict__ out) {
    __shared__ float sbuf[32];
    int row = blockIdx.x;
    int t = threadIdx.x;
    float v = x[(size_t)row * DQ + t];

    float mu  = block_sum(v, sbuf) * (1.f / DQ);
    float d   = v - mu;
    float var = block_sum(d * d, sbuf) * (1.f / DQ);
    float y   = d * rsqrtf(var + 1e-5f) * w1[t] + b1[t];

    mu  = block_sum(y, sbuf) * (1.f / DQ);
    d   = y - mu;
    var = block_sum(d * d, sbuf) * (1.f / DQ);
    out[(size_t)row * DQ + t] = d * rsqrtf(var + 1e-5f) * w2[t] + b2[t];
}

// ---------------- generic NT SGEMM: C[M,N] = A[M,K] * B[N,K]^T (+epilogue) ----
// EPI bits: 1 = add bias[col], 2 = add resid[row*N+col], 4 = softplus activation
#define EPI_BIAS 1
#define EPI_RESID 2
#define EPI_SOFTPLUS 4

template<int EPI>
__global__ __launch_bounds__(256)
void sgemm_nt(const float* __restrict__ A, const float* __restrict__ B,
              const float* __restrict__ bias, const float* __restrict__ resid,
              float* __restrict__ C, int M, int N, int K, int lda, int ldb) {
    const int TM = 128, TN = 128, TK = 16;
    __shared__ __align__(16) float As[TK][TM + 4];
    __shared__ __align__(16) float Bs[TK][TN + 4];

    int tid = threadIdx.x;
    int bm = blockIdx.y * TM;
    int bn = blockIdx.x * TN;

    int arow = tid >> 2;          // 0..63
    int acol = (tid & 3) << 2;    // 0,4,8,12

    int tmb = (tid >> 4) << 3;    // thread tile row base 0..120
    int tnb = (tid & 15) << 3;    // thread tile col base 0..120

    float acc[8][8];
    #pragma unroll
    for (int i = 0; i < 8; i++)
        #pragma unroll
        for (int j = 0; j < 8; j++) acc[i][j] = 0.f;

    for (int k0 = 0; k0 < K; k0 += TK) {
        #pragma unroll
        for (int h = 0; h < 2; h++) {
            int r = arow + h * 64;
            float4 av = *(const float4*)(A + (size_t)(bm + r) * lda + k0 + acol);
            As[acol + 0][r] = av.x; As[acol + 1][r] = av.y;
            As[acol + 2][r] = av.z; As[acol + 3][r] = av.w;
        }
        #pragma unroll
        for (int h = 0; h < 2; h++) {
            int r = arow + h * 64;
            float4 bv = make_float4(0.f, 0.f, 0.f, 0.f);
            if (bn + r < N)
                bv = *(const float4*)(B + (size_t)(bn + r) * ldb + k0 + acol);
            Bs[acol + 0][r] = bv.x; Bs[acol + 1][r] = bv.y;
            Bs[acol + 2][r] = bv.z; Bs[acol + 3][r] = bv.w;
        }
        __syncthreads();

        #pragma unroll
        for (int kk = 0; kk < TK; kk++) {
            float a[8], b[8];
            float4 a0 = *(const float4*)&As[kk][tmb];
            float4 a1 = *(const float4*)&As[kk][tmb + 4];
            float4 b0 = *(const float4*)&Bs[kk][tnb];
            float4 b1 = *(const float4*)&Bs[kk][tnb + 4];
            a[0]=a0.x;a[1]=a0.y;a[2]=a0.z;a[3]=a0.w;a[4]=a1.x;a[5]=a1.y;a[6]=a1.z;a[7]=a1.w;
            b[0]=b0.x;b[1]=b0.y;b[2]=b0.z;b[3]=b0.w;b[4]=b1.x;b[5]=b1.y;b[6]=b1.z;b[7]=b1.w;
            #pragma unroll
            for (int i = 0; i < 8; i++)
                #pragma unroll
                for (int j = 0; j < 8; j++)
                    acc[i][j] = fmaf(a[i], b[j], acc[i][j]);
        }
        __syncthreads();
    }

    #pragma unroll
    for (int i = 0; i < 8; i++) {
        int row = bm + tmb + i;
        #pragma unroll
        for (int j = 0; j < 8; j++) {
            int col = bn + tnb + j;
            if (col < N) {
                float v = acc[i][j];
                if (EPI & EPI_BIAS)     v += bias[col];
                if (EPI & EPI_SOFTPLUS) v = (v > 20.f) ? v : log1pf(__expf(v));
                if (EPI & EPI_RESID)    v += resid[(size_t)row * N + col];
                C[(size_t)row * N + col] = v;
            }
        }
    }
}

// ---------------- causal depthwise conv (k=4) + silu --------------------------
__global__ void conv_silu_kernel(const float* __restrict__ xz,
                                 const float* __restrict__ cw,
                                 const float* __restrict__ cb,
                                 float* __restrict__ xc) {
    int idx = blockIdx.x * blockDim.x + threadIdx.x;
    if (idx >= BL * DI) return;
    int d = idx & (DI - 1);
    int row = idx >> 10;
    int l = row & (LQ - 1);
    float s = cb[d];
    #pragma unroll
    for (int j = 0; j < 4; j++) {
        int lp = l - 3 + j;
        if (lp >= 0)
            s = fmaf(xz[(size_t)(row - 3 + j) * 2048 + d], cw[d * 4 + j], s);
    }
    float sig = 1.f / (1.f + __expf(-s));
    xc[idx] = s * sig;
}

// ---------------- selective scan --------------------------------------------
// lane = (local_channel<<4) | state; each half-warp owns one channel's 16 states.
__global__ void scan_kernel(const float* __restrict__ delta_sp,
                            const float* __restrict__ xc,
                            const float* __restrict__ dbc,
                            const float* __restrict__ xz,
                            const float* __restrict__ A_log,
                            const float* __restrict__ D_param,
                            float* __restrict__ yfull) {
    int tid = threadIdx.x;
    int lane = tid & 31;
    int warp = tid >> 5;
    int n  = lane & 15;
    int cw = lane >> 4;
    int ch = blockIdx.x * 16 + warp * 2 + cw;   // 0..2047
    int b = ch >> 10;
    int d = ch & (DI - 1);

    float An = -__expf(A_log[d * DSTATE + n]);
    float Dp = D_param[d];
    float h = 0.f;
    size_t rbase = (size_t)b * LQ;

    for (int t = 0; t < LQ; t++) {
        size_t row = rbase + t;
        float dl = delta_sp[row * DI + d];
        float xv = xc[row * DI + d];
        float Bn = dbc[row * 64 + 32 + n];
        float Cn = dbc[row * 64 + 48 + n];
        float dA = __expf(dl * An);
        h = fmaf(dA, h, dl * Bn * xv);
        float p = h * Cn;
        p += __shfl_xor_sync(0xffffffffu, p, 1);
        p += __shfl_xor_sync(0xffffffffu, p, 2);
        p += __shfl_xor_sync(0xffffffffu, p, 4);
        p += __shfl_xor_sync(0xffffffffu, p, 8);
        if (n == 0) {
            float z = xz[row * 2048 + DI + d];
            float sz = z / (1.f + __expf(-z));
            yfull[row * DI + d] = (p + Dp * xv) * sz;
        }
    }
}

// ---------------- KAN basis: 1 - tanh^2((k - grid_g)/0.33) -------------------
__global__ void basis_kernel(const float* __restrict__ k,
                             const float* __restrict__ grid,
                             float* __restrict__ basis) {
    int idx = blockIdx.x * blockDim.x + threadIdx.x;
    if (idx >= BL * DQ * NG) return;
    int j = idx & (DQ * NG - 1);
    int row = idx >> 12;
    int d = j >> 3, g = j & 7;
    float t = tanhf((k[(size_t)row * DQ + d] - grid[g]) * (float)(1.0 / 0.33));
    basis[idx] = 1.f - t * t;
}

// ---------------- host orchestration ----------------------------------------
extern "C" void kernel_launch(void* const* d_in, const int* in_sizes, int n_in,
                              void* d_out, int out_size) {
    const float* x      = (const float*)d_in[0];
    const float* n1_w   = (const float*)d_in[1];
    const float* n1_b   = (const float*)d_in[2];
    const float* mn_w   = (const float*)d_in[3];
    const float* mn_b   = (const float*)d_in[4];
    const float* in_w   = (const float*)d_in[5];
    const float* in_b   = (const float*)d_in[6];
    const float* conv_w = (const float*)d_in[7];
    const float* conv_b = (const float*)d_in[8];
    const float* xp_w   = (const float*)d_in[9];
    const float* dt_w   = (const float*)d_in[10];
    const float* dt_b   = (const float*)d_in[11];
    const float* A_log  = (const float*)d_in[12];
    const float* D_par  = (const float*)d_in[13];
    const float* out_w  = (const float*)d_in[14];
    const float* out_b  = (const float*)d_in[15];
    const float* n2_w   = (const float*)d_in[16];
    const float* n2_b   = (const float*)d_in[17];
    const float* kn_w   = (const float*)d_in[18];
    const float* kn_b   = (const float*)d_in[19];
    const float* grid   = (const float*)d_in[20];
    const float* spl_w  = (const float*)d_in[21];
    float* out = (float*)d_out;

    float *p_u, *p_xz, *p_xc, *p_dbc, *p_delta, *p_yfull, *p_x2, *p_k, *p_basis;
    cudaGetSymbolAddress((void**)&p_u,     g_u);
    cudaGetSymbolAddress((void**)&p_xz,    g_xz);
    cudaGetSymbolAddress((void**)&p_xc,    g_xc);
    cudaGetSymbolAddress((void**)&p_dbc,   g_dbc);
    cudaGetSymbolAddress((void**)&p_delta, g_delta);
    cudaGetSymbolAddress((void**)&p_yfull, g_yfull);
    cudaGetSymbolAddress((void**)&p_x2,    g_x2);
    cudaGetSymbolAddress((void**)&p_k,     g_k);
    cudaGetSymbolAddress((void**)&p_basis, g_basis);

    // 1. u = LN(LN(x, n1), mn)
    ln2_kernel<<<BL, DQ>>>(x, n1_w, n1_b, mn_w, mn_b, p_u);

    // 2. xz = u @ in_w^T + in_b   [4096 x 2048, K=512]
    {
        dim3 grd(2048 / 128, BL / 128);
        sgemm_nt<EPI_BIAS><<<grd, 256>>>(p_u, in_w, in_b, nullptr, p_xz,
                                         BL, 2048, DQ, DQ, DQ);
    }

    // 3. xc = silu(causal depthwise conv(xm) + conv_b)
    conv_silu_kernel<<<(BL * DI) / 256, 256>>>(p_xz, conv_w, conv_b, p_xc);

    // 4. dbc = xc @ xp_w^T        [4096 x 64, K=1024]
    {
        dim3 grd(1, BL / 128);
        sgemm_nt<0><<<grd, 256>>>(p_xc, xp_w, nullptr, nullptr, p_dbc,
                                  BL, 64, DI, DI, DI);
    }

    // 5. delta = softplus(delta_raw @ dt_w^T + dt_b)   [4096 x 1024, K=32]
    {
        dim3 grd(DI / 128, BL / 128);
        sgemm_nt<EPI_BIAS | EPI_SOFTPLUS><<<grd, 256>>>(p_dbc, dt_w, dt_b, nullptr,
                                                        p_delta, BL, DI, 32, 64, 32);
    }

    // 6. selective scan -> yfull = (y + D*xc) * silu(z)
    scan_kernel<<<128, 256>>>(p_delta, p_xc, p_dbc, p_xz, A_log, D_par, p_yfull);

    // 7. x2 = x + yfull @ out_w^T + out_b    [4096 x 512, K=1024]
    {
        dim3 grd(DQ / 128, BL / 128);
        sgemm_nt<EPI_BIAS | EPI_RESID><<<grd, 256>>>(p_yfull, out_w, out_b, x,
                                                     p_x2, BL, DQ, DI, DI, DI);
    }

    // 8. k = LN(LN(x2, n2), kn)
    ln2_kernel<<<BL, DQ>>>(p_x2, n2_w, n2_b, kn_w, kn_b, p_k);

    // 9. basis = 1 - tanh^2((k - grid)/0.33)  [4096 x 4096]
    basis_kernel<<<(BL * DQ * NG) / 256, 256>>>(p_k, grid, p_basis);

    // 10. out = x2 + basis @ spl_w^T          [4096 x 512, K=4096]
    {
        dim3 grd(DQ / 128, BL / 128);
        sgemm_nt<EPI_RESID><<<grd, 256>>>(p_basis, spl_w, nullptr, p_x2, out,
                                          BL, DQ, DQ * NG, DQ * NG, DQ * NG);
    }
    (void)in_sizes; (void)n_in; (void)out_size;
}

// round 2
// speedup vs baseline: 1.3239x; 1.3239x over previous
#include <cuda_runtime.h>
#include <math.h>

// Problem constants
#define BQ 2
#define LQ 2048
#define DQ 512
#define DI 1024
#define BL (BQ*LQ)          // 4096 rows
#define DSTATE 16
#define NG 8

// ---------------- device scratch --------------------------------------------
__device__ float g_u[BL*DQ];                 // LN(LN(x))
__device__ float g_xz[(size_t)BL*2048];      // in_proj output (xm | z)
__device__ float g_xc[(size_t)BL*DI];        // conv+silu
__device__ float g_dbc[BL*64];               // x_proj output (delta_raw|B|C)
__device__ float g_delta[(size_t)BL*DI];     // softplus(dt_proj)
__device__ float g_yfull[(size_t)BL*DI];     // (scan_y + D*xc) * silu(z)
__device__ float g_x2[BL*DQ];                // x + mix
__device__ float g_k[BL*DQ];                 // LN(LN(x2))

// ---------------- block reduction helper -------------------------------------
__device__ __forceinline__ float block_sum(float v, float* sbuf) {
    #pragma unroll
    for (int o = 16; o > 0; o >>= 1) v += __shfl_xor_sync(0xffffffffu, v, o);
    int lane = threadIdx.x & 31, w = threadIdx.x >> 5;
    if (lane == 0) sbuf[w] = v;
    __syncthreads();
    if (w == 0) {
        v = (lane < ((int)blockDim.x >> 5)) ? sbuf[lane] : 0.f;
        #pragma unroll
        for (int o = 8; o > 0; o >>= 1) v += __shfl_xor_sync(0xffffffffu, v, o);
        if (lane == 0) sbuf[0] = v;
    }
    __syncthreads();
    v = sbuf[0];
    __syncthreads();
    return v;
}

// ---------------- double layernorm, row length 512 ----------------------------
__global__ void ln2_kernel(const float* __restrict__ x,
                           const float* __restrict__ w1, const float* __restrict__ b1,
                           const float* __restrict__ w2, const float* __restrict__ b2,
                           float* __restrict__ out) {
    __shared__ float sbuf[32];
    int row = blockIdx.x;
    int t = threadIdx.x;
    float v = x[(size_t)row * DQ + t];

    float mu  = block_sum(v, sbuf) * (1.f / DQ);
    float d   = v - mu;
    float var = block_sum(d * d, sbuf) * (1.f / DQ);
    float y   = d * rsqrtf(var + 1e-5f) * w1[t] + b1[t];

    mu  = block_sum(y, sbuf) * (1.f / DQ);
    d   = y - mu;
    var = block_sum(d * d, sbuf) * (1.f / DQ);
    out[(size_t)row * DQ + t] = d * rsqrtf(var + 1e-5f) * w2[t] + b2[t];
}

// ---------------- epilogue flag bits -----------------------------------------
#define EPI_BIAS 1
#define EPI_RESID 2
#define EPI_SOFTPLUS 4

__device__ __forceinline__ float epi_apply(float v, int col, size_t row, int N,
                                           int EPI, const float* bias,
                                           const float* resid) {
    if (EPI & EPI_BIAS)     v += bias[col];
    if (EPI & EPI_SOFTPLUS) v = (v > 20.f) ? v : log1pf(__expf(v));
    if (EPI & EPI_RESID)    v += resid[row * N + col];
    return v;
}

// ---------------- 128x128 double-buffered NT SGEMM ----------------------------
// C[M,N] = A[M,K] * B[N,K]^T. Requires M%128==0, N%128==0, K%16==0.
template<int EPI>
__global__ __launch_bounds__(256, 2)
void sgemm128(const float* __restrict__ A, const float* __restrict__ B,
              const float* __restrict__ bias, const float* __restrict__ resid,
              float* __restrict__ C, int N, int K, int lda, int ldb) {
    const int TK = 16;
    __shared__ __align__(16) float As[2][TK][128 + 4];
    __shared__ __align__(16) float Bs[2][TK][128 + 4];

    int tid = threadIdx.x;
    int bm = blockIdx.y * 128;
    int bn = blockIdx.x * 128;

    int arow = tid >> 2;          // 0..63
    int acol = (tid & 3) << 2;    // 0,4,8,12
    int tmb = (tid >> 4) << 3;
    int tnb = (tid & 15) << 3;

    const float* Ap0 = A + (size_t)(bm + arow) * lda + acol;
    const float* Ap1 = A + (size_t)(bm + arow + 64) * lda + acol;
    const float* Bp0 = B + (size_t)(bn + arow) * ldb + acol;
    const float* Bp1 = B + (size_t)(bn + arow + 64) * ldb + acol;

    float4 ra0 = *(const float4*)(Ap0);
    float4 ra1 = *(const float4*)(Ap1);
    float4 rb0 = *(const float4*)(Bp0);
    float4 rb1 = *(const float4*)(Bp1);
    {
        As[0][acol+0][arow] = ra0.x; As[0][acol+1][arow] = ra0.y;
        As[0][acol+2][arow] = ra0.z; As[0][acol+3][arow] = ra0.w;
        As[0][acol+0][arow+64] = ra1.x; As[0][acol+1][arow+64] = ra1.y;
        As[0][acol+2][arow+64] = ra1.z; As[0][acol+3][arow+64] = ra1.w;
        Bs[0][acol+0][arow] = rb0.x; Bs[0][acol+1][arow] = rb0.y;
        Bs[0][acol+2][arow] = rb0.z; Bs[0][acol+3][arow] = rb0.w;
        Bs[0][acol+0][arow+64] = rb1.x; Bs[0][acol+1][arow+64] = rb1.y;
        Bs[0][acol+2][arow+64] = rb1.z; Bs[0][acol+3][arow+64] = rb1.w;
    }
    __syncthreads();

    float acc[8][8];
    #pragma unroll
    for (int i = 0; i < 8; i++)
        #pragma unroll
        for (int j = 0; j < 8; j++) acc[i][j] = 0.f;

    int nk = K / TK;
    for (int it = 0; it < nk; it++) {
        int cur = it & 1, nxt = cur ^ 1;
        bool more = (it + 1 < nk);
        if (more) {
            int ko = (it + 1) * TK;
            ra0 = *(const float4*)(Ap0 + ko);
            ra1 = *(const float4*)(Ap1 + ko);
            rb0 = *(const float4*)(Bp0 + ko);
            rb1 = *(const float4*)(Bp1 + ko);
        }
        #pragma unroll
        for (int kk = 0; kk < TK; kk++) {
            float a[8], b[8];
            float4 a0 = *(const float4*)&As[cur][kk][tmb];
            float4 a1 = *(const float4*)&As[cur][kk][tmb + 4];
            float4 b0 = *(const float4*)&Bs[cur][kk][tnb];
            float4 b1 = *(const float4*)&Bs[cur][kk][tnb + 4];
            a[0]=a0.x;a[1]=a0.y;a[2]=a0.z;a[3]=a0.w;a[4]=a1.x;a[5]=a1.y;a[6]=a1.z;a[7]=a1.w;
            b[0]=b0.x;b[1]=b0.y;b[2]=b0.z;b[3]=b0.w;b[4]=b1.x;b[5]=b1.y;b[6]=b1.z;b[7]=b1.w;
            #pragma unroll
            for (int i = 0; i < 8; i++)
                #pragma unroll
                for (int j = 0; j < 8; j++)
                    acc[i][j] = fmaf(a[i], b[j], acc[i][j]);
        }
        if (more) {
            As[nxt][acol+0][arow] = ra0.x; As[nxt][acol+1][arow] = ra0.y;
            As[nxt][acol+2][arow] = ra0.z; As[nxt][acol+3][arow] = ra0.w;
            As[nxt][acol+0][arow+64] = ra1.x; As[nxt][acol+1][arow+64] = ra1.y;
            As[nxt][acol+2][arow+64] = ra1.z; As[nxt][acol+3][arow+64] = ra1.w;
            Bs[nxt][acol+0][arow] = rb0.x; Bs[nxt][acol+1][arow] = rb0.y;
            Bs[nxt][acol+2][arow] = rb0.z; Bs[nxt][acol+3][arow] = rb0.w;
            Bs[nxt][acol+0][arow+64] = rb1.x; Bs[nxt][acol+1][arow+64] = rb1.y;
            Bs[nxt][acol+2][arow+64] = rb1.z; Bs[nxt][acol+3][arow+64] = rb1.w;
        }
        __syncthreads();
    }

    #pragma unroll
    for (int i = 0; i < 8; i++) {
        size_t row = bm + tmb + i;
        #pragma unroll
        for (int j = 0; j < 8; j++) {
            int col = bn + tnb + j;
            C[row * N + col] = epi_apply(acc[i][j], col, row, N, EPI, bias, resid);
        }
    }
}

// ---------------- 64x128 double-buffered NT SGEMM (optional fused KAN basis) --
// If KANA: A is k-matrix [M,512]; logical A[row, kc] = sech2((k[row,kc>>3]-grid[kc&7])/0.33)
template<int EPI, bool KANA>
__global__ __launch_bounds__(256)
void sgemm64(const float* __restrict__ A, const float* __restrict__ B,
             const float* __restrict__ bias, const float* __restrict__ resid,
             const float* __restrict__ grd, float* __restrict__ C,
             int N, int K, int lda, int ldb) {
    const int TK = 16;
    __shared__ __align__(16) float As[2][TK][64 + 4];
    __shared__ __align__(16) float Bs[2][TK][128 + 4];

    int tid = threadIdx.x;
    int bm = blockIdx.y * 64;
    int bn = blockIdx.x * 128;

    int arow = tid >> 2;          // 0..63
    int acol = (tid & 3) << 2;
    int tmb = (tid >> 4) << 2;    // 0..60, 4 rows per thread
    int tnb = (tid & 15) << 3;

    float4 glo = make_float4(0.f,0.f,0.f,0.f), ghi = glo;
    if (KANA) {
        glo = make_float4(__ldg(grd+0), __ldg(grd+1), __ldg(grd+2), __ldg(grd+3));
        ghi = make_float4(__ldg(grd+4), __ldg(grd+5), __ldg(grd+6), __ldg(grd+7));
    }
    const float INV = 1.0f / 0.33f;

    const float* Bp0 = B + (size_t)(bn + arow) * ldb + acol;
    const float* Bp1 = B + (size_t)(bn + arow + 64) * ldb + acol;
    const float* Ap  = KANA ? nullptr : (A + (size_t)(bm + arow) * lda + acol);
    const float* Kp  = KANA ? (A + (size_t)(bm + arow) * 512) : nullptr;

    // A-tile producer (either global load or on-the-fly basis)
    auto load_a = [&](int ko) -> float4 {
        if (!KANA) return *(const float4*)(Ap + ko);
        int kc0 = ko + acol;
        float kv = Kp[kc0 >> 3];
        float4 g = (kc0 & 4) ? ghi : glo;
        float4 r;
        {
            float s0 = fabsf((kv - g.x) * INV); float e0 = __expf(-2.f * s0);
            float s1 = fabsf((kv - g.y) * INV); float e1 = __expf(-2.f * s1);
            float s2 = fabsf((kv - g.z) * INV); float e2 = __expf(-2.f * s2);
            float s3 = fabsf((kv - g.w) * INV); float e3 = __expf(-2.f * s3);
            r.x = __fdividef(4.f * e0, (1.f + e0) * (1.f + e0));
            r.y = __fdividef(4.f * e1, (1.f + e1) * (1.f + e1));
            r.z = __fdividef(4.f * e2, (1.f + e2) * (1.f + e2));
            r.w = __fdividef(4.f * e3, (1.f + e3) * (1.f + e3));
        }
        return r;
    };

    float4 ra = load_a(0);
    float4 rb0 = *(const float4*)(Bp0);
    float4 rb1 = *(const float4*)(Bp1);
    {
        As[0][acol+0][arow] = ra.x; As[0][acol+1][arow] = ra.y;
        As[0][acol+2][arow] = ra.z; As[0][acol+3][arow] = ra.w;
        Bs[0][acol+0][arow] = rb0.x; Bs[0][acol+1][arow] = rb0.y;
        Bs[0][acol+2][arow] = rb0.z; Bs[0][acol+3][arow] = rb0.w;
        Bs[0][acol+0][arow+64] = rb1.x; Bs[0][acol+1][arow+64] = rb1.y;
        Bs[0][acol+2][arow+64] = rb1.z; Bs[0][acol+3][arow+64] = rb1.w;
    }
    __syncthreads();

    float acc[4][8];
    #pragma unroll
    for (int i = 0; i < 4; i++)
        #pragma unroll
        for (int j = 0; j < 8; j++) acc[i][j] = 0.f;

    int nk = K / TK;
    for (int it = 0; it < nk; it++) {
        int cur = it & 1, nxt = cur ^ 1;
        bool more = (it + 1 < nk);
        if (more) {
            int ko = (it + 1) * TK;
            ra  = load_a(ko);
            rb0 = *(const float4*)(Bp0 + ko);
            rb1 = *(const float4*)(Bp1 + ko);
        }
        #pragma unroll
        for (int kk = 0; kk < TK; kk++) {
            float a[4], b[8];
            float4 a0 = *(const float4*)&As[cur][kk][tmb];
            float4 b0 = *(const float4*)&Bs[cur][kk][tnb];
            float4 b1 = *(const float4*)&Bs[cur][kk][tnb + 4];
            a[0]=a0.x;a[1]=a0.y;a[2]=a0.z;a[3]=a0.w;
            b[0]=b0.x;b[1]=b0.y;b[2]=b0.z;b[3]=b0.w;b[4]=b1.x;b[5]=b1.y;b[6]=b1.z;b[7]=b1.w;
            #pragma unroll
            for (int i = 0; i < 4; i++)
                #pragma unroll
                for (int j = 0; j < 8; j++)
                    acc[i][j] = fmaf(a[i], b[j], acc[i][j]);
        }
        if (more) {
            As[nxt][acol+0][arow] = ra.x; As[nxt][acol+1][arow] = ra.y;
            As[nxt][acol+2][arow] = ra.z; As[nxt][acol+3][arow] = ra.w;
            Bs[nxt][acol+0][arow] = rb0.x; Bs[nxt][acol+1][arow] = rb0.y;
            Bs[nxt][acol+2][arow] = rb0.z; Bs[nxt][acol+3][arow] = rb0.w;
            Bs[nxt][acol+0][arow+64] = rb1.x; Bs[nxt][acol+1][arow+64] = rb1.y;
            Bs[nxt][acol+2][arow+64] = rb1.z; Bs[nxt][acol+3][arow+64] = rb1.w;
        }
        __syncthreads();
    }

    #pragma unroll
    for (int i = 0; i < 4; i++) {
        size_t row = bm + tmb + i;
        #pragma unroll
        for (int j = 0; j < 8; j++) {
            int col = bn + tnb + j;
            C[row * N + col] = epi_apply(acc[i][j], col, row, N, EPI, bias, resid);
        }
    }
}

// ---------------- dedicated x_proj GEMM: [4096,1024] x [64,1024]^T ------------
__global__ __launch_bounds__(256)
void xproj_kernel(const float* __restrict__ A, const float* __restrict__ B,
                  float* __restrict__ C) {
    __shared__ float As[16][34];
    __shared__ float Bs[16][68];
    int tid = threadIdx.x;
    int r0 = blockIdx.x * 32;
    int lrow = tid >> 3;          // 0..31
    int lc = (tid & 7) * 8;       // 0..56

    float acc[8];
    #pragma unroll
    for (int j = 0; j < 8; j++) acc[j] = 0.f;

    for (int k0 = 0; k0 < 1024; k0 += 16) {
        float2 va = *(const float2*)(A + (size_t)(r0 + (tid >> 3)) * 1024 + k0 + (tid & 7) * 2);
        As[(tid & 7) * 2 + 0][tid >> 3] = va.x;
        As[(tid & 7) * 2 + 1][tid >> 3] = va.y;
        float4 vb = *(const float4*)(B + (size_t)(tid >> 2) * 1024 + k0 + (tid & 3) * 4);
        Bs[(tid & 3) * 4 + 0][tid >> 2] = vb.x;
        Bs[(tid & 3) * 4 + 1][tid >> 2] = vb.y;
        Bs[(tid & 3) * 4 + 2][tid >> 2] = vb.z;
        Bs[(tid & 3) * 4 + 3][tid >> 2] = vb.w;
        __syncthreads();
        #pragma unroll
        for (int kk = 0; kk < 16; kk++) {
            float a = As[kk][lrow];
            #pragma unroll
            for (int j = 0; j < 8; j++)
                acc[j] = fmaf(a, Bs[kk][lc + j], acc[j]);
        }
        __syncthreads();
    }
    #pragma unroll
    for (int j = 0; j < 8; j++)
        C[(size_t)(r0 + lrow) * 64 + lc + j] = acc[j];
}

// ---------------- causal depthwise conv (k=4) + silu --------------------------
__global__ void conv_silu_kernel(const float* __restrict__ xz,
                                 const float* __restrict__ cw,
                                 const float* __restrict__ cb,
                                 float* __restrict__ xc) {
    int idx = blockIdx.x * blockDim.x + threadIdx.x;
    if (idx >= BL * DI) return;
    int d = idx & (DI - 1);
    int row = idx >> 10;
    int l = row & (LQ - 1);
    float s = cb[d];
    #pragma unroll
    for (int j = 0; j < 4; j++) {
        int lp = l - 3 + j;
        if (lp >= 0)
            s = fmaf(xz[(size_t)(row - 3 + j) * 2048 + d], cw[d * 4 + j], s);
    }
    float sig = 1.f / (1.f + __expf(-s));
    xc[idx] = s * sig;
}

// ---------------- selective scan (software-prefetched) -----------------------
__global__ void scan_kernel(const float* __restrict__ delta_sp,
                            const float* __restrict__ xc,
                            const float* __restrict__ dbc,
                            const float* __restrict__ xz,
                            const float* __restrict__ A_log,
                            const float* __restrict__ D_param,
                            float* __restrict__ yfull) {
    int tid = threadIdx.x;
    int lane = tid & 31;
    int warp = tid >> 5;
    int n  = lane & 15;
    int cw = lane >> 4;
    int ch = blockIdx.x * 16 + warp * 2 + cw;   // 0..2047
    int b = ch >> 10;
    int d = ch & (DI - 1);

    float An = -__expf(A_log[d * DSTATE + n]);
    float Dp = D_param[d];
    float h = 0.f;
    size_t rbase = (size_t)b * LQ;

    // prefetch t=0
    size_t r = rbase;
    float dl = delta_sp[r * DI + d];
    float xv = xc[r * DI + d];
    float Bn = dbc[r * 64 + 32 + n];
    float Cn = dbc[r * 64 + 48 + n];
    float zv = xz[r * 2048 + DI + d];

    for (int t = 0; t < LQ; t++) {
        float dl2 = 0.f, xv2 = 0.f, Bn2 = 0.f, Cn2 = 0.f, zv2 = 0.f;
        if (t + 1 < LQ) {
            size_t r2 = rbase + t + 1;
            dl2 = delta_sp[r2 * DI + d];
            xv2 = xc[r2 * DI + d];
            Bn2 = dbc[r2 * 64 + 32 + n];
            Cn2 = dbc[r2 * 64 + 48 + n];
            zv2 = xz[r2 * 2048 + DI + d];
        }
        size_t row = rbase + t;
        float dA = __expf(dl * An);
        h = fmaf(dA, h, dl * Bn * xv);
        float p = h * Cn;
        p += __shfl_xor_sync(0xffffffffu, p, 1);
        p += __shfl_xor_sync(0xffffffffu, p, 2);
        p += __shfl_xor_sync(0xffffffffu, p, 4);
        p += __shfl_xor_sync(0xffffffffu, p, 8);
        if (n == 0) {
            float sz = zv / (1.f + __expf(-zv));
            yfull[row * DI + d] = (p + Dp * xv) * sz;
        }
        dl = dl2; xv = xv2; Bn = Bn2; Cn = Cn2; zv = zv2;
    }
}

// ---------------- host orchestration -----------------------------------------
extern "C" void kernel_launch(void* const* d_in, const int* in_sizes, int n_in,
                              void* d_out, int out_size) {
    const float* x      = (const float*)d_in[0];
    const float* n1_w   = (const float*)d_in[1];
    const float* n1_b   = (const float*)d_in[2];
    const float* mn_w   = (const float*)d_in[3];
    const float* mn_b   = (const float*)d_in[4];
    const float* in_w   = (const float*)d_in[5];
    const float* in_b   = (const float*)d_in[6];
    const float* conv_w = (const float*)d_in[7];
    const float* conv_b = (const float*)d_in[8];
    const float* xp_w   = (const float*)d_in[9];
    const float* dt_w   = (const float*)d_in[10];
    const float* dt_b   = (const float*)d_in[11];
    const float* A_log  = (const float*)d_in[12];
    const float* D_par  = (const float*)d_in[13];
    const float* out_w  = (const float*)d_in[14];
    const float* out_b  = (const float*)d_in[15];
    const float* n2_w   = (const float*)d_in[16];
    const float* n2_b   = (const float*)d_in[17];
    const float* kn_w   = (const float*)d_in[18];
    const float* kn_b   = (const float*)d_in[19];
    const float* grid   = (const float*)d_in[20];
    const float* spl_w  = (const float*)d_in[21];
    float* out = (float*)d_out;

    float *p_u, *p_xz, *p_xc, *p_dbc, *p_delta, *p_yfull, *p_x2, *p_k;
    cudaGetSymbolAddress((void**)&p_u,     g_u);
    cudaGetSymbolAddress((void**)&p_xz,    g_xz);
    cudaGetSymbolAddress((void**)&p_xc,    g_xc);
    cudaGetSymbolAddress((void**)&p_dbc,   g_dbc);
    cudaGetSymbolAddress((void**)&p_delta, g_delta);
    cudaGetSymbolAddress((void**)&p_yfull, g_yfull);
    cudaGetSymbolAddress((void**)&p_x2,    g_x2);
    cudaGetSymbolAddress((void**)&p_k,     g_k);

    // 1. u = LN(LN(x, n1), mn)
    ln2_kernel<<<BL, DQ>>>(x, n1_w, n1_b, mn_w, mn_b, p_u);

    // 2. xz = u @ in_w^T + in_b   [4096 x 2048, K=512]
    {
        dim3 grd(2048 / 128, BL / 128);
        sgemm128<EPI_BIAS><<<grd, 256>>>(p_u, in_w, in_b, nullptr, p_xz,
                                         2048, DQ, DQ, DQ);
    }

    // 3. xc = silu(causal depthwise conv(xm) + conv_b)
    conv_silu_kernel<<<(BL * DI) / 256, 256>>>(p_xz, conv_w, conv_b, p_xc);

    // 4. dbc = xc @ xp_w^T        [4096 x 64, K=1024]
    xproj_kernel<<<BL / 32, 256>>>(p_xc, xp_w, p_dbc);

    // 5. delta = softplus(delta_raw @ dt_w^T + dt_b)   [4096 x 1024, K=32]
    {
        dim3 grd(DI / 128, BL / 128);
        sgemm128<EPI_BIAS | EPI_SOFTPLUS><<<grd, 256>>>(p_dbc, dt_w, dt_b, nullptr,
                                                        p_delta, DI, 32, 64, 32);
    }

    // 6. selective scan -> yfull = (y + D*xc) * silu(z)
    scan_kernel<<<128, 256>>>(p_delta, p_xc, p_dbc, p_xz, A_log, D_par, p_yfull);

    // 7. x2 = x + yfull @ out_w^T + out_b    [4096 x 512, K=1024]
    {
        dim3 grd(DQ / 128, BL / 64);
        sgemm64<EPI_BIAS | EPI_RESID, false><<<grd, 256>>>(p_yfull, out_w, out_b, x,
                                                           nullptr, p_x2, DQ, DI, DI, DI);
    }

    // 8. k = LN(LN(x2, n2), kn)
    ln2_kernel<<<BL, DQ>>>(p_x2, n2_w, n2_b, kn_w, kn_b, p_k);

    // 9+10. out = x2 + basis(k) @ spl_w^T  [4096 x 512, K=4096], basis fused
    {
        dim3 grd(DQ / 128, BL / 64);
        sgemm64<EPI_RESID, true><<<grd, 256>>>(p_k, spl_w, nullptr, p_x2,
                                               grid, out, DQ, DQ * NG, 0, DQ * NG);
    }
    (void)in_sizes; (void)n_in; (void)out_size;
}

// round 4
// speedup vs baseline: 2.0185x; 1.5247x over previous
#include <cuda_runtime.h>
#include <cuda_bf16.h>
#include <math.h>
#include <stdint.h>

// Problem constants
#define BQ 2
#define LQ 2048
#define DQ 512
#define DI 1024
#define BL (BQ*LQ)          // 4096 rows
#define DSTATE 16
#define NG 8

// ---------------- device scratch ---------------------------------------------
__device__ float g_xz[(size_t)BL*2048];      // in_proj output (xm | z), fp32
__device__ float g_xc[(size_t)BL*DI];        // conv+silu
__device__ float g_dbc[BL*64];               // x_proj output
__device__ float g_delta[(size_t)BL*DI];     // softplus(dt_proj)
__device__ float g_x2[BL*DQ];                // x + mix
__device__ float g_k[BL*DQ];                 // LN(LN(x2))

__device__ __nv_bfloat16 g_uh[(size_t)BL*DQ],  g_ul[(size_t)BL*DQ];    // ln2(x) hi/lo
__device__ __nv_bfloat16 g_iwh[2048*DQ],       g_iwl[2048*DQ];         // in_w
__device__ __nv_bfloat16 g_yh[(size_t)BL*DI],  g_yl[(size_t)BL*DI];    // scan out
__device__ __nv_bfloat16 g_owh[DQ*DI],         g_owl[DQ*DI];           // out_w
__device__ __nv_bfloat16 g_bh[(size_t)BL*4096],g_bl[(size_t)BL*4096];  // KAN basis
__device__ __nv_bfloat16 g_swh[DQ*4096],       g_swl[DQ*4096];         // spl_w

// ---------------- PTX helpers (sm_80-class, valid on sm_100) ------------------
#define CP_ASYNC16(s, g) \
    asm volatile("cp.async.cg.shared.global [%0], [%1], 16;" :: "r"(s), "l"(g))
#define CP_COMMIT() asm volatile("cp.async.commit_group;" ::: "memory")
#define CP_WAIT(n)  asm volatile("cp.async.wait_group %0;" :: "n"(n) : "memory")

__device__ __forceinline__ void ldsm4(uint32_t* r, uint32_t addr) {
    asm volatile("ldmatrix.sync.aligned.m8n8.x4.shared.b16 {%0,%1,%2,%3}, [%4];"
                 : "=r"(r[0]), "=r"(r[1]), "=r"(r[2]), "=r"(r[3]) : "r"(addr));
}
__device__ __forceinline__ void mma_bf16(float* c, const uint32_t* a, const uint32_t* b) {
    asm volatile("mma.sync.aligned.m16n8k16.row.col.f32.bf16.bf16.f32 "
                 "{%0,%1,%2,%3}, {%4,%5,%6,%7}, {%8,%9}, {%0,%1,%2,%3};"
                 : "+f"(c[0]), "+f"(c[1]), "+f"(c[2]), "+f"(c[3])
                 : "r"(a[0]), "r"(a[1]), "r"(a[2]), "r"(a[3]),
                   "r"(b[0]), "r"(b[1]));
}

// ---------------- epilogue flags ---------------------------------------------
#define EPI_BIAS 1
#define EPI_RESID 2
#define EPI_SOFTPLUS 4

// ---------------- split-bf16 NT GEMM via mma.sync -----------------------------
// C[M,N] = (Ah+Al)[M,K] * (Bh+Bl)[N,K]^T, fp32 accum, 3-term compensated.
// Block 128x128, 8 warps (warp tile 64x32), K chunks of 32, cp.async pipelined.
// Smem matrix: 128 rows x 32 bf16, row stride 80B (ldmatrix conflict-free).
#define MG_STRIDE 80
#define MG_MAT    10240          // 128 * 80
#define MG_SMEM   (2 * 4 * MG_MAT)   // 81920 B

template<int EPI>
__global__ __launch_bounds__(256, 2)
void mgemm(const __nv_bfloat16* __restrict__ Ah, const __nv_bfloat16* __restrict__ Al,
           const __nv_bfloat16* __restrict__ Bh, const __nv_bfloat16* __restrict__ Bl,
           const float* __restrict__ bias, const float* __restrict__ resid,
           float* __restrict__ C, int N, int K) {
    extern __shared__ __align__(128) char smem[];
    uint32_t sb = (uint32_t)__cvta_generic_to_shared(smem);
    int tid = threadIdx.x;
    int lane = tid & 31, warp = tid >> 5;
    int bm = blockIdx.y * 128, bn = blockIdx.x * 128;
    int wm = (warp >> 2) * 64;       // 0 or 64
    int wn = (warp & 3) * 32;        // 0,32,64,96

    const __nv_bfloat16* P0 = Ah; const __nv_bfloat16* P1 = Al;
    const __nv_bfloat16* P2 = Bh; const __nv_bfloat16* P3 = Bl;

    int nc = K / 32;

    auto issue = [&](int c) {
        int k0 = c * 32;
        uint32_t bufb = sb + (c & 1) * 4 * MG_MAT;
        #pragma unroll
        for (int m = 0; m < 4; m++) {
            const __nv_bfloat16* src = (m == 0) ? P0 : (m == 1) ? P1 : (m == 2) ? P2 : P3;
            int rb = (m < 2) ? bm : bn;
            #pragma unroll
            for (int i = 0; i < 2; i++) {
                int idx = tid + i * 256;
                int row = idx >> 2, seg = idx & 3;
                const __nv_bfloat16* g = src + (size_t)(rb + row) * K + k0 + seg * 8;
                uint32_t s = bufb + m * MG_MAT + row * MG_STRIDE + seg * 16;
                CP_ASYNC16(s, g);
            }
        }
        CP_COMMIT();
    };

    float acc[4][4][4];
    #pragma unroll
    for (int mt = 0; mt < 4; mt++)
        #pragma unroll
        for (int nt = 0; nt < 4; nt++)
            #pragma unroll
            for (int q = 0; q < 4; q++) acc[mt][nt][q] = 0.f;

    issue(0);
    issue(1);

    for (int c = 0; c < nc; c++) {
        if (c + 1 < nc) { CP_WAIT(1); } else { CP_WAIT(0); }
        __syncthreads();
        uint32_t base = sb + (c & 1) * 4 * MG_MAT;
        uint32_t rsel = (lane & 15) * MG_STRIDE;
        #pragma unroll
        for (int kst = 0; kst < 2; kst++) {
            uint32_t kb = kst * 32 + (lane >> 4) * 16;
            uint32_t bh[4][2], bl[4][2], af[4][4];
            #pragma unroll
            for (int p = 0; p < 2; p++) {
                uint32_t r[4];
                ldsm4(r, base + 2 * MG_MAT + (wn + p * 16) * MG_STRIDE + rsel + kb);
                bh[p*2][0] = r[0]; bh[p*2][1] = r[2];
                bh[p*2+1][0] = r[1]; bh[p*2+1][1] = r[3];
                ldsm4(r, base + 3 * MG_MAT + (wn + p * 16) * MG_STRIDE + rsel + kb);
                bl[p*2][0] = r[0]; bl[p*2][1] = r[2];
                bl[p*2+1][0] = r[1]; bl[p*2+1][1] = r[3];
            }
            #pragma unroll
            for (int mt = 0; mt < 4; mt++)
                ldsm4(af[mt], base + (wm + mt * 16) * MG_STRIDE + rsel + kb);
            #pragma unroll
            for (int mt = 0; mt < 4; mt++)
                #pragma unroll
                for (int nt = 0; nt < 4; nt++) {
                    mma_bf16(acc[mt][nt], af[mt], bh[nt]);
                    mma_bf16(acc[mt][nt], af[mt], bl[nt]);
                }
            #pragma unroll
            for (int mt = 0; mt < 4; mt++)
                ldsm4(af[mt], base + MG_MAT + (wm + mt * 16) * MG_STRIDE + rsel + kb);
            #pragma unroll
            for (int mt = 0; mt < 4; mt++)
                #pragma unroll
                for (int nt = 0; nt < 4; nt++)
                    mma_bf16(acc[mt][nt], af[mt], bh[nt]);
        }
        __syncthreads();
        if (c + 2 < nc) issue(c + 2);
    }

    // epilogue
    int g = lane >> 2, tig = lane & 3;
    #pragma unroll
    for (int mt = 0; mt < 4; mt++) {
        size_t r0 = (size_t)bm + wm + mt * 16 + g;
        size_t r1 = r0 + 8;
        #pragma unroll
        for (int nt = 0; nt < 4; nt++) {
            int col = bn + wn + nt * 8 + tig * 2;
            float2 v0 = make_float2(acc[mt][nt][0], acc[mt][nt][1]);
            float2 v1 = make_float2(acc[mt][nt][2], acc[mt][nt][3]);
            if (EPI & EPI_BIAS) {
                float b0 = bias[col], b1 = bias[col + 1];
                v0.x += b0; v0.y += b1; v1.x += b0; v1.y += b1;
            }
            if (EPI & EPI_RESID) {
                const float* rp0 = resid + r0 * N + col;
                const float* rp1 = resid + r1 * N + col;
                v0.x += rp0[0]; v0.y += rp0[1];
                v1.x += rp1[0]; v1.y += rp1[1];
            }
            *(float2*)(C + r0 * N + col) = v0;
            *(float2*)(C + r1 * N + col) = v1;
        }
    }
}

// ---------------- block reduction helper --------------------------------------
__device__ __forceinline__ float block_sum(float v, float* sbuf) {
    #pragma unroll
    for (int o = 16; o > 0; o >>= 1) v += __shfl_xor_sync(0xffffffffu, v, o);
    int lane = threadIdx.x & 31, w = threadIdx.x >> 5;
    if (lane == 0) sbuf[w] = v;
    __syncthreads();
    if (w == 0) {
        v = (lane < ((int)blockDim.x >> 5)) ? sbuf[lane] : 0.f;
        #pragma unroll
        for (int o = 8; o > 0; o >>= 1) v += __shfl_xor_sync(0xffffffffu, v, o);
        if (lane == 0) sbuf[0] = v;
    }
    __syncthreads();
    v = sbuf[0];
    __syncthreads();
    return v;
}

// ---------------- double layernorm; optional fp32 + bf16 hi/lo outputs --------
__global__ void ln2_kernel(const float* __restrict__ x,
                           const float* __restrict__ w1, const float* __restrict__ b1,
                           const float* __restrict__ w2, const float* __restrict__ b2,
                           float* __restrict__ o32,
                           __nv_bfloat16* __restrict__ oh, __nv_bfloat16* __restrict__ ol) {
    __shared__ float sbuf[32];
    int row = blockIdx.x;
    int t = threadIdx.x;
    float v = x[(size_t)row * DQ + t];

    float mu  = block_sum(v, sbuf) * (1.f / DQ);
    float d   = v - mu;
    float var = block_sum(d * d, sbuf) * (1.f / DQ);
    float y   = d * rsqrtf(var + 1e-5f) * w1[t] + b1[t];

    mu  = block_sum(y, sbuf) * (1.f / DQ);
    d   = y - mu;
    var = block_sum(d * d, sbuf) * (1.f / DQ);
    float o = d * rsqrtf(var + 1e-5f) * w2[t] + b2[t];
    size_t i = (size_t)row * DQ + t;
    if (o32) o32[i] = o;
    if (oh) {
        __nv_bfloat16 h = __float2bfloat16(o);
        oh[i] = h;
        ol[i] = __float2bfloat16(o - __bfloat162float(h));
    }
}

// ---------------- fp32 -> bf16 hi/lo split ------------------------------------
__global__ void split_kernel(const float* __restrict__ s,
                             __nv_bfloat16* __restrict__ h,
                             __nv_bfloat16* __restrict__ l, int n4) {
    int i = blockIdx.x * 256 + threadIdx.x;
    if (i >= n4) return;
    float4 v = ((const float4*)s)[i];
    __nv_bfloat16 hx = __float2bfloat16(v.x), hy = __float2bfloat16(v.y);
    __nv_bfloat16 hz = __float2bfloat16(v.z), hw = __float2bfloat16(v.w);
    __nv_bfloat162* hp = (__nv_bfloat162*)h;
    __nv_bfloat162* lp = (__nv_bfloat162*)l;
    hp[2 * i + 0] = __nv_bfloat162(hx, hy);
    hp[2 * i + 1] = __nv_bfloat162(hz, hw);
    lp[2 * i + 0] = __nv_bfloat162(__float2bfloat16(v.x - __bfloat162float(hx)),
                                   __float2bfloat16(v.y - __bfloat162float(hy)));
    lp[2 * i + 1] = __nv_bfloat162(__float2bfloat16(v.z - __bfloat162float(hz)),
                                   __float2bfloat16(v.w - __bfloat162float(hw)));
}

// ---------------- fp32 SGEMM 128x128 (dt_proj, K=32) --------------------------
template<int EPI>
__global__ __launch_bounds__(256, 2)
void sgemm128(const float* __restrict__ A, const float* __restrict__ B,
              const float* __restrict__ bias, const float* __restrict__ resid,
              float* __restrict__ C, int N, int K, int lda, int ldb) {
    const int TK = 16;
    __shared__ __align__(16) float As[2][TK][128 + 4];
    __shared__ __align__(16) float Bs[2][TK][128 + 4];

    int tid = threadIdx.x;
    int bm = blockIdx.y * 128;
    int bn = blockIdx.x * 128;
    int arow = tid >> 2;
    int acol = (tid & 3) << 2;
    int tmb = (tid >> 4) << 3;
    int tnb = (tid & 15) << 3;

    const float* Ap0 = A + (size_t)(bm + arow) * lda + acol;
    const float* Ap1 = A + (size_t)(bm + arow + 64) * lda + acol;
    const float* Bp0 = B + (size_t)(bn + arow) * ldb + acol;
    const float* Bp1 = B + (size_t)(bn + arow + 64) * ldb + acol;

    float4 ra0 = *(const float4*)(Ap0);
    float4 ra1 = *(const float4*)(Ap1);
    float4 rb0 = *(const float4*)(Bp0);
    float4 rb1 = *(const float4*)(Bp1);
    As[0][acol+0][arow] = ra0.x; As[0][acol+1][arow] = ra0.y;
    As[0][acol+2][arow] = ra0.z; As[0][acol+3][arow] = ra0.w;
    As[0][acol+0][arow+64] = ra1.x; As[0][acol+1][arow+64] = ra1.y;
    As[0][acol+2][arow+64] = ra1.z; As[0][acol+3][arow+64] = ra1.w;
    Bs[0][acol+0][arow] = rb0.x; Bs[0][acol+1][arow] = rb0.y;
    Bs[0][acol+2][arow] = rb0.z; Bs[0][acol+3][arow] = rb0.w;
    Bs[0][acol+0][arow+64] = rb1.x; Bs[0][acol+1][arow+64] = rb1.y;
    Bs[0][acol+2][arow+64] = rb1.z; Bs[0][acol+3][arow+64] = rb1.w;
    __syncthreads();

    float acc[8][8];
    #pragma unroll
    for (int i = 0; i < 8; i++)
        #pragma unroll
        for (int j = 0; j < 8; j++) acc[i][j] = 0.f;

    int nk = K / TK;
    for (int it = 0; it < nk; it++) {
        int cur = it & 1, nxt = cur ^ 1;
        bool more = (it + 1 < nk);
        if (more) {
            int ko = (it + 1) * TK;
            ra0 = *(const float4*)(Ap0 + ko);
            ra1 = *(const float4*)(Ap1 + ko);
            rb0 = *(const float4*)(Bp0 + ko);
            rb1 = *(const float4*)(Bp1 + ko);
        }
        #pragma unroll
        for (int kk = 0; kk < TK; kk++) {
            float a[8], b[8];
            float4 a0 = *(const float4*)&As[cur][kk][tmb];
            float4 a1 = *(const float4*)&As[cur][kk][tmb + 4];
            float4 b0 = *(const float4*)&Bs[cur][kk][tnb];
            float4 b1 = *(const float4*)&Bs[cur][kk][tnb + 4];
            a[0]=a0.x;a[1]=a0.y;a[2]=a0.z;a[3]=a0.w;a[4]=a1.x;a[5]=a1.y;a[6]=a1.z;a[7]=a1.w;
            b[0]=b0.x;b[1]=b0.y;b[2]=b0.z;b[3]=b0.w;b[4]=b1.x;b[5]=b1.y;b[6]=b1.z;b[7]=b1.w;
            #pragma unroll
            for (int i = 0; i < 8; i++)
                #pragma unroll
                for (int j = 0; j < 8; j++)
                    acc[i][j] = fmaf(a[i], b[j], acc[i][j]);
        }
        if (more) {
            As[nxt][acol+0][arow] = ra0.x; As[nxt][acol+1][arow] = ra0.y;
            As[nxt][acol+2][arow] = ra0.z; As[nxt][acol+3][arow] = ra0.w;
            As[nxt][acol+0][arow+64] = ra1.x; As[nxt][acol+1][arow+64] = ra1.y;
            As[nxt][acol+2][arow+64] = ra1.z; As[nxt][acol+3][arow+64] = ra1.w;
            Bs[nxt][acol+0][arow] = rb0.x; Bs[nxt][acol+1][arow] = rb0.y;
            Bs[nxt][acol+2][arow] = rb0.z; Bs[nxt][acol+3][arow] = rb0.w;
            Bs[nxt][acol+0][arow+64] = rb1.x; Bs[nxt][acol+1][arow+64] = rb1.y;
            Bs[nxt][acol+2][arow+64] = rb1.z; Bs[nxt][acol+3][arow+64] = rb1.w;
        }
        __syncthreads();
    }

    #pragma unroll
    for (int i = 0; i < 8; i++) {
        size_t row = bm + tmb + i;
        #pragma unroll
        for (int j = 0; j < 8; j++) {
            int col = bn + tnb + j;
            float v = acc[i][j];
            if (EPI & EPI_BIAS)     v += bias[col];
            if (EPI & EPI_SOFTPLUS) v = (v > 20.f) ? v : log1pf(__expf(v));
            if (EPI & EPI_RESID)    v += resid[row * N + col];
            C[row * N + col] = v;
        }
    }
}

// ---------------- x_proj: [4096,1024] x [64,1024]^T, 16 rows/CTA --------------
__global__ __launch_bounds__(256)
void xproj_kernel(const float* __restrict__ A, const float* __restrict__ B,
                  float* __restrict__ C) {
    __shared__ float As[16][68];
    __shared__ float Bs[64][68];
    int tid = threadIdx.x;
    int r0 = blockIdx.x * 16;
    int rr = tid >> 6;        // 0..3
    int cc = tid & 63;        // 0..63
    float acc[4] = {0.f, 0.f, 0.f, 0.f};

    for (int k0 = 0; k0 < 1024; k0 += 64) {
        {
            int row = tid >> 4, seg = tid & 15;
            float4 v = *(const float4*)(A + (size_t)(r0 + row) * 1024 + k0 + seg * 4);
            *(float4*)&As[row][seg * 4] = v;
        }
        #pragma unroll
        for (int i = 0; i < 4; i++) {
            int idx = tid + i * 256;
            int row = idx >> 4, seg = idx & 15;
            float4 v = *(const float4*)(B + (size_t)row * 1024 + k0 + seg * 4);
            *(float4*)&Bs[row][seg * 4] = v;
        }
        __syncthreads();
        #pragma unroll
        for (int kk = 0; kk < 64; kk += 4) {
            float4 bv = *(float4*)&Bs[cc][kk];
            #pragma unroll
            for (int i = 0; i < 4; i++) {
                float4 av = *(float4*)&As[i * 4 + rr][kk];
                acc[i] = fmaf(av.x, bv.x, acc[i]);
                acc[i] = fmaf(av.y, bv.y, acc[i]);
                acc[i] = fmaf(av.z, bv.z, acc[i]);
                acc[i] = fmaf(av.w, bv.w, acc[i]);
            }
        }
        __syncthreads();
    }
    #pragma unroll
    for (int i = 0; i < 4; i++)
        C[(size_t)(r0 + i * 4 + rr) * 64 + cc] = acc[i];
}

// ---------------- causal depthwise conv (k=4) + silu --------------------------
__global__ void conv_silu_kernel(const float* __restrict__ xz,
                                 const float* __restrict__ cw,
                                 const float* __restrict__ cb,
                                 float* __restrict__ xc) {
    int idx = blockIdx.x * blockDim.x + threadIdx.x;
    if (idx >= BL * DI) return;
    int d = idx & (DI - 1);
    int row = idx >> 10;
    int l = row & (LQ - 1);
    float s = cb[d];
    #pragma unroll
    for (int j = 0; j < 4; j++) {
        int lp = l - 3 + j;
        if (lp >= 0)
            s = fmaf(xz[(size_t)(row - 3 + j) * 2048 + d], cw[d * 4 + j], s);
    }
    float sig = 1.f / (1.f + __expf(-s));
    xc[idx] = s * sig;
}

// ---------------- selective scan (prefetched), bf16 hi/lo output --------------
__global__ void scan_kernel(const float* __restrict__ delta_sp,
                            const float* __restrict__ xc,
                            const float* __restrict__ dbc,
                            const float* __restrict__ xz,
                            const float* __restrict__ A_log,
                            const float* __restrict__ D_param,
                            __nv_bfloat16* __restrict__ yh,
                            __nv_bfloat16* __restrict__ yl) {
    int tid = threadIdx.x;
    int lane = tid & 31;
    int warp = tid >> 5;
    int n  = lane & 15;
    int cw = lane >> 4;
    int ch = blockIdx.x * 16 + warp * 2 + cw;
    int b = ch >> 10;
    int d = ch & (DI - 1);

    float An = -__expf(A_log[d * DSTATE + n]);
    float Dp = D_param[d];
    float h = 0.f;
    size_t rbase = (size_t)b * LQ;

    size_t r = rbase;
    float dl = delta_sp[r * DI + d];
    float xv = xc[r * DI + d];
    float Bn = dbc[r * 64 + 32 + n];
    float Cn = dbc[r * 64 + 48 + n];
    float zv = xz[r * 2048 + DI + d];

    for (int t = 0; t < LQ; t++) {
        float dl2 = 0.f, xv2 = 0.f, Bn2 = 0.f, Cn2 = 0.f, zv2 = 0.f;
        if (t + 1 < LQ) {
            size_t r2 = rbase + t + 1;
            dl2 = delta_sp[r2 * DI + d];
            xv2 = xc[r2 * DI + d];
            Bn2 = dbc[r2 * 64 + 32 + n];
            Cn2 = dbc[r2 * 64 + 48 + n];
            zv2 = xz[r2 * 2048 + DI + d];
        }
        size_t row = rbase + t;
        float dA = __expf(dl * An);
        h = fmaf(dA, h, dl * Bn * xv);
        float p = h * Cn;
        p += __shfl_xor_sync(0xffffffffu, p, 1);
        p += __shfl_xor_sync(0xffffffffu, p, 2);
        p += __shfl_xor_sync(0xffffffffu, p, 4);
        p += __shfl_xor_sync(0xffffffffu, p, 8);
        if (n == 0) {
            float sz = zv / (1.f + __expf(-zv));
            float yv = (p + Dp * xv) * sz;
            __nv_bfloat16 hv = __float2bfloat16(yv);
            yh[row * DI + d] = hv;
            yl[row * DI + d] = __float2bfloat16(yv - __bfloat162float(hv));
        }
        dl = dl2; xv = xv2; Bn = Bn2; Cn = Cn2; zv = zv2;
    }
}

// ---------------- KAN basis to bf16 hi/lo -------------------------------------
__global__ void basis_split_kernel(const float* __restrict__ k,
                                   const float* __restrict__ grid,
                                   __nv_bfloat16* __restrict__ bh,
                                   __nv_bfloat16* __restrict__ bl) {
    int idx = blockIdx.x * blockDim.x + threadIdx.x;
    int j = idx & 4095;
    int row = idx >> 12;
    int d = j >> 3, g = j & 7;
    float t = tanhf((k[(size_t)row * DQ + d] - grid[g]) * (float)(1.0 / 0.33));
    float v = 1.f - t * t;
    __nv_bfloat16 h = __float2bfloat16(v);
    bh[idx] = h;
    bl[idx] = __float2bfloat16(v - __bfloat162float(h));
}

// ---------------- host orchestration ------------------------------------------
extern "C" void kernel_launch(void* const* d_in, const int* in_sizes, int n_in,
                              void* d_out, int out_size) {
    const float* x      = (const float*)d_in[0];
    const float* n1_w   = (const float*)d_in[1];
    const float* n1_b   = (const float*)d_in[2];
    const float* mn_w   = (const float*)d_in[3];
    const float* mn_b   = (const float*)d_in[4];
    const float* in_w   = (const float*)d_in[5];
    const float* in_b   = (const float*)d_in[6];
    const float* conv_w = (const float*)d_in[7];
    const float* conv_b = (const float*)d_in[8];
    const float* xp_w   = (const float*)d_in[9];
    const float* dt_w   = (const float*)d_in[10];
    const float* dt_b   = (const float*)d_in[11];
    const float* A_log  = (const float*)d_in[12];
    const float* D_par  = (const float*)d_in[13];
    const float* out_w  = (const float*)d_in[14];
    const float* out_b  = (const float*)d_in[15];
    const float* n2_w   = (const float*)d_in[16];
    const float* n2_b   = (const float*)d_in[17];
    const float* kn_w   = (const float*)d_in[18];
    const float* kn_b   = (const float*)d_in[19];
    const float* grid   = (const float*)d_in[20];
    const float* spl_w  = (const float*)d_in[21];
    float* out = (float*)d_out;

    float *p_xz, *p_xc, *p_dbc, *p_delta, *p_x2, *p_k;
    __nv_bfloat16 *p_uh, *p_ul, *p_iwh, *p_iwl, *p_yh, *p_yl, *p_owh, *p_owl,
                  *p_bh, *p_bl, *p_swh, *p_swl;
    cudaGetSymbolAddress((void**)&p_xz,    g_xz);
    cudaGetSymbolAddress((void**)&p_xc,    g_xc);
    cudaGetSymbolAddress((void**)&p_dbc,   g_dbc);
    cudaGetSymbolAddress((void**)&p_delta, g_delta);
    cudaGetSymbolAddress((void**)&p_x2,    g_x2);
    cudaGetSymbolAddress((void**)&p_k,     g_k);
    cudaGetSymbolAddress((void**)&p_uh,  g_uh);  cudaGetSymbolAddress((void**)&p_ul,  g_ul);
    cudaGetSymbolAddress((void**)&p_iwh, g_iwh); cudaGetSymbolAddress((void**)&p_iwl, g_iwl);
    cudaGetSymbolAddress((void**)&p_yh,  g_yh);  cudaGetSymbolAddress((void**)&p_yl,  g_yl);
    cudaGetSymbolAddress((void**)&p_owh, g_owh); cudaGetSymbolAddress((void**)&p_owl, g_owl);
    cudaGetSymbolAddress((void**)&p_bh,  g_bh);  cudaGetSymbolAddress((void**)&p_bl,  g_bl);
    cudaGetSymbolAddress((void**)&p_swh, g_swh); cudaGetSymbolAddress((void**)&p_swl, g_swl);

    cudaFuncSetAttribute(mgemm<EPI_BIAS>,
                         cudaFuncAttributeMaxDynamicSharedMemorySize, MG_SMEM);
    cudaFuncSetAttribute(mgemm<EPI_BIAS | EPI_RESID>,
                         cudaFuncAttributeMaxDynamicSharedMemorySize, MG_SMEM);
    cudaFuncSetAttribute(mgemm<EPI_RESID>,
                         cudaFuncAttributeMaxDynamicSharedMemorySize, MG_SMEM);

    // weight splits
    split_kernel<<<(2048 * DQ / 4 + 255) / 256, 256>>>(in_w,  p_iwh, p_iwl, 2048 * DQ / 4);
    split_kernel<<<(DQ * DI / 4 + 255) / 256, 256>>>(out_w, p_owh, p_owl, DQ * DI / 4);
    split_kernel<<<(DQ * 4096 / 4 + 255) / 256, 256>>>(spl_w, p_swh, p_swl, DQ * 4096 / 4);

    // 1. u = LN(LN(x)) -> bf16 hi/lo
    ln2_kernel<<<BL, DQ>>>(x, n1_w, n1_b, mn_w, mn_b, nullptr, p_uh, p_ul);

    // 2. xz = u @ in_w^T + in_b   [4096 x 2048, K=512]  (mma)
    mgemm<EPI_BIAS><<<dim3(2048 / 128, BL / 128), 256, MG_SMEM>>>(
        p_uh, p_ul, p_iwh, p_iwl, in_b, nullptr, p_xz, 2048, DQ);

    // 3. conv + silu
    conv_silu_kernel<<<(BL * DI) / 256, 256>>>(p_xz, conv_w, conv_b, p_xc);

    // 4. dbc = xc @ xp_w^T  [4096 x 64, K=1024]
    xproj_kernel<<<BL / 16, 256>>>(p_xc, xp_w, p_dbc);

    // 5. delta = softplus(dt_proj)  [4096 x 1024, K=32]
    sgemm128<EPI_BIAS | EPI_SOFTPLUS><<<dim3(DI / 128, BL / 128), 256>>>(
        p_dbc, dt_w, dt_b, nullptr, p_delta, DI, 32, 64, 32);

    // 6. scan -> y hi/lo
    scan_kernel<<<128, 256>>>(p_delta, p_xc, p_dbc, p_xz, A_log, D_par, p_yh, p_yl);

    // 7. x2 = x + y @ out_w^T + out_b  [4096 x 512, K=1024]  (mma)
    mgemm<EPI_BIAS | EPI_RESID><<<dim3(DQ / 128, BL / 128), 256, MG_SMEM>>>(
        p_yh, p_yl, p_owh, p_owl, out_b, x, p_x2, DQ, DI);

    // 8. k = LN(LN(x2)) -> fp32
    ln2_kernel<<<BL, DQ>>>(p_x2, n2_w, n2_b, kn_w, kn_b, p_k, nullptr, nullptr);

    // 9. basis -> bf16 hi/lo
    basis_split_kernel<<<(BL * 4096) / 256, 256>>>(p_k, grid, p_bh, p_bl);

    // 10. out = x2 + basis @ spl_w^T  [4096 x 512, K=4096]  (mma)
    mgemm<EPI_RESID><<<dim3(DQ / 128, BL / 128), 256, MG_SMEM>>>(
        p_bh, p_bl, p_swh, p_swl, nullptr, p_x2, out, DQ, 4096);

    (void)in_sizes; (void)n_in; (void)out_size;
}

// round 5
// speedup vs baseline: 4.0373x; 2.0001x over previous
#include <cuda_runtime.h>
#include <cuda_bf16.h>
#include <math.h>
#include <stdint.h>

// Problem constants
#define BQ 2
#define LQ 2048
#define DQ 512
#define DI 1024
#define BL (BQ*LQ)          // 4096 rows
#define DSTATE 16
#define NG 8
#define TC 128              // scan chunk length
#define NCH (LQ/TC)         // 16 chunks

// ---------------- device scratch ---------------------------------------------
__device__ float g_xz[(size_t)BL*2048];      // in_proj output (xm | z), fp32
__device__ float g_xc[(size_t)BL*DI];        // conv+silu
__device__ float g_dbc[BL*64];               // x_proj output
__device__ float g_delta[(size_t)BL*DI];     // softplus(dt_proj)
__device__ float g_x2[BL*DQ];                // x + mix
__device__ float g_k[BL*DQ];                 // LN(LN(x2))

__device__ float g_P[(size_t)BQ*NCH*DI*DSTATE];  // chunk products
__device__ float g_S[(size_t)BQ*NCH*DI*DSTATE];  // chunk local end states
__device__ float g_H[(size_t)BQ*NCH*DI*DSTATE];  // chunk initial states

__device__ __nv_bfloat16 g_uh[(size_t)BL*DQ],  g_ul[(size_t)BL*DQ];    // ln2(x) hi/lo
__device__ __nv_bfloat16 g_iwh[2048*DQ],       g_iwl[2048*DQ];         // in_w
__device__ __nv_bfloat16 g_yh[(size_t)BL*DI],  g_yl[(size_t)BL*DI];    // scan out
__device__ __nv_bfloat16 g_owh[DQ*DI],         g_owl[DQ*DI];           // out_w
__device__ __nv_bfloat16 g_bh[(size_t)BL*4096],g_bl[(size_t)BL*4096];  // KAN basis
__device__ __nv_bfloat16 g_swh[DQ*4096],       g_swl[DQ*4096];         // spl_w

// ---------------- PTX helpers (sm_80-class, valid on sm_100) ------------------
#define CP_ASYNC16(s, g) \
    asm volatile("cp.async.cg.shared.global [%0], [%1], 16;" :: "r"(s), "l"(g))
#define CP_COMMIT() asm volatile("cp.async.commit_group;" ::: "memory")
#define CP_WAIT(n)  asm volatile("cp.async.wait_group %0;" :: "n"(n) : "memory")

__device__ __forceinline__ void ldsm4(uint32_t* r, uint32_t addr) {
    asm volatile("ldmatrix.sync.aligned.m8n8.x4.shared.b16 {%0,%1,%2,%3}, [%4];"
                 : "=r"(r[0]), "=r"(r[1]), "=r"(r[2]), "=r"(r[3]) : "r"(addr));
}
__device__ __forceinline__ void mma_bf16(float* c, const uint32_t* a, const uint32_t* b) {
    asm volatile("mma.sync.aligned.m16n8k16.row.col.f32.bf16.bf16.f32 "
                 "{%0,%1,%2,%3}, {%4,%5,%6,%7}, {%8,%9}, {%0,%1,%2,%3};"
                 : "+f"(c[0]), "+f"(c[1]), "+f"(c[2]), "+f"(c[3])
                 : "r"(a[0]), "r"(a[1]), "r"(a[2]), "r"(a[3]),
                   "r"(b[0]), "r"(b[1]));
}

// ---------------- epilogue flags ---------------------------------------------
#define EPI_BIAS 1
#define EPI_RESID 2
#define EPI_SOFTPLUS 4

// ---------------- split-bf16 NT GEMM via mma.sync -----------------------------
#define MG_STRIDE 80
#define MG_MAT    10240          // 128 * 80
#define MG_SMEM   (2 * 4 * MG_MAT)   // 81920 B

template<int EPI>
__global__ __launch_bounds__(256, 2)
void mgemm(const __nv_bfloat16* __restrict__ Ah, const __nv_bfloat16* __restrict__ Al,
           const __nv_bfloat16* __restrict__ Bh, const __nv_bfloat16* __restrict__ Bl,
           const float* __restrict__ bias, const float* __restrict__ resid,
           float* __restrict__ C, int N, int K) {
    extern __shared__ __align__(128) char smem[];
    uint32_t sb = (uint32_t)__cvta_generic_to_shared(smem);
    int tid = threadIdx.x;
    int lane = tid & 31, warp = tid >> 5;
    int bm = blockIdx.y * 128, bn = blockIdx.x * 128;
    int wm = (warp >> 2) * 64;       // 0 or 64
    int wn = (warp & 3) * 32;        // 0,32,64,96

    const __nv_bfloat16* P0 = Ah; const __nv_bfloat16* P1 = Al;
    const __nv_bfloat16* P2 = Bh; const __nv_bfloat16* P3 = Bl;

    int nc = K / 32;

    auto issue = [&](int c) {
        int k0 = c * 32;
        uint32_t bufb = sb + (c & 1) * 4 * MG_MAT;
        #pragma unroll
        for (int m = 0; m < 4; m++) {
            const __nv_bfloat16* src = (m == 0) ? P0 : (m == 1) ? P1 : (m == 2) ? P2 : P3;
            int rb = (m < 2) ? bm : bn;
            #pragma unroll
            for (int i = 0; i < 2; i++) {
                int idx = tid + i * 256;
                int row = idx >> 2, seg = idx & 3;
                const __nv_bfloat16* g = src + (size_t)(rb + row) * K + k0 + seg * 8;
                uint32_t s = bufb + m * MG_MAT + row * MG_STRIDE + seg * 16;
                CP_ASYNC16(s, g);
            }
        }
        CP_COMMIT();
    };

    float acc[4][4][4];
    #pragma unroll
    for (int mt = 0; mt < 4; mt++)
        #pragma unroll
        for (int nt = 0; nt < 4; nt++)
            #pragma unroll
            for (int q = 0; q < 4; q++) acc[mt][nt][q] = 0.f;

    issue(0);
    issue(1);

    for (int c = 0; c < nc; c++) {
        if (c + 1 < nc) { CP_WAIT(1); } else { CP_WAIT(0); }
        __syncthreads();
        uint32_t base = sb + (c & 1) * 4 * MG_MAT;
        uint32_t rsel = (lane & 15) * MG_STRIDE;
        #pragma unroll
        for (int kst = 0; kst < 2; kst++) {
            uint32_t kb = kst * 32 + (lane >> 4) * 16;
            uint32_t bh[4][2], bl[4][2], af[4][4];
            #pragma unroll
            for (int p = 0; p < 2; p++) {
                uint32_t r[4];
                ldsm4(r, base + 2 * MG_MAT + (wn + p * 16) * MG_STRIDE + rsel + kb);
                bh[p*2][0] = r[0]; bh[p*2][1] = r[2];
                bh[p*2+1][0] = r[1]; bh[p*2+1][1] = r[3];
                ldsm4(r, base + 3 * MG_MAT + (wn + p * 16) * MG_STRIDE + rsel + kb);
                bl[p*2][0] = r[0]; bl[p*2][1] = r[2];
                bl[p*2+1][0] = r[1]; bl[p*2+1][1] = r[3];
            }
            #pragma unroll
            for (int mt = 0; mt < 4; mt++)
                ldsm4(af[mt], base + (wm + mt * 16) * MG_STRIDE + rsel + kb);
            #pragma unroll
            for (int mt = 0; mt < 4; mt++)
                #pragma unroll
                for (int nt = 0; nt < 4; nt++) {
                    mma_bf16(acc[mt][nt], af[mt], bh[nt]);
                    mma_bf16(acc[mt][nt], af[mt], bl[nt]);
                }
            #pragma unroll
            for (int mt = 0; mt < 4; mt++)
                ldsm4(af[mt], base + MG_MAT + (wm + mt * 16) * MG_STRIDE + rsel + kb);
            #pragma unroll
            for (int mt = 0; mt < 4; mt++)
                #pragma unroll
                for (int nt = 0; nt < 4; nt++)
                    mma_bf16(acc[mt][nt], af[mt], bh[nt]);
        }
        __syncthreads();
        if (c + 2 < nc) issue(c + 2);
    }

    // epilogue
    int g = lane >> 2, tig = lane & 3;
    #pragma unroll
    for (int mt = 0; mt < 4; mt++) {
        size_t r0 = (size_t)bm + wm + mt * 16 + g;
        size_t r1 = r0 + 8;
        #pragma unroll
        for (int nt = 0; nt < 4; nt++) {
            int col = bn + wn + nt * 8 + tig * 2;
            float2 v0 = make_float2(acc[mt][nt][0], acc[mt][nt][1]);
            float2 v1 = make_float2(acc[mt][nt][2], acc[mt][nt][3]);
            if (EPI & EPI_BIAS) {
                float b0 = bias[col], b1 = bias[col + 1];
                v0.x += b0; v0.y += b1; v1.x += b0; v1.y += b1;
            }
            if (EPI & EPI_RESID) {
                const float* rp0 = resid + r0 * N + col;
                const float* rp1 = resid + r1 * N + col;
                v0.x += rp0[0]; v0.y += rp0[1];
                v1.x += rp1[0]; v1.y += rp1[1];
            }
            *(float2*)(C + r0 * N + col) = v0;
            *(float2*)(C + r1 * N + col) = v1;
        }
    }
}

// ---------------- block reduction helper --------------------------------------
__device__ __forceinline__ float block_sum(float v, float* sbuf) {
    #pragma unroll
    for (int o = 16; o > 0; o >>= 1) v += __shfl_xor_sync(0xffffffffu, v, o);
    int lane = threadIdx.x & 31, w = threadIdx.x >> 5;
    if (lane == 0) sbuf[w] = v;
    __syncthreads();
    if (w == 0) {
        v = (lane < ((int)blockDim.x >> 5)) ? sbuf[lane] : 0.f;
        #pragma unroll
        for (int o = 8; o > 0; o >>= 1) v += __shfl_xor_sync(0xffffffffu, v, o);
        if (lane == 0) sbuf[0] = v;
    }
    __syncthreads();
    v = sbuf[0];
    __syncthreads();
    return v;
}

// ---------------- double layernorm; optional fp32 + bf16 hi/lo outputs --------
__global__ void ln2_kernel(const float* __restrict__ x,
                           const float* __restrict__ w1, const float* __restrict__ b1,
                           const float* __restrict__ w2, const float* __restrict__ b2,
                           float* __restrict__ o32,
                           __nv_bfloat16* __restrict__ oh, __nv_bfloat16* __restrict__ ol) {
    __shared__ float sbuf[32];
    int row = blockIdx.x;
    int t = threadIdx.x;
    float v = x[(size_t)row * DQ + t];

    float mu  = block_sum(v, sbuf) * (1.f / DQ);
    float d   = v - mu;
    float var = block_sum(d * d, sbuf) * (1.f / DQ);
    float y   = d * rsqrtf(var + 1e-5f) * w1[t] + b1[t];

    mu  = block_sum(y, sbuf) * (1.f / DQ);
    d   = y - mu;
    var = block_sum(d * d, sbuf) * (1.f / DQ);
    float o = d * rsqrtf(var + 1e-5f) * w2[t] + b2[t];
    size_t i = (size_t)row * DQ + t;
    if (o32) o32[i] = o;
    if (oh) {
        __nv_bfloat16 h = __float2bfloat16(o);
        oh[i] = h;
        ol[i] = __float2bfloat16(o - __bfloat162float(h));
    }
}

// ---------------- fp32 -> bf16 hi/lo split ------------------------------------
__global__ void split_kernel(const float* __restrict__ s,
                             __nv_bfloat16* __restrict__ h,
                             __nv_bfloat16* __restrict__ l, int n4) {
    int i = blockIdx.x * 256 + threadIdx.x;
    if (i >= n4) return;
    float4 v = ((const float4*)s)[i];
    __nv_bfloat16 hx = __float2bfloat16(v.x), hy = __float2bfloat16(v.y);
    __nv_bfloat16 hz = __float2bfloat16(v.z), hw = __float2bfloat16(v.w);
    __nv_bfloat162* hp = (__nv_bfloat162*)h;
    __nv_bfloat162* lp = (__nv_bfloat162*)l;
    hp[2 * i + 0] = __nv_bfloat162(hx, hy);
    hp[2 * i + 1] = __nv_bfloat162(hz, hw);
    lp[2 * i + 0] = __nv_bfloat162(__float2bfloat16(v.x - __bfloat162float(hx)),
                                   __float2bfloat16(v.y - __bfloat162float(hy)));
    lp[2 * i + 1] = __nv_bfloat162(__float2bfloat16(v.z - __bfloat162float(hz)),
                                   __float2bfloat16(v.w - __bfloat162float(hw)));
}

// ---------------- fp32 SGEMM 128x128 (dt_proj, K=32) --------------------------
template<int EPI>
__global__ __launch_bounds__(256, 2)
void sgemm128(const float* __restrict__ A, const float* __restrict__ B,
              const float* __restrict__ bias, const float* __restrict__ resid,
              float* __restrict__ C, int N, int K, int lda, int ldb) {
    const int TK = 16;
    __shared__ __align__(16) float As[2][TK][128 + 4];
    __shared__ __align__(16) float Bs[2][TK][128 + 4];

    int tid = threadIdx.x;
    int bm = blockIdx.y * 128;
    int bn = blockIdx.x * 128;
    int arow = tid >> 2;
    int acol = (tid & 3) << 2;
    int tmb = (tid >> 4) << 3;
    int tnb = (tid & 15) << 3;

    const float* Ap0 = A + (size_t)(bm + arow) * lda + acol;
    const float* Ap1 = A + (size_t)(bm + arow + 64) * lda + acol;
    const float* Bp0 = B + (size_t)(bn + arow) * ldb + acol;
    const float* Bp1 = B + (size_t)(bn + arow + 64) * ldb + acol;

    float4 ra0 = *(const float4*)(Ap0);
    float4 ra1 = *(const float4*)(Ap1);
    float4 rb0 = *(const float4*)(Bp0);
    float4 rb1 = *(const float4*)(Bp1);
    As[0][acol+0][arow] = ra0.x; As[0][acol+1][arow] = ra0.y;
    As[0][acol+2][arow] = ra0.z; As[0][acol+3][arow] = ra0.w;
    As[0][acol+0][arow+64] = ra1.x; As[0][acol+1][arow+64] = ra1.y;
    As[0][acol+2][arow+64] = ra1.z; As[0][acol+3][arow+64] = ra1.w;
    Bs[0][acol+0][arow] = rb0.x; Bs[0][acol+1][arow] = rb0.y;
    Bs[0][acol+2][arow] = rb0.z; Bs[0][acol+3][arow] = rb0.w;
    Bs[0][acol+0][arow+64] = rb1.x; Bs[0][acol+1][arow+64] = rb1.y;
    Bs[0][acol+2][arow+64] = rb1.z; Bs[0][acol+3][arow+64] = rb1.w;
    __syncthreads();

    float acc[8][8];
    #pragma unroll
    for (int i = 0; i < 8; i++)
        #pragma unroll
        for (int j = 0; j < 8; j++) acc[i][j] = 0.f;

    int nk = K / TK;
    for (int it = 0; it < nk; it++) {
        int cur = it & 1, nxt = cur ^ 1;
        bool more = (it + 1 < nk);
        if (more) {
            int ko = (it + 1) * TK;
            ra0 = *(const float4*)(Ap0 + ko);
            ra1 = *(const float4*)(Ap1 + ko);
            rb0 = *(const float4*)(Bp0 + ko);
            rb1 = *(const float4*)(Bp1 + ko);
        }
        #pragma unroll
        for (int kk = 0; kk < TK; kk++) {
            float a[8], b[8];
            float4 a0 = *(const float4*)&As[cur][kk][tmb];
            float4 a1 = *(const float4*)&As[cur][kk][tmb + 4];
            float4 b0 = *(const float4*)&Bs[cur][kk][tnb];
            float4 b1 = *(const float4*)&Bs[cur][kk][tnb + 4];
            a[0]=a0.x;a[1]=a0.y;a[2]=a0.z;a[3]=a0.w;a[4]=a1.x;a[5]=a1.y;a[6]=a1.z;a[7]=a1.w;
            b[0]=b0.x;b[1]=b0.y;b[2]=b0.z;b[3]=b0.w;b[4]=b1.x;b[5]=b1.y;b[6]=b1.z;b[7]=b1.w;
            #pragma unroll
            for (int i = 0; i < 8; i++)
                #pragma unroll
                for (int j = 0; j < 8; j++)
                    acc[i][j] = fmaf(a[i], b[j], acc[i][j]);
        }
        if (more) {
            As[nxt][acol+0][arow] = ra0.x; As[nxt][acol+1][arow] = ra0.y;
            As[nxt][acol+2][arow] = ra0.z; As[nxt][acol+3][arow] = ra0.w;
            As[nxt][acol+0][arow+64] = ra1.x; As[nxt][acol+1][arow+64] = ra1.y;
            As[nxt][acol+2][arow+64] = ra1.z; As[nxt][acol+3][arow+64] = ra1.w;
            Bs[nxt][acol+0][arow] = rb0.x; Bs[nxt][acol+1][arow] = rb0.y;
            Bs[nxt][acol+2][arow] = rb0.z; Bs[nxt][acol+3][arow] = rb0.w;
            Bs[nxt][acol+0][arow+64] = rb1.x; Bs[nxt][acol+1][arow+64] = rb1.y;
            Bs[nxt][acol+2][arow+64] = rb1.z; Bs[nxt][acol+3][arow+64] = rb1.w;
        }
        __syncthreads();
    }

    #pragma unroll
    for (int i = 0; i < 8; i++) {
        size_t row = bm + tmb + i;
        #pragma unroll
        for (int j = 0; j < 8; j++) {
            int col = bn + tnb + j;
            float v = acc[i][j];
            if (EPI & EPI_BIAS)     v += bias[col];
            if (EPI & EPI_SOFTPLUS) v = (v > 20.f) ? v : log1pf(__expf(v));
            if (EPI & EPI_RESID)    v += resid[row * N + col];
            C[row * N + col] = v;
        }
    }
}

// ---------------- x_proj: [4096,1024] x [64,1024]^T, 16 rows/CTA --------------
__global__ __launch_bounds__(256)
void xproj_kernel(const float* __restrict__ A, const float* __restrict__ B,
                  float* __restrict__ C) {
    __shared__ float As[16][68];
    __shared__ float Bs[64][68];
    int tid = threadIdx.x;
    int r0 = blockIdx.x * 16;
    int rr = tid >> 6;        // 0..3
    int cc = tid & 63;        // 0..63
    float acc[4] = {0.f, 0.f, 0.f, 0.f};

    for (int k0 = 0; k0 < 1024; k0 += 64) {
        {
            int row = tid >> 4, seg = tid & 15;
            float4 v = *(const float4*)(A + (size_t)(r0 + row) * 1024 + k0 + seg * 4);
            *(float4*)&As[row][seg * 4] = v;
        }
        #pragma unroll
        for (int i = 0; i < 4; i++) {
            int idx = tid + i * 256;
            int row = idx >> 4, seg = idx & 15;
            float4 v = *(const float4*)(B + (size_t)row * 1024 + k0 + seg * 4);
            *(float4*)&Bs[row][seg * 4] = v;
        }
        __syncthreads();
        #pragma unroll
        for (int kk = 0; kk < 64; kk += 4) {
            float4 bv = *(float4*)&Bs[cc][kk];
            #pragma unroll
            for (int i = 0; i < 4; i++) {
                float4 av = *(float4*)&As[i * 4 + rr][kk];
                acc[i] = fmaf(av.x, bv.x, acc[i]);
                acc[i] = fmaf(av.y, bv.y, acc[i]);
                acc[i] = fmaf(av.z, bv.z, acc[i]);
                acc[i] = fmaf(av.w, bv.w, acc[i]);
            }
        }
        __syncthreads();
    }
    #pragma unroll
    for (int i = 0; i < 4; i++)
        C[(size_t)(r0 + i * 4 + rr) * 64 + cc] = acc[i];
}

// ---------------- causal depthwise conv (k=4) + silu --------------------------
__global__ void conv_silu_kernel(const float* __restrict__ xz,
                                 const float* __restrict__ cw,
                                 const float* __restrict__ cb,
                                 float* __restrict__ xc) {
    int idx = blockIdx.x * blockDim.x + threadIdx.x;
    if (idx >= BL * DI) return;
    int d = idx & (DI - 1);
    int row = idx >> 10;
    int l = row & (LQ - 1);
    float s = cb[d];
    #pragma unroll
    for (int j = 0; j < 4; j++) {
        int lp = l - 3 + j;
        if (lp >= 0)
            s = fmaf(xz[(size_t)(row - 3 + j) * 2048 + d], cw[d * 4 + j], s);
    }
    float sig = 1.f / (1.f + __expf(-s));
    xc[idx] = s * sig;
}

// ---------------- chunked scan, pass 1: per-chunk (P, S) ----------------------
// block: 256 threads = 16 channels x 16 states; grid: b(2) x chunk(16) x dtile(64)
__global__ __launch_bounds__(256)
void scan1_kernel(const float* __restrict__ delta_sp,
                  const float* __restrict__ xc,
                  const float* __restrict__ dbc,
                  const float* __restrict__ A_log,
                  float* __restrict__ Pout, float* __restrict__ Sout) {
    __shared__ float s_dl[TC][16];
    __shared__ float s_xv[TC][16];
    __shared__ float s_B[TC][16];
    int bx = blockIdx.x;
    int dt = bx & 63;
    int c  = (bx >> 6) & 15;
    int b  = bx >> 10;
    int tid = threadIdx.x;
    int n = tid & 15, dloc = tid >> 4;
    int d = dt * 16 + dloc;
    size_t row0 = (size_t)b * LQ + c * TC;

    #pragma unroll
    for (int i = 0; i < 2; i++) {
        int idx = tid + i * 256;
        int t = idx >> 2, q = idx & 3;
        *(float4*)&s_dl[t][q * 4] = *(const float4*)(delta_sp + (row0 + t) * DI + dt * 16 + q * 4);
        *(float4*)&s_xv[t][q * 4] = *(const float4*)(xc + (row0 + t) * DI + dt * 16 + q * 4);
        *(float4*)&s_B[t][q * 4]  = *(const float4*)(dbc + (row0 + t) * 64 + 32 + q * 4);
    }
    __syncthreads();

    float An = -__expf(A_log[d * DSTATE + n]);
    float h = 0.f, P = 1.f;
    #pragma unroll 4
    for (int t = 0; t < TC; t++) {
        float dl = s_dl[t][dloc];
        float dA = __expf(dl * An);
        h = fmaf(dA, h, dl * s_B[t][n] * s_xv[t][dloc]);
        P *= dA;
    }
    size_t o = (((size_t)b * NCH + c) * DI + (size_t)dt * 16) * DSTATE + tid;
    Pout[o] = P;
    Sout[o] = h;
}

// ---------------- chunked scan: carry over chunks -----------------------------
__global__ void scan_carry_kernel(const float* __restrict__ P,
                                  const float* __restrict__ S,
                                  float* __restrict__ H) {
    int idx = blockIdx.x * 256 + threadIdx.x;   // 0..32767 = b*16384 + d*16 + n
    int b = idx >> 14;
    int rem = idx & 16383;
    float carry = 0.f;
    #pragma unroll
    for (int c = 0; c < NCH; c++) {
        size_t o = (((size_t)b * NCH + c) << 14) + rem;
        H[o] = carry;
        carry = fmaf(P[o], carry, S[o]);
    }
}

// ---------------- chunked scan, pass 2: y + gating, bf16 hi/lo out ------------
__global__ __launch_bounds__(256)
void scan2_kernel(const float* __restrict__ delta_sp,
                  const float* __restrict__ xc,
                  const float* __restrict__ dbc,
                  const float* __restrict__ xz,
                  const float* __restrict__ A_log,
                  const float* __restrict__ D_param,
                  const float* __restrict__ H,
                  __nv_bfloat16* __restrict__ yh,
                  __nv_bfloat16* __restrict__ yl) {
    __shared__ float s_dl[TC][16];
    __shared__ float s_xv[TC][16];
    __shared__ float s_B[TC][16];
    __shared__ float s_C[TC][16];
    __shared__ float s_y[TC][16];
    int bx = blockIdx.x;
    int dt = bx & 63;
    int c  = (bx >> 6) & 15;
    int b  = bx >> 10;
    int tid = threadIdx.x;
    int n = tid & 15, dloc = tid >> 4;
    int d = dt * 16 + dloc;
    size_t row0 = (size_t)b * LQ + c * TC;

    #pragma unroll
    for (int i = 0; i < 2; i++) {
        int idx = tid + i * 256;
        int t = idx >> 2, q = idx & 3;
        *(float4*)&s_dl[t][q * 4] = *(const float4*)(delta_sp + (row0 + t) * DI + dt * 16 + q * 4);
        *(float4*)&s_xv[t][q * 4] = *(const float4*)(xc + (row0 + t) * DI + dt * 16 + q * 4);
        *(float4*)&s_B[t][q * 4]  = *(const float4*)(dbc + (row0 + t) * 64 + 32 + q * 4);
        *(float4*)&s_C[t][q * 4]  = *(const float4*)(dbc + (row0 + t) * 64 + 48 + q * 4);
    }
    __syncthreads();

    float An = -__expf(A_log[d * DSTATE + n]);
    float Dp = D_param[d];
    size_t o = (((size_t)b * NCH + c) * DI + (size_t)dt * 16) * DSTATE + tid;
    float h = H[o];

    #pragma unroll 4
    for (int t = 0; t < TC; t++) {
        float dl = s_dl[t][dloc];
        float xv = s_xv[t][dloc];
        float dA = __expf(dl * An);
        h = fmaf(dA, h, dl * s_B[t][n] * xv);
        float p = h * s_C[t][n];
        p += __shfl_xor_sync(0xffffffffu, p, 1);
        p += __shfl_xor_sync(0xffffffffu, p, 2);
        p += __shfl_xor_sync(0xffffffffu, p, 4);
        p += __shfl_xor_sync(0xffffffffu, p, 8);
        if (n == 0) s_y[t][dloc] = p + Dp * xv;
    }
    __syncthreads();

    // gate with silu(z) and write bf16 hi/lo, coalesced
    #pragma unroll
    for (int i = 0; i < 8; i++) {
        int idx = tid + i * 256;
        int t = idx >> 4, dl2 = idx & 15;
        size_t row = row0 + t;
        float zv = xz[row * 2048 + DI + dt * 16 + dl2];
        float sz = zv / (1.f + __expf(-zv));
        float yv = s_y[t][dl2] * sz;
        __nv_bfloat16 hv = __float2bfloat16(yv);
        yh[row * DI + dt * 16 + dl2] = hv;
        yl[row * DI + dt * 16 + dl2] = __float2bfloat16(yv - __bfloat162float(hv));
    }
}

// ---------------- KAN basis to bf16 hi/lo -------------------------------------
__global__ void basis_split_kernel(const float* __restrict__ k,
                                   const float* __restrict__ grid,
                                   __nv_bfloat16* __restrict__ bh,
                                   __nv_bfloat16* __restrict__ bl) {
    int idx = blockIdx.x * blockDim.x + threadIdx.x;
    int j = idx & 4095;
    int row = idx >> 12;
    int d = j >> 3, g = j & 7;
    float t = tanhf((k[(size_t)row * DQ + d] - grid[g]) * (float)(1.0 / 0.33));
    float v = 1.f - t * t;
    __nv_bfloat16 h = __float2bfloat16(v);
    bh[idx] = h;
    bl[idx] = __float2bfloat16(v - __bfloat162float(h));
}

// ---------------- host orchestration ------------------------------------------
extern "C" void kernel_launch(void* const* d_in, const int* in_sizes, int n_in,
                              void* d_out, int out_size) {
    const float* x      = (const float*)d_in[0];
    const float* n1_w   = (const float*)d_in[1];
    const float* n1_b   = (const float*)d_in[2];
    const float* mn_w   = (const float*)d_in[3];
    const float* mn_b   = (const float*)d_in[4];
    const float* in_w   = (const float*)d_in[5];
    const float* in_b   = (const float*)d_in[6];
    const float* conv_w = (const float*)d_in[7];
    const float* conv_b = (const float*)d_in[8];
    const float* xp_w   = (const float*)d_in[9];
    const float* dt_w   = (const float*)d_in[10];
    const float* dt_b   = (const float*)d_in[11];
    const float* A_log  = (const float*)d_in[12];
    const float* D_par  = (const float*)d_in[13];
    const float* out_w  = (const float*)d_in[14];
    const float* out_b  = (const float*)d_in[15];
    const float* n2_w   = (const float*)d_in[16];
    const float* n2_b   = (const float*)d_in[17];
    const float* kn_w   = (const float*)d_in[18];
    const float* kn_b   = (const float*)d_in[19];
    const float* grid   = (const float*)d_in[20];
    const float* spl_w  = (const float*)d_in[21];
    float* out = (float*)d_out;

    float *p_xz, *p_xc, *p_dbc, *p_delta, *p_x2, *p_k, *p_P, *p_S, *p_H;
    __nv_bfloat16 *p_uh, *p_ul, *p_iwh, *p_iwl, *p_yh, *p_yl, *p_owh, *p_owl,
                  *p_bh, *p_bl, *p_swh, *p_swl;
    cudaGetSymbolAddress((void**)&p_xz,    g_xz);
    cudaGetSymbolAddress((void**)&p_xc,    g_xc);
    cudaGetSymbolAddress((void**)&p_dbc,   g_dbc);
    cudaGetSymbolAddress((void**)&p_delta, g_delta);
    cudaGetSymbolAddress((void**)&p_x2,    g_x2);
    cudaGetSymbolAddress((void**)&p_k,     g_k);
    cudaGetSymbolAddress((void**)&p_P,     g_P);
    cudaGetSymbolAddress((void**)&p_S,     g_S);
    cudaGetSymbolAddress((void**)&p_H,     g_H);
    cudaGetSymbolAddress((void**)&p_uh,  g_uh);  cudaGetSymbolAddress((void**)&p_ul,  g_ul);
    cudaGetSymbolAddress((void**)&p_iwh, g_iwh); cudaGetSymbolAddress((void**)&p_iwl, g_iwl);
    cudaGetSymbolAddress((void**)&p_yh,  g_yh);  cudaGetSymbolAddress((void**)&p_yl,  g_yl);
    cudaGetSymbolAddress((void**)&p_owh, g_owh); cudaGetSymbolAddress((void**)&p_owl, g_owl);
    cudaGetSymbolAddress((void**)&p_bh,  g_bh);  cudaGetSymbolAddress((void**)&p_bl,  g_bl);
    cudaGetSymbolAddress((void**)&p_swh, g_swh); cudaGetSymbolAddress((void**)&p_swl, g_swl);

    cudaFuncSetAttribute(mgemm<EPI_BIAS>,
                         cudaFuncAttributeMaxDynamicSharedMemorySize, MG_SMEM);
    cudaFuncSetAttribute(mgemm<EPI_BIAS | EPI_RESID>,
                         cudaFuncAttributeMaxDynamicSharedMemorySize, MG_SMEM);
    cudaFuncSetAttribute(mgemm<EPI_RESID>,
                         cudaFuncAttributeMaxDynamicSharedMemorySize, MG_SMEM);

    // weight splits
    split_kernel<<<(2048 * DQ / 4 + 255) / 256, 256>>>(in_w,  p_iwh, p_iwl, 2048 * DQ / 4);
    split_kernel<<<(DQ * DI / 4 + 255) / 256, 256>>>(out_w, p_owh, p_owl, DQ * DI / 4);
    split_kernel<<<(DQ * 4096 / 4 + 255) / 256, 256>>>(spl_w, p_swh, p_swl, DQ * 4096 / 4);

    // 1. u = LN(LN(x)) -> bf16 hi/lo
    ln2_kernel<<<BL, DQ>>>(x, n1_w, n1_b, mn_w, mn_b, nullptr, p_uh, p_ul);

    // 2. xz = u @ in_w^T + in_b   [4096 x 2048, K=512]  (mma)
    mgemm<EPI_BIAS><<<dim3(2048 / 128, BL / 128), 256, MG_SMEM>>>(
        p_uh, p_ul, p_iwh, p_iwl, in_b, nullptr, p_xz, 2048, DQ);

    // 3. conv + silu
    conv_silu_kernel<<<(BL * DI) / 256, 256>>>(p_xz, conv_w, conv_b, p_xc);

    // 4. dbc = xc @ xp_w^T  [4096 x 64, K=1024]
    xproj_kernel<<<BL / 16, 256>>>(p_xc, xp_w, p_dbc);

    // 5. delta = softplus(dt_proj)  [4096 x 1024, K=32]
    sgemm128<EPI_BIAS | EPI_SOFTPLUS><<<dim3(DI / 128, BL / 128), 256>>>(
        p_dbc, dt_w, dt_b, nullptr, p_delta, DI, 32, 64, 32);

    // 6. chunked parallel scan -> y hi/lo
    scan1_kernel<<<BQ * NCH * 64, 256>>>(p_delta, p_xc, p_dbc, A_log, p_P, p_S);
    scan_carry_kernel<<<(BQ * DI * DSTATE) / 256, 256>>>(p_P, p_S, p_H);
    scan2_kernel<<<BQ * NCH * 64, 256>>>(p_delta, p_xc, p_dbc, p_xz, A_log, D_par,
                                         p_H, p_yh, p_yl);

    // 7. x2 = x + y @ out_w^T + out_b  [4096 x 512, K=1024]  (mma)
    mgemm<EPI_BIAS | EPI_RESID><<<dim3(DQ / 128, BL / 128), 256, MG_SMEM>>>(
        p_yh, p_yl, p_owh, p_owl, out_b, x, p_x2, DQ, DI);

    // 8. k = LN(LN(x2)) -> fp32
    ln2_kernel<<<BL, DQ>>>(p_x2, n2_w, n2_b, kn_w, kn_b, p_k, nullptr, nullptr);

    // 9. basis -> bf16 hi/lo
    basis_split_kernel<<<(BL * 4096) / 256, 256>>>(p_k, grid, p_bh, p_bl);

    // 10. out = x2 + basis @ spl_w^T  [4096 x 512, K=4096]  (mma)
    mgemm<EPI_RESID><<<dim3(DQ / 128, BL / 128), 256, MG_SMEM>>>(
        p_bh, p_bl, p_swh, p_swl, nullptr, p_x2, out, DQ, 4096);

    (void)in_sizes; (void)n_in; (void)out_size;
}

// round 6
// speedup vs baseline: 4.8887x; 1.2109x over previous
#include <cuda_runtime.h>
#include <cuda_fp16.h>
#include <math.h>
#include <stdint.h>

// Problem constants
#define BQ 2
#define LQ 2048
#define DQ 512
#define DI 1024
#define BL (BQ*LQ)          // 4096 rows
#define DSTATE 16
#define NG 8
#define TC 128              // scan chunk length
#define NCH (LQ/TC)         // 16 chunks

// ---------------- device scratch ---------------------------------------------
__device__ float g_xz[(size_t)BL*2048];      // in_proj output (xm | z), fp32
__device__ float g_xc[(size_t)BL*DI];        // conv+silu
__device__ float g_dbc[BL*64];               // x_proj output
__device__ float g_delta[(size_t)BL*DI];     // softplus(dt_proj)
__device__ float g_x2[BL*DQ];                // x + mix
__device__ float g_k[BL*DQ];                 // LN(LN(x2))

__device__ float g_P[(size_t)BQ*NCH*DI*DSTATE];  // chunk products
__device__ float g_S[(size_t)BQ*NCH*DI*DSTATE];  // chunk local end states
__device__ float g_H[(size_t)BQ*NCH*DI*DSTATE];  // chunk initial states

__device__ __half g_uh[(size_t)BL*DQ],  g_ul[(size_t)BL*DQ];    // ln2(x) hi/lo
__device__ __half g_iwh[2048*DQ];                                // in_w fp16
__device__ __half g_yh[(size_t)BL*DI],  g_yl[(size_t)BL*DI];    // scan out
__device__ __half g_owh[DQ*DI];                                  // out_w fp16
__device__ __half g_bh[(size_t)BL*4096],g_bl[(size_t)BL*4096];  // KAN basis
__device__ __half g_swh[DQ*4096];                                // spl_w fp16

// ---------------- PTX helpers (sm_80-class, valid on sm_100) ------------------
#define CP_ASYNC16(s, g) \
    asm volatile("cp.async.cg.shared.global [%0], [%1], 16;" :: "r"(s), "l"(g))
#define CP_COMMIT() asm volatile("cp.async.commit_group;" ::: "memory")
#define CP_WAIT(n)  asm volatile("cp.async.wait_group %0;" :: "n"(n) : "memory")

__device__ __forceinline__ void ldsm4(uint32_t* r, uint32_t addr) {
    asm volatile("ldmatrix.sync.aligned.m8n8.x4.shared.b16 {%0,%1,%2,%3}, [%4];"
                 : "=r"(r[0]), "=r"(r[1]), "=r"(r[2]), "=r"(r[3]) : "r"(addr));
}
__device__ __forceinline__ void mma_f16(float* c, const uint32_t* a, const uint32_t* b) {
    asm volatile("mma.sync.aligned.m16n8k16.row.col.f32.f16.f16.f32 "
                 "{%0,%1,%2,%3}, {%4,%5,%6,%7}, {%8,%9}, {%0,%1,%2,%3};"
                 : "+f"(c[0]), "+f"(c[1]), "+f"(c[2]), "+f"(c[3])
                 : "r"(a[0]), "r"(a[1]), "r"(a[2]), "r"(a[3]),
                   "r"(b[0]), "r"(b[1]));
}

// ---------------- epilogue flags ---------------------------------------------
#define EPI_BIAS 1
#define EPI_RESID 2
#define EPI_SOFTPLUS 4

// ---------------- split-fp16 2-term NT GEMM via mma.sync ----------------------
// C[M,N] = (Ah+Al)[M,K] * Bh[N,K]^T, fp32 accum.
#define MG_STRIDE 80
#define MG_MAT    10240          // 128 * 80
#define MG_SMEM   (2 * 3 * MG_MAT)   // 61440 B

template<int EPI>
__global__ __launch_bounds__(256, 2)
void mgemm(const __half* __restrict__ Ah, const __half* __restrict__ Al,
           const __half* __restrict__ Bh,
           const float* __restrict__ bias, const float* __restrict__ resid,
           float* __restrict__ C, int N, int K) {
    extern __shared__ __align__(128) char smem[];
    uint32_t sb = (uint32_t)__cvta_generic_to_shared(smem);
    int tid = threadIdx.x;
    int lane = tid & 31, warp = tid >> 5;
    int bm = blockIdx.y * 128, bn = blockIdx.x * 128;
    int wm = (warp >> 2) * 64;       // 0 or 64
    int wn = (warp & 3) * 32;        // 0,32,64,96

    int nc = K / 32;

    auto issue = [&](int c) {
        int k0 = c * 32;
        uint32_t bufb = sb + (c & 1) * 3 * MG_MAT;
        #pragma unroll
        for (int m = 0; m < 3; m++) {
            const __half* src = (m == 0) ? Ah : (m == 1) ? Al : Bh;
            int rb = (m < 2) ? bm : bn;
            #pragma unroll
            for (int i = 0; i < 2; i++) {
                int idx = tid + i * 256;
                int row = idx >> 2, seg = idx & 3;
                const __half* g = src + (size_t)(rb + row) * K + k0 + seg * 8;
                uint32_t s = bufb + m * MG_MAT + row * MG_STRIDE + seg * 16;
                CP_ASYNC16(s, g);
            }
        }
        CP_COMMIT();
    };

    float acc[4][4][4];
    #pragma unroll
    for (int mt = 0; mt < 4; mt++)
        #pragma unroll
        for (int nt = 0; nt < 4; nt++)
            #pragma unroll
            for (int q = 0; q < 4; q++) acc[mt][nt][q] = 0.f;

    issue(0);
    issue(1);

    for (int c = 0; c < nc; c++) {
        if (c + 1 < nc) { CP_WAIT(1); } else { CP_WAIT(0); }
        __syncthreads();
        uint32_t base = sb + (c & 1) * 3 * MG_MAT;
        uint32_t rsel = (lane & 15) * MG_STRIDE;
        #pragma unroll
        for (int kst = 0; kst < 2; kst++) {
            uint32_t kb = kst * 32 + (lane >> 4) * 16;
            uint32_t bf[4][2], af[4][4];
            #pragma unroll
            for (int p = 0; p < 2; p++) {
                uint32_t r[4];
                ldsm4(r, base + 2 * MG_MAT + (wn + p * 16) * MG_STRIDE + rsel + kb);
                bf[p*2][0] = r[0]; bf[p*2][1] = r[2];
                bf[p*2+1][0] = r[1]; bf[p*2+1][1] = r[3];
            }
            #pragma unroll
            for (int mt = 0; mt < 4; mt++)
                ldsm4(af[mt], base + (wm + mt * 16) * MG_STRIDE + rsel + kb);
            #pragma unroll
            for (int mt = 0; mt < 4; mt++)
                #pragma unroll
                for (int nt = 0; nt < 4; nt++)
                    mma_f16(acc[mt][nt], af[mt], bf[nt]);
            #pragma unroll
            for (int mt = 0; mt < 4; mt++)
                ldsm4(af[mt], base + MG_MAT + (wm + mt * 16) * MG_STRIDE + rsel + kb);
            #pragma unroll
            for (int mt = 0; mt < 4; mt++)
                #pragma unroll
                for (int nt = 0; nt < 4; nt++)
                    mma_f16(acc[mt][nt], af[mt], bf[nt]);
        }
        __syncthreads();
        if (c + 2 < nc) issue(c + 2);
    }

    // epilogue
    int g = lane >> 2, tig = lane & 3;
    #pragma unroll
    for (int mt = 0; mt < 4; mt++) {
        size_t r0 = (size_t)bm + wm + mt * 16 + g;
        size_t r1 = r0 + 8;
        #pragma unroll
        for (int nt = 0; nt < 4; nt++) {
            int col = bn + wn + nt * 8 + tig * 2;
            float2 v0 = make_float2(acc[mt][nt][0], acc[mt][nt][1]);
            float2 v1 = make_float2(acc[mt][nt][2], acc[mt][nt][3]);
            if (EPI & EPI_BIAS) {
                float b0 = bias[col], b1 = bias[col + 1];
                v0.x += b0; v0.y += b1; v1.x += b0; v1.y += b1;
            }
            if (EPI & EPI_RESID) {
                const float* rp0 = resid + r0 * N + col;
                const float* rp1 = resid + r1 * N + col;
                v0.x += rp0[0]; v0.y += rp0[1];
                v1.x += rp1[0]; v1.y += rp1[1];
            }
            *(float2*)(C + r0 * N + col) = v0;
            *(float2*)(C + r1 * N + col) = v1;
        }
    }
}

// ---------------- double layernorm, warp-per-row ------------------------------
__global__ __launch_bounds__(256)
void ln2_kernel(const float* __restrict__ x,
                const float* __restrict__ w1, const float* __restrict__ b1,
                const float* __restrict__ w2, const float* __restrict__ b2,
                float* __restrict__ o32,
                __half* __restrict__ oh, __half* __restrict__ ol) {
    int lane = threadIdx.x & 31;
    int row = blockIdx.x * 8 + (threadIdx.x >> 5);
    const float4* xr = (const float4*)(x + (size_t)row * DQ);
    float4 v[4];
    float s = 0.f;
    #pragma unroll
    for (int i = 0; i < 4; i++) {
        v[i] = xr[lane + i * 32];
        s += v[i].x + v[i].y + v[i].z + v[i].w;
    }
    #pragma unroll
    for (int o = 16; o > 0; o >>= 1) s += __shfl_xor_sync(0xffffffffu, s, o);
    float mu = s * (1.f / DQ);
    float q = 0.f;
    #pragma unroll
    for (int i = 0; i < 4; i++) {
        float a = v[i].x - mu, b = v[i].y - mu, c = v[i].z - mu, d = v[i].w - mu;
        q += a * a + b * b + c * c + d * d;
    }
    #pragma unroll
    for (int o = 16; o > 0; o >>= 1) q += __shfl_xor_sync(0xffffffffu, q, o);
    float rs = rsqrtf(q * (1.f / DQ) + 1e-5f);
    #pragma unroll
    for (int i = 0; i < 4; i++) {
        float4 w = ((const float4*)w1)[lane + i * 32];
        float4 b = ((const float4*)b1)[lane + i * 32];
        v[i].x = (v[i].x - mu) * rs * w.x + b.x;
        v[i].y = (v[i].y - mu) * rs * w.y + b.y;
        v[i].z = (v[i].z - mu) * rs * w.z + b.z;
        v[i].w = (v[i].w - mu) * rs * w.w + b.w;
    }
    // second LN
    s = 0.f;
    #pragma unroll
    for (int i = 0; i < 4; i++) s += v[i].x + v[i].y + v[i].z + v[i].w;
    #pragma unroll
    for (int o = 16; o > 0; o >>= 1) s += __shfl_xor_sync(0xffffffffu, s, o);
    mu = s * (1.f / DQ);
    q = 0.f;
    #pragma unroll
    for (int i = 0; i < 4; i++) {
        float a = v[i].x - mu, b = v[i].y - mu, c = v[i].z - mu, d = v[i].w - mu;
        q += a * a + b * b + c * c + d * d;
    }
    #pragma unroll
    for (int o = 16; o > 0; o >>= 1) q += __shfl_xor_sync(0xffffffffu, q, o);
    rs = rsqrtf(q * (1.f / DQ) + 1e-5f);
    #pragma unroll
    for (int i = 0; i < 4; i++) {
        float4 w = ((const float4*)w2)[lane + i * 32];
        float4 b = ((const float4*)b2)[lane + i * 32];
        v[i].x = (v[i].x - mu) * rs * w.x + b.x;
        v[i].y = (v[i].y - mu) * rs * w.y + b.y;
        v[i].z = (v[i].z - mu) * rs * w.z + b.z;
        v[i].w = (v[i].w - mu) * rs * w.w + b.w;
    }
    if (o32) {
        float4* orow = (float4*)(o32 + (size_t)row * DQ);
        #pragma unroll
        for (int i = 0; i < 4; i++) orow[lane + i * 32] = v[i];
    }
    if (oh) {
        __half2* hp = (__half2*)(oh + (size_t)row * DQ);
        __half2* lp = (__half2*)(ol + (size_t)row * DQ);
        #pragma unroll
        for (int i = 0; i < 4; i++) {
            int j = (lane + i * 32) * 2;
            __half hx = __float2half_rn(v[i].x), hy = __float2half_rn(v[i].y);
            __half hz = __float2half_rn(v[i].z), hw = __float2half_rn(v[i].w);
            hp[j + 0] = __halves2half2(hx, hy);
            hp[j + 1] = __halves2half2(hz, hw);
            lp[j + 0] = __halves2half2(__float2half_rn(v[i].x - __half2float(hx)),
                                       __float2half_rn(v[i].y - __half2float(hy)));
            lp[j + 1] = __halves2half2(__float2half_rn(v[i].z - __half2float(hz)),
                                       __float2half_rn(v[i].w - __half2float(hw)));
        }
    }
}

// ---------------- fp32 -> fp16 hi/lo split ------------------------------------
__global__ void split_kernel(const float* __restrict__ s,
                             __half* __restrict__ h,
                             __half* __restrict__ l, int n4) {
    int i = blockIdx.x * 256 + threadIdx.x;
    if (i >= n4) return;
    float4 v = ((const float4*)s)[i];
    __half hx = __float2half_rn(v.x), hy = __float2half_rn(v.y);
    __half hz = __float2half_rn(v.z), hw = __float2half_rn(v.w);
    __half2* hp = (__half2*)h;
    hp[2 * i + 0] = __halves2half2(hx, hy);
    hp[2 * i + 1] = __halves2half2(hz, hw);
    if (l) {
        __half2* lp = (__half2*)l;
        lp[2 * i + 0] = __halves2half2(__float2half_rn(v.x - __half2float(hx)),
                                       __float2half_rn(v.y - __half2float(hy)));
        lp[2 * i + 1] = __halves2half2(__float2half_rn(v.z - __half2float(hz)),
                                       __float2half_rn(v.w - __half2float(hw)));
    }
}

// ---------------- fp32 SGEMM 128x128 (dt_proj, K=32) --------------------------
template<int EPI>
__global__ __launch_bounds__(256, 2)
void sgemm128(const float* __restrict__ A, const float* __restrict__ B,
              const float* __restrict__ bias, const float* __restrict__ resid,
              float* __restrict__ C, int N, int K, int lda, int ldb) {
    const int TK = 16;
    __shared__ __align__(16) float As[2][TK][128 + 4];
    __shared__ __align__(16) float Bs[2][TK][128 + 4];

    int tid = threadIdx.x;
    int bm = blockIdx.y * 128;
    int bn = blockIdx.x * 128;
    int arow = tid >> 2;
    int acol = (tid & 3) << 2;
    int tmb = (tid >> 4) << 3;
    int tnb = (tid & 15) << 3;

    const float* Ap0 = A + (size_t)(bm + arow) * lda + acol;
    const float* Ap1 = A + (size_t)(bm + arow + 64) * lda + acol;
    const float* Bp0 = B + (size_t)(bn + arow) * ldb + acol;
    const float* Bp1 = B + (size_t)(bn + arow + 64) * ldb + acol;

    float4 ra0 = *(const float4*)(Ap0);
    float4 ra1 = *(const float4*)(Ap1);
    float4 rb0 = *(const float4*)(Bp0);
    float4 rb1 = *(const float4*)(Bp1);
    As[0][acol+0][arow] = ra0.x; As[0][acol+1][arow] = ra0.y;
    As[0][acol+2][arow] = ra0.z; As[0][acol+3][arow] = ra0.w;
    As[0][acol+0][arow+64] = ra1.x; As[0][acol+1][arow+64] = ra1.y;
    As[0][acol+2][arow+64] = ra1.z; As[0][acol+3][arow+64] = ra1.w;
    Bs[0][acol+0][arow] = rb0.x; Bs[0][acol+1][arow] = rb0.y;
    Bs[0][acol+2][arow] = rb0.z; Bs[0][acol+3][arow] = rb0.w;
    Bs[0][acol+0][arow+64] = rb1.x; Bs[0][acol+1][arow+64] = rb1.y;
    Bs[0][acol+2][arow+64] = rb1.z; Bs[0][acol+3][arow+64] = rb1.w;
    __syncthreads();

    float acc[8][8];
    #pragma unroll
    for (int i = 0; i < 8; i++)
        #pragma unroll
        for (int j = 0; j < 8; j++) acc[i][j] = 0.f;

    int nk = K / TK;
    for (int it = 0; it < nk; it++) {
        int cur = it & 1, nxt = cur ^ 1;
        bool more = (it + 1 < nk);
        if (more) {
            int ko = (it + 1) * TK;
            ra0 = *(const float4*)(Ap0 + ko);
            ra1 = *(const float4*)(Ap1 + ko);
            rb0 = *(const float4*)(Bp0 + ko);
            rb1 = *(const float4*)(Bp1 + ko);
        }
        #pragma unroll
        for (int kk = 0; kk < TK; kk++) {
            float a[8], b[8];
            float4 a0 = *(const float4*)&As[cur][kk][tmb];
            float4 a1 = *(const float4*)&As[cur][kk][tmb + 4];
            float4 b0 = *(const float4*)&Bs[cur][kk][tnb];
            float4 b1 = *(const float4*)&Bs[cur][kk][tnb + 4];
            a[0]=a0.x;a[1]=a0.y;a[2]=a0.z;a[3]=a0.w;a[4]=a1.x;a[5]=a1.y;a[6]=a1.z;a[7]=a1.w;
            b[0]=b0.x;b[1]=b0.y;b[2]=b0.z;b[3]=b0.w;b[4]=b1.x;b[5]=b1.y;b[6]=b1.z;b[7]=b1.w;
            #pragma unroll
            for (int i = 0; i < 8; i++)
                #pragma unroll
                for (int j = 0; j < 8; j++)
                    acc[i][j] = fmaf(a[i], b[j], acc[i][j]);
        }
        if (more) {
            As[nxt][acol+0][arow] = ra0.x; As[nxt][acol+1][arow] = ra0.y;
            As[nxt][acol+2][arow] = ra0.z; As[nxt][acol+3][arow] = ra0.w;
            As[nxt][acol+0][arow+64] = ra1.x; As[nxt][acol+1][arow+64] = ra1.y;
            As[nxt][acol+2][arow+64] = ra1.z; As[nxt][acol+3][arow+64] = ra1.w;
            Bs[nxt][acol+0][arow] = rb0.x; Bs[nxt][acol+1][arow] = rb0.y;
            Bs[nxt][acol+2][arow] = rb0.z; Bs[nxt][acol+3][arow] = rb0.w;
            Bs[nxt][acol+0][arow+64] = rb1.x; Bs[nxt][acol+1][arow+64] = rb1.y;
            Bs[nxt][acol+2][arow+64] = rb1.z; Bs[nxt][acol+3][arow+64] = rb1.w;
        }
        __syncthreads();
    }

    #pragma unroll
    for (int i = 0; i < 8; i++) {
        size_t row = bm + tmb + i;
        #pragma unroll
        for (int j = 0; j < 8; j++) {
            int col = bn + tnb + j;
            float v = acc[i][j];
            if (EPI & EPI_BIAS)     v += bias[col];
            if (EPI & EPI_SOFTPLUS) v = (v > 20.f) ? v : log1pf(__expf(v));
            if (EPI & EPI_RESID)    v += resid[row * N + col];
            C[row * N + col] = v;
        }
    }
}

// ---------------- x_proj: [4096,1024] x [64,1024]^T, 16 rows/CTA --------------
// conflict-free: row-major smem [row][68], float4-over-k inner, 4 cols/thread
__global__ __launch_bounds__(256)
void xproj_kernel(const float* __restrict__ A, const float* __restrict__ B,
                  float* __restrict__ C) {
    __shared__ float As[16][68];
    __shared__ float Bs[64][68];
    int tid = threadIdx.x;
    int r0 = blockIdx.x * 16;
    int rr = tid >> 4;        // 0..15 (row)
    int ccq = tid & 15;       // 0..15 (col group)
    float acc[4] = {0.f, 0.f, 0.f, 0.f};

    for (int k0 = 0; k0 < 1024; k0 += 64) {
        {
            int row = tid >> 4, seg = tid & 15;
            *(float4*)&As[row][seg * 4] =
                *(const float4*)(A + (size_t)(r0 + row) * 1024 + k0 + seg * 4);
        }
        #pragma unroll
        for (int i = 0; i < 4; i++) {
            int idx = tid + i * 256;
            int row = idx >> 4, seg = idx & 15;
            *(float4*)&Bs[row][seg * 4] =
                *(const float4*)(B + (size_t)row * 1024 + k0 + seg * 4);
        }
        __syncthreads();
        #pragma unroll 4
        for (int kk = 0; kk < 64; kk += 4) {
            float4 a = *(float4*)&As[rr][kk];
            #pragma unroll
            for (int j = 0; j < 4; j++) {
                float4 b = *(float4*)&Bs[ccq + 16 * j][kk];
                acc[j] = fmaf(a.x, b.x, acc[j]);
                acc[j] = fmaf(a.y, b.y, acc[j]);
                acc[j] = fmaf(a.z, b.z, acc[j]);
                acc[j] = fmaf(a.w, b.w, acc[j]);
            }
        }
        __syncthreads();
    }
    #pragma unroll
    for (int j = 0; j < 4; j++)
        C[(size_t)(r0 + rr) * 64 + ccq + 16 * j] = acc[j];
}

// ---------------- causal depthwise conv (k=4) + silu --------------------------
__global__ void conv_silu_kernel(const float* __restrict__ xz,
                                 const float* __restrict__ cw,
                                 const float* __restrict__ cb,
                                 float* __restrict__ xc) {
    int idx = blockIdx.x * blockDim.x + threadIdx.x;
    if (idx >= BL * DI) return;
    int d = idx & (DI - 1);
    int row = idx >> 10;
    int l = row & (LQ - 1);
    float s = cb[d];
    #pragma unroll
    for (int j = 0; j < 4; j++) {
        int lp = l - 3 + j;
        if (lp >= 0)
            s = fmaf(xz[(size_t)(row - 3 + j) * 2048 + d], cw[d * 4 + j], s);
    }
    float sig = 1.f / (1.f + __expf(-s));
    xc[idx] = s * sig;
}

// ---------------- chunked scan, pass 1 ---------------------------------------
__global__ __launch_bounds__(256)
void scan1_kernel(const float* __restrict__ delta_sp,
                  const float* __restrict__ xc,
                  const float* __restrict__ dbc,
                  const float* __restrict__ A_log,
                  float* __restrict__ Pout, float* __restrict__ Sout) {
    __shared__ float s_dl[TC][16];
    __shared__ float s_xv[TC][16];
    __shared__ float s_B[TC][16];
    int bx = blockIdx.x;
    int dt = bx & 63;
    int c  = (bx >> 6) & 15;
    int b  = bx >> 10;
    int tid = threadIdx.x;
    int n = tid & 15, dloc = tid >> 4;
    int d = dt * 16 + dloc;
    size_t row0 = (size_t)b * LQ + c * TC;

    #pragma unroll
    for (int i = 0; i < 2; i++) {
        int idx = tid + i * 256;
        int t = idx >> 2, q = idx & 3;
        *(float4*)&s_dl[t][q * 4] = *(const float4*)(delta_sp + (row0 + t) * DI + dt * 16 + q * 4);
        *(float4*)&s_xv[t][q * 4] = *(const float4*)(xc + (row0 + t) * DI + dt * 16 + q * 4);
        *(float4*)&s_B[t][q * 4]  = *(const float4*)(dbc + (row0 + t) * 64 + 32 + q * 4);
    }
    __syncthreads();

    float An = -__expf(A_log[d * DSTATE + n]);
    float h = 0.f, P = 1.f;
    #pragma unroll 4
    for (int t = 0; t < TC; t++) {
        float dl = s_dl[t][dloc];
        float dA = __expf(dl * An);
        h = fmaf(dA, h, dl * s_B[t][n] * s_xv[t][dloc]);
        P *= dA;
    }
    size_t o = (((size_t)b * NCH + c) * DI + (size_t)dt * 16) * DSTATE + tid;
    Pout[o] = P;
    Sout[o] = h;
}

// ---------------- chunked scan: carry -----------------------------------------
__global__ void scan_carry_kernel(const float* __restrict__ P,
                                  const float* __restrict__ S,
                                  float* __restrict__ H) {
    int idx = blockIdx.x * 256 + threadIdx.x;
    int b = idx >> 14;
    int rem = idx & 16383;
    float carry = 0.f;
    #pragma unroll
    for (int c = 0; c < NCH; c++) {
        size_t o = (((size_t)b * NCH + c) << 14) + rem;
        H[o] = carry;
        carry = fmaf(P[o], carry, S[o]);
    }
}

// ---------------- chunked scan, pass 2: fp16 hi/lo out ------------------------
__global__ __launch_bounds__(256)
void scan2_kernel(const float* __restrict__ delta_sp,
                  const float* __restrict__ xc,
                  const float* __restrict__ dbc,
                  const float* __restrict__ xz,
                  const float* __restrict__ A_log,
                  const float* __restrict__ D_param,
                  const float* __restrict__ H,
                  __half* __restrict__ yh,
                  __half* __restrict__ yl) {
    __shared__ float s_dl[TC][16];
    __shared__ float s_xv[TC][16];
    __shared__ float s_B[TC][16];
    __shared__ float s_C[TC][16];
    __shared__ float s_y[TC][16];
    int bx = blockIdx.x;
    int dt = bx & 63;
    int c  = (bx >> 6) & 15;
    int b  = bx >> 10;
    int tid = threadIdx.x;
    int n = tid & 15, dloc = tid >> 4;
    int d = dt * 16 + dloc;
    size_t row0 = (size_t)b * LQ + c * TC;

    #pragma unroll
    for (int i = 0; i < 2; i++) {
        int idx = tid + i * 256;
        int t = idx >> 2, q = idx & 3;
        *(float4*)&s_dl[t][q * 4] = *(const float4*)(delta_sp + (row0 + t) * DI + dt * 16 + q * 4);
        *(float4*)&s_xv[t][q * 4] = *(const float4*)(xc + (row0 + t) * DI + dt * 16 + q * 4);
        *(float4*)&s_B[t][q * 4]  = *(const float4*)(dbc + (row0 + t) * 64 + 32 + q * 4);
        *(float4*)&s_C[t][q * 4]  = *(const float4*)(dbc + (row0 + t) * 64 + 48 + q * 4);
    }
    __syncthreads();

    float An = -__expf(A_log[d * DSTATE + n]);
    float Dp = D_param[d];
    size_t o = (((size_t)b * NCH + c) * DI + (size_t)dt * 16) * DSTATE + tid;
    float h = H[o];

    #pragma unroll 4
    for (int t = 0; t < TC; t++) {
        float dl = s_dl[t][dloc];
        float xv = s_xv[t][dloc];
        float dA = __expf(dl * An);
        h = fmaf(dA, h, dl * s_B[t][n] * xv);
        float p = h * s_C[t][n];
        p += __shfl_xor_sync(0xffffffffu, p, 1);
        p += __shfl_xor_sync(0xffffffffu, p, 2);
        p += __shfl_xor_sync(0xffffffffu, p, 4);
        p += __shfl_xor_sync(0xffffffffu, p, 8);
        if (n == 0) s_y[t][dloc] = p + Dp * xv;
    }
    __syncthreads();

    #pragma unroll
    for (int i = 0; i < 8; i++) {
        int idx = tid + i * 256;
        int t = idx >> 4, dl2 = idx & 15;
        size_t row = row0 + t;
        float zv = xz[row * 2048 + DI + dt * 16 + dl2];
        float sz = zv / (1.f + __expf(-zv));
        float yv = s_y[t][dl2] * sz;
        __half hv = __float2half_rn(yv);
        yh[row * DI + dt * 16 + dl2] = hv;
        yl[row * DI + dt * 16 + dl2] = __float2half_rn(yv - __half2float(hv));
    }
}

// ---------------- KAN basis to fp16 hi/lo -------------------------------------
__global__ void basis_split_kernel(const float* __restrict__ k,
                                   const float* __restrict__ grid,
                                   __half* __restrict__ bh,
                                   __half* __restrict__ bl) {
    int idx = blockIdx.x * blockDim.x + threadIdx.x;
    int j = idx & 4095;
    int row = idx >> 12;
    int d = j >> 3, g = j & 7;
    float t = tanhf((k[(size_t)row * DQ + d] - grid[g]) * (float)(1.0 / 0.33));
    float v = 1.f - t * t;
    __half h = __float2half_rn(v);
    bh[idx] = h;
    bl[idx] = __float2half_rn(v - __half2float(h));
}

// ---------------- host orchestration ------------------------------------------
extern "C" void kernel_launch(void* const* d_in, const int* in_sizes, int n_in,
                              void* d_out, int out_size) {
    const float* x      = (const float*)d_in[0];
    const float* n1_w   = (const float*)d_in[1];
    const float* n1_b   = (const float*)d_in[2];
    const float* mn_w   = (const float*)d_in[3];
    const float* mn_b   = (const float*)d_in[4];
    const float* in_w   = (const float*)d_in[5];
    const float* in_b   = (const float*)d_in[6];
    const float* conv_w = (const float*)d_in[7];
    const float* conv_b = (const float*)d_in[8];
    const float* xp_w   = (const float*)d_in[9];
    const float* dt_w   = (const float*)d_in[10];
    const float* dt_b   = (const float*)d_in[11];
    const float* A_log  = (const float*)d_in[12];
    const float* D_par  = (const float*)d_in[13];
    const float* out_w  = (const float*)d_in[14];
    const float* out_b  = (const float*)d_in[15];
    const float* n2_w   = (const float*)d_in[16];
    const float* n2_b   = (const float*)d_in[17];
    const float* kn_w   = (const float*)d_in[18];
    const float* kn_b   = (const float*)d_in[19];
    const float* grid   = (const float*)d_in[20];
    const float* spl_w  = (const float*)d_in[21];
    float* out = (float*)d_out;

    float *p_xz, *p_xc, *p_dbc, *p_delta, *p_x2, *p_k, *p_P, *p_S, *p_H;
    __half *p_uh, *p_ul, *p_iwh, *p_yh, *p_yl, *p_owh, *p_bh, *p_bl, *p_swh;
    cudaGetSymbolAddress((void**)&p_xz,    g_xz);
    cudaGetSymbolAddress((void**)&p_xc,    g_xc);
    cudaGetSymbolAddress((void**)&p_dbc,   g_dbc);
    cudaGetSymbolAddress((void**)&p_delta, g_delta);
    cudaGetSymbolAddress((void**)&p_x2,    g_x2);
    cudaGetSymbolAddress((void**)&p_k,     g_k);
    cudaGetSymbolAddress((void**)&p_P,     g_P);
    cudaGetSymbolAddress((void**)&p_S,     g_S);
    cudaGetSymbolAddress((void**)&p_H,     g_H);
    cudaGetSymbolAddress((void**)&p_uh,  g_uh);  cudaGetSymbolAddress((void**)&p_ul,  g_ul);
    cudaGetSymbolAddress((void**)&p_iwh, g_iwh);
    cudaGetSymbolAddress((void**)&p_yh,  g_yh);  cudaGetSymbolAddress((void**)&p_yl,  g_yl);
    cudaGetSymbolAddress((void**)&p_owh, g_owh);
    cudaGetSymbolAddress((void**)&p_bh,  g_bh);  cudaGetSymbolAddress((void**)&p_bl,  g_bl);
    cudaGetSymbolAddress((void**)&p_swh, g_swh);

    cudaFuncSetAttribute(mgemm<EPI_BIAS>,
                         cudaFuncAttributeMaxDynamicSharedMemorySize, MG_SMEM);
    cudaFuncSetAttribute(mgemm<EPI_BIAS | EPI_RESID>,
                         cudaFuncAttributeMaxDynamicSharedMemorySize, MG_SMEM);
    cudaFuncSetAttribute(mgemm<EPI_RESID>,
                         cudaFuncAttributeMaxDynamicSharedMemorySize, MG_SMEM);

    // weight rounding to fp16 (hi only)
    split_kernel<<<(2048 * DQ / 4 + 255) / 256, 256>>>(in_w,  p_iwh, nullptr, 2048 * DQ / 4);
    split_kernel<<<(DQ * DI / 4 + 255) / 256, 256>>>(out_w, p_owh, nullptr, DQ * DI / 4);
    split_kernel<<<(DQ * 4096 / 4 + 255) / 256, 256>>>(spl_w, p_swh, nullptr, DQ * 4096 / 4);

    // 1. u = LN(LN(x)) -> fp16 hi/lo
    ln2_kernel<<<BL / 8, 256>>>(x, n1_w, n1_b, mn_w, mn_b, nullptr, p_uh, p_ul);

    // 2. xz = u @ in_w^T + in_b   [4096 x 2048, K=512]
    mgemm<EPI_BIAS><<<dim3(2048 / 128, BL / 128), 256, MG_SMEM>>>(
        p_uh, p_ul, p_iwh, in_b, nullptr, p_xz, 2048, DQ);

    // 3. conv + silu
    conv_silu_kernel<<<(BL * DI) / 256, 256>>>(p_xz, conv_w, conv_b, p_xc);

    // 4. dbc = xc @ xp_w^T  [4096 x 64, K=1024]
    xproj_kernel<<<BL / 16, 256>>>(p_xc, xp_w, p_dbc);

    // 5. delta = softplus(dt_proj)  [4096 x 1024, K=32]
    sgemm128<EPI_BIAS | EPI_SOFTPLUS><<<dim3(DI / 128, BL / 128), 256>>>(
        p_dbc, dt_w, dt_b, nullptr, p_delta, DI, 32, 64, 32);

    // 6. chunked parallel scan -> y hi/lo
    scan1_kernel<<<BQ * NCH * 64, 256>>>(p_delta, p_xc, p_dbc, A_log, p_P, p_S);
    scan_carry_kernel<<<(BQ * DI * DSTATE) / 256, 256>>>(p_P, p_S, p_H);
    scan2_kernel<<<BQ * NCH * 64, 256>>>(p_delta, p_xc, p_dbc, p_xz, A_log, D_par,
                                         p_H, p_yh, p_yl);

    // 7. x2 = x + y @ out_w^T + out_b  [4096 x 512, K=1024]
    mgemm<EPI_BIAS | EPI_RESID><<<dim3(DQ / 128, BL / 128), 256, MG_SMEM>>>(
        p_yh, p_yl, p_owh, out_b, x, p_x2, DQ, DI);

    // 8. k = LN(LN(x2)) -> fp32
    ln2_kernel<<<BL / 8, 256>>>(p_x2, n2_w, n2_b, kn_w, kn_b, p_k, nullptr, nullptr);

    // 9. basis -> fp16 hi/lo
    basis_split_kernel<<<(BL * 4096) / 256, 256>>>(p_k, grid, p_bh, p_bl);

    // 10. out = x2 + basis @ spl_w^T  [4096 x 512, K=4096]
    mgemm<EPI_RESID><<<dim3(DQ / 128, BL / 128), 256, MG_SMEM>>>(
        p_bh, p_bl, p_swh, nullptr, p_x2, out, DQ, 4096);

    (void)in_sizes; (void)n_in; (void)out_size;
}

// round 7
// speedup vs baseline: 4.9118x; 1.0047x over previous
#include <cuda_runtime.h>
#include <cuda_fp16.h>
#include <math.h>
#include <stdint.h>

// Problem constants
#define BQ 2
#define LQ 2048
#define DQ 512
#define DI 1024
#define BL (BQ*LQ)          // 4096 rows
#define DSTATE 16
#define NG 8
#define TC 128              // scan chunk length
#define NCH (LQ/TC)         // 16 chunks

// ---------------- device scratch ---------------------------------------------
__device__ float g_xz[(size_t)BL*2048];      // in_proj output (xm | z), fp32
__device__ float g_xc[(size_t)BL*DI];        // conv+silu
__device__ float g_dbc[BL*64];               // x_proj output
__device__ float g_delta[(size_t)BL*DI];     // softplus(dt_proj)
__device__ float g_x2[BL*DQ];                // x + mix
__device__ float g_k[BL*DQ];                 // LN(LN(x2))

__device__ float g_P[(size_t)BQ*NCH*DI*DSTATE];  // chunk products
__device__ float g_S[(size_t)BQ*NCH*DI*DSTATE];  // chunk local end states
__device__ float g_H[(size_t)BQ*NCH*DI*DSTATE];  // chunk initial states

__device__ __half g_uh[(size_t)BL*DQ],  g_ul[(size_t)BL*DQ];    // ln2(x) hi/lo
__device__ __half g_iwh[2048*DQ];                                // in_w fp16
__device__ __half g_yh[(size_t)BL*DI],  g_yl[(size_t)BL*DI];    // scan out
__device__ __half g_owh[DQ*DI];                                  // out_w fp16
__device__ __half g_bh[(size_t)BL*4096],g_bl[(size_t)BL*4096];  // KAN basis
__device__ __half g_swh[DQ*4096];                                // spl_w fp16

// ---------------- PTX helpers (sm_80-class, valid on sm_100) ------------------
#define CP_ASYNC16(s, g) \
    asm volatile("cp.async.cg.shared.global [%0], [%1], 16;" :: "r"(s), "l"(g))
#define CP_COMMIT() asm volatile("cp.async.commit_group;" ::: "memory")
#define CP_WAIT(n)  asm volatile("cp.async.wait_group %0;" :: "n"(n) : "memory")

__device__ __forceinline__ void ldsm4(uint32_t* r, uint32_t addr) {
    asm volatile("ldmatrix.sync.aligned.m8n8.x4.shared.b16 {%0,%1,%2,%3}, [%4];"
                 : "=r"(r[0]), "=r"(r[1]), "=r"(r[2]), "=r"(r[3]) : "r"(addr));
}
__device__ __forceinline__ void mma_f16(float* c, const uint32_t* a, const uint32_t* b) {
    asm volatile("mma.sync.aligned.m16n8k16.row.col.f32.f16.f16.f32 "
                 "{%0,%1,%2,%3}, {%4,%5,%6,%7}, {%8,%9}, {%0,%1,%2,%3};"
                 : "+f"(c[0]), "+f"(c[1]), "+f"(c[2]), "+f"(c[3])
                 : "r"(a[0]), "r"(a[1]), "r"(a[2]), "r"(a[3]),
                   "r"(b[0]), "r"(b[1]));
}

// ---------------- epilogue flags ---------------------------------------------
#define EPI_BIAS 1
#define EPI_RESID 2
#define EPI_SOFTPLUS 4

// ---------------- split-fp16 2-term NT GEMM via mma.sync ----------------------
// C[M,N] = (Ah+Al)[M,K] * Bh[N,K]^T, fp32 accum.
// Block tile 128 x NT (NT = 128 or 64), K chunks of 32, cp.async 2-stage.
// Smem stride 80 B/row (ldmatrix conflict-free).
#define MG_STRIDE 80
#define MG_A 10240                 // 128 * 80 per A matrix

template<int NT, int EPI>
__global__ __launch_bounds__(256, 2)
void mgemm(const __half* __restrict__ Ah, const __half* __restrict__ Al,
           const __half* __restrict__ Bh,
           const float* __restrict__ bias, const float* __restrict__ resid,
           float* __restrict__ C, int N, int K) {
    constexpr int MT = (NT == 128) ? 4 : 2;    // m-frags (16 rows) per warp
    constexpr int S_B = NT * MG_STRIDE;
    constexpr int STAGE = 2 * MG_A + S_B;

    extern __shared__ __align__(128) char smem[];
    uint32_t sb = (uint32_t)__cvta_generic_to_shared(smem);
    int tid = threadIdx.x;
    int lane = tid & 31, warp = tid >> 5;
    int bm = blockIdx.y * 128, bn = blockIdx.x * NT;
    int wm = (NT == 128) ? (warp >> 2) * 64 : (warp >> 1) * 32;
    int wn = (NT == 128) ? (warp & 3) * 32 : (warp & 1) * 32;

    int nc = K / 32;

    auto issue = [&](int c) {
        int k0 = c * 32;
        uint32_t bufb = sb + (c & 1) * STAGE;
        #pragma unroll
        for (int m = 0; m < 2; m++) {
            const __half* src = m ? Al : Ah;
            #pragma unroll
            for (int i = 0; i < 2; i++) {
                int idx = tid + i * 256;
                int row = idx >> 2, seg = idx & 3;
                const __half* g = src + (size_t)(bm + row) * K + k0 + seg * 8;
                CP_ASYNC16(bufb + m * MG_A + row * MG_STRIDE + seg * 16, g);
            }
        }
        #pragma unroll
        for (int i = 0; i < NT / 64; i++) {
            int idx = tid + i * 256;
            int row = idx >> 2, seg = idx & 3;
            const __half* g = Bh + (size_t)(bn + row) * K + k0 + seg * 8;
            CP_ASYNC16(bufb + 2 * MG_A + row * MG_STRIDE + seg * 16, g);
        }
        CP_COMMIT();
    };

    float acc[MT][4][4];
    #pragma unroll
    for (int mt = 0; mt < MT; mt++)
        #pragma unroll
        for (int nt = 0; nt < 4; nt++)
            #pragma unroll
            for (int q = 0; q < 4; q++) acc[mt][nt][q] = 0.f;

    issue(0);
    issue(1);

    for (int c = 0; c < nc; c++) {
        if (c + 1 < nc) { CP_WAIT(1); } else { CP_WAIT(0); }
        __syncthreads();
        uint32_t base = sb + (c & 1) * STAGE;
        uint32_t rsel = (lane & 15) * MG_STRIDE;
        #pragma unroll
        for (int kst = 0; kst < 2; kst++) {
            uint32_t kb = kst * 32 + (lane >> 4) * 16;
            uint32_t bf[4][2], af[MT][4];
            #pragma unroll
            for (int p = 0; p < 2; p++) {
                uint32_t r[4];
                ldsm4(r, base + 2 * MG_A + (wn + p * 16) * MG_STRIDE + rsel + kb);
                bf[p*2][0] = r[0]; bf[p*2][1] = r[2];
                bf[p*2+1][0] = r[1]; bf[p*2+1][1] = r[3];
            }
            #pragma unroll
            for (int mt = 0; mt < MT; mt++)
                ldsm4(af[mt], base + (wm + mt * 16) * MG_STRIDE + rsel + kb);
            #pragma unroll
            for (int mt = 0; mt < MT; mt++)
                #pragma unroll
                for (int nt = 0; nt < 4; nt++)
                    mma_f16(acc[mt][nt], af[mt], bf[nt]);
            #pragma unroll
            for (int mt = 0; mt < MT; mt++)
                ldsm4(af[mt], base + MG_A + (wm + mt * 16) * MG_STRIDE + rsel + kb);
            #pragma unroll
            for (int mt = 0; mt < MT; mt++)
                #pragma unroll
                for (int nt = 0; nt < 4; nt++)
                    mma_f16(acc[mt][nt], af[mt], bf[nt]);
        }
        __syncthreads();
        if (c + 2 < nc) issue(c + 2);
    }

    // epilogue
    int g = lane >> 2, tig = lane & 3;
    #pragma unroll
    for (int mt = 0; mt < MT; mt++) {
        size_t r0 = (size_t)bm + wm + mt * 16 + g;
        size_t r1 = r0 + 8;
        #pragma unroll
        for (int nt = 0; nt < 4; nt++) {
            int col = bn + wn + nt * 8 + tig * 2;
            float2 v0 = make_float2(acc[mt][nt][0], acc[mt][nt][1]);
            float2 v1 = make_float2(acc[mt][nt][2], acc[mt][nt][3]);
            if (EPI & EPI_BIAS) {
                float b0 = bias[col], b1 = bias[col + 1];
                v0.x += b0; v0.y += b1; v1.x += b0; v1.y += b1;
            }
            if (EPI & EPI_RESID) {
                const float* rp0 = resid + r0 * N + col;
                const float* rp1 = resid + r1 * N + col;
                v0.x += rp0[0]; v0.y += rp0[1];
                v1.x += rp1[0]; v1.y += rp1[1];
            }
            *(float2*)(C + r0 * N + col) = v0;
            *(float2*)(C + r1 * N + col) = v1;
        }
    }
}

// ---------------- double layernorm, warp-per-row ------------------------------
__global__ __launch_bounds__(256)
void ln2_kernel(const float* __restrict__ x,
                const float* __restrict__ w1, const float* __restrict__ b1,
                const float* __restrict__ w2, const float* __restrict__ b2,
                float* __restrict__ o32,
                __half* __restrict__ oh, __half* __restrict__ ol) {
    int lane = threadIdx.x & 31;
    int row = blockIdx.x * 8 + (threadIdx.x >> 5);
    const float4* xr = (const float4*)(x + (size_t)row * DQ);
    float4 v[4];
    float s = 0.f;
    #pragma unroll
    for (int i = 0; i < 4; i++) {
        v[i] = xr[lane + i * 32];
        s += v[i].x + v[i].y + v[i].z + v[i].w;
    }
    #pragma unroll
    for (int o = 16; o > 0; o >>= 1) s += __shfl_xor_sync(0xffffffffu, s, o);
    float mu = s * (1.f / DQ);
    float q = 0.f;
    #pragma unroll
    for (int i = 0; i < 4; i++) {
        float a = v[i].x - mu, b = v[i].y - mu, c = v[i].z - mu, d = v[i].w - mu;
        q += a * a + b * b + c * c + d * d;
    }
    #pragma unroll
    for (int o = 16; o > 0; o >>= 1) q += __shfl_xor_sync(0xffffffffu, q, o);
    float rs = rsqrtf(q * (1.f / DQ) + 1e-5f);
    #pragma unroll
    for (int i = 0; i < 4; i++) {
        float4 w = ((const float4*)w1)[lane + i * 32];
        float4 b = ((const float4*)b1)[lane + i * 32];
        v[i].x = (v[i].x - mu) * rs * w.x + b.x;
        v[i].y = (v[i].y - mu) * rs * w.y + b.y;
        v[i].z = (v[i].z - mu) * rs * w.z + b.z;
        v[i].w = (v[i].w - mu) * rs * w.w + b.w;
    }
    // second LN
    s = 0.f;
    #pragma unroll
    for (int i = 0; i < 4; i++) s += v[i].x + v[i].y + v[i].z + v[i].w;
    #pragma unroll
    for (int o = 16; o > 0; o >>= 1) s += __shfl_xor_sync(0xffffffffu, s, o);
    mu = s * (1.f / DQ);
    q = 0.f;
    #pragma unroll
    for (int i = 0; i < 4; i++) {
        float a = v[i].x - mu, b = v[i].y - mu, c = v[i].z - mu, d = v[i].w - mu;
        q += a * a + b * b + c * c + d * d;
    }
    #pragma unroll
    for (int o = 16; o > 0; o >>= 1) q += __shfl_xor_sync(0xffffffffu, q, o);
    rs = rsqrtf(q * (1.f / DQ) + 1e-5f);
    #pragma unroll
    for (int i = 0; i < 4; i++) {
        float4 w = ((const float4*)w2)[lane + i * 32];
        float4 b = ((const float4*)b2)[lane + i * 32];
        v[i].x = (v[i].x - mu) * rs * w.x + b.x;
        v[i].y = (v[i].y - mu) * rs * w.y + b.y;
        v[i].z = (v[i].z - mu) * rs * w.z + b.z;
        v[i].w = (v[i].w - mu) * rs * w.w + b.w;
    }
    if (o32) {
        float4* orow = (float4*)(o32 + (size_t)row * DQ);
        #pragma unroll
        for (int i = 0; i < 4; i++) orow[lane + i * 32] = v[i];
    }
    if (oh) {
        __half2* hp = (__half2*)(oh + (size_t)row * DQ);
        __half2* lp = (__half2*)(ol + (size_t)row * DQ);
        #pragma unroll
        for (int i = 0; i < 4; i++) {
            int j = (lane + i * 32) * 2;
            __half hx = __float2half_rn(v[i].x), hy = __float2half_rn(v[i].y);
            __half hz = __float2half_rn(v[i].z), hw = __float2half_rn(v[i].w);
            hp[j + 0] = __halves2half2(hx, hy);
            hp[j + 1] = __halves2half2(hz, hw);
            lp[j + 0] = __halves2half2(__float2half_rn(v[i].x - __half2float(hx)),
                                       __float2half_rn(v[i].y - __half2float(hy)));
            lp[j + 1] = __halves2half2(__float2half_rn(v[i].z - __half2float(hz)),
                                       __float2half_rn(v[i].w - __half2float(hw)));
        }
    }
}

// ---------------- fp32 -> fp16 hi/lo split ------------------------------------
__global__ void split_kernel(const float* __restrict__ s,
                             __half* __restrict__ h,
                             __half* __restrict__ l, int n4) {
    int i = blockIdx.x * 256 + threadIdx.x;
    if (i >= n4) return;
    float4 v = ((const float4*)s)[i];
    __half hx = __float2half_rn(v.x), hy = __float2half_rn(v.y);
    __half hz = __float2half_rn(v.z), hw = __float2half_rn(v.w);
    __half2* hp = (__half2*)h;
    hp[2 * i + 0] = __halves2half2(hx, hy);
    hp[2 * i + 1] = __halves2half2(hz, hw);
    if (l) {
        __half2* lp = (__half2*)l;
        lp[2 * i + 0] = __halves2half2(__float2half_rn(v.x - __half2float(hx)),
                                       __float2half_rn(v.y - __half2float(hy)));
        lp[2 * i + 1] = __halves2half2(__float2half_rn(v.z - __half2float(hz)),
                                       __float2half_rn(v.w - __half2float(hw)));
    }
}

// ---------------- fp32 SGEMM 128x128 (dt_proj, K=32) --------------------------
template<int EPI>
__global__ __launch_bounds__(256, 2)
void sgemm128(const float* __restrict__ A, const float* __restrict__ B,
              const float* __restrict__ bias, const float* __restrict__ resid,
              float* __restrict__ C, int N, int K, int lda, int ldb) {
    const int TK = 16;
    __shared__ __align__(16) float As[2][TK][128 + 4];
    __shared__ __align__(16) float Bs[2][TK][128 + 4];

    int tid = threadIdx.x;
    int bm = blockIdx.y * 128;
    int bn = blockIdx.x * 128;
    int arow = tid >> 2;
    int acol = (tid & 3) << 2;
    int tmb = (tid >> 4) << 3;
    int tnb = (tid & 15) << 3;

    const float* Ap0 = A + (size_t)(bm + arow) * lda + acol;
    const float* Ap1 = A + (size_t)(bm + arow + 64) * lda + acol;
    const float* Bp0 = B + (size_t)(bn + arow) * ldb + acol;
    const float* Bp1 = B + (size_t)(bn + arow + 64) * ldb + acol;

    float4 ra0 = *(const float4*)(Ap0);
    float4 ra1 = *(const float4*)(Ap1);
    float4 rb0 = *(const float4*)(Bp0);
    float4 rb1 = *(const float4*)(Bp1);
    As[0][acol+0][arow] = ra0.x; As[0][acol+1][arow] = ra0.y;
    As[0][acol+2][arow] = ra0.z; As[0][acol+3][arow] = ra0.w;
    As[0][acol+0][arow+64] = ra1.x; As[0][acol+1][arow+64] = ra1.y;
    As[0][acol+2][arow+64] = ra1.z; As[0][acol+3][arow+64] = ra1.w;
    Bs[0][acol+0][arow] = rb0.x; Bs[0][acol+1][arow] = rb0.y;
    Bs[0][acol+2][arow] = rb0.z; Bs[0][acol+3][arow] = rb0.w;
    Bs[0][acol+0][arow+64] = rb1.x; Bs[0][acol+1][arow+64] = rb1.y;
    Bs[0][acol+2][arow+64] = rb1.z; Bs[0][acol+3][arow+64] = rb1.w;
    __syncthreads();

    float acc[8][8];
    #pragma unroll
    for (int i = 0; i < 8; i++)
        #pragma unroll
        for (int j = 0; j < 8; j++) acc[i][j] = 0.f;

    int nk = K / TK;
    for (int it = 0; it < nk; it++) {
        int cur = it & 1, nxt = cur ^ 1;
        bool more = (it + 1 < nk);
        if (more) {
            int ko = (it + 1) * TK;
            ra0 = *(const float4*)(Ap0 + ko);
            ra1 = *(const float4*)(Ap1 + ko);
            rb0 = *(const float4*)(Bp0 + ko);
            rb1 = *(const float4*)(Bp1 + ko);
        }
        #pragma unroll
        for (int kk = 0; kk < TK; kk++) {
            float a[8], b[8];
            float4 a0 = *(const float4*)&As[cur][kk][tmb];
            float4 a1 = *(const float4*)&As[cur][kk][tmb + 4];
            float4 b0 = *(const float4*)&Bs[cur][kk][tnb];
            float4 b1 = *(const float4*)&Bs[cur][kk][tnb + 4];
            a[0]=a0.x;a[1]=a0.y;a[2]=a0.z;a[3]=a0.w;a[4]=a1.x;a[5]=a1.y;a[6]=a1.z;a[7]=a1.w;
            b[0]=b0.x;b[1]=b0.y;b[2]=b0.z;b[3]=b0.w;b[4]=b1.x;b[5]=b1.y;b[6]=b1.z;b[7]=b1.w;
            #pragma unroll
            for (int i = 0; i < 8; i++)
                #pragma unroll
                for (int j = 0; j < 8; j++)
                    acc[i][j] = fmaf(a[i], b[j], acc[i][j]);
        }
        if (more) {
            As[nxt][acol+0][arow] = ra0.x; As[nxt][acol+1][arow] = ra0.y;
            As[nxt][acol+2][arow] = ra0.z; As[nxt][acol+3][arow] = ra0.w;
            As[nxt][acol+0][arow+64] = ra1.x; As[nxt][acol+1][arow+64] = ra1.y;
            As[nxt][acol+2][arow+64] = ra1.z; As[nxt][acol+3][arow+64] = ra1.w;
            Bs[nxt][acol+0][arow] = rb0.x; Bs[nxt][acol+1][arow] = rb0.y;
            Bs[nxt][acol+2][arow] = rb0.z; Bs[nxt][acol+3][arow] = rb0.w;
            Bs[nxt][acol+0][arow+64] = rb1.x; Bs[nxt][acol+1][arow+64] = rb1.y;
            Bs[nxt][acol+2][arow+64] = rb1.z; Bs[nxt][acol+3][arow+64] = rb1.w;
        }
        __syncthreads();
    }

    #pragma unroll
    for (int i = 0; i < 8; i++) {
        size_t row = bm + tmb + i;
        #pragma unroll
        for (int j = 0; j < 8; j++) {
            int col = bn + tnb + j;
            float v = acc[i][j];
            if (EPI & EPI_BIAS)     v += bias[col];
            if (EPI & EPI_SOFTPLUS) v = (v > 20.f) ? v : log1pf(__expf(v));
            if (EPI & EPI_RESID)    v += resid[row * N + col];
            C[row * N + col] = v;
        }
    }
}

// ---------------- x_proj: [4096,1024] x [64,1024]^T, 16 rows/CTA --------------
__global__ __launch_bounds__(256)
void xproj_kernel(const float* __restrict__ A, const float* __restrict__ B,
                  float* __restrict__ C) {
    __shared__ float As[16][68];
    __shared__ float Bs[64][68];
    int tid = threadIdx.x;
    int r0 = blockIdx.x * 16;
    int rr = tid >> 4;        // 0..15 (row)
    int ccq = tid & 15;       // 0..15 (col group)
    float acc[4] = {0.f, 0.f, 0.f, 0.f};

    for (int k0 = 0; k0 < 1024; k0 += 64) {
        {
            int row = tid >> 4, seg = tid & 15;
            *(float4*)&As[row][seg * 4] =
                *(const float4*)(A + (size_t)(r0 + row) * 1024 + k0 + seg * 4);
        }
        #pragma unroll
        for (int i = 0; i < 4; i++) {
            int idx = tid + i * 256;
            int row = idx >> 4, seg = idx & 15;
            *(float4*)&Bs[row][seg * 4] =
                *(const float4*)(B + (size_t)row * 1024 + k0 + seg * 4);
        }
        __syncthreads();
        #pragma unroll 4
        for (int kk = 0; kk < 64; kk += 4) {
            float4 a = *(float4*)&As[rr][kk];
            #pragma unroll
            for (int j = 0; j < 4; j++) {
                float4 b = *(float4*)&Bs[ccq + 16 * j][kk];
                acc[j] = fmaf(a.x, b.x, acc[j]);
                acc[j] = fmaf(a.y, b.y, acc[j]);
                acc[j] = fmaf(a.z, b.z, acc[j]);
                acc[j] = fmaf(a.w, b.w, acc[j]);
            }
        }
        __syncthreads();
    }
    #pragma unroll
    for (int j = 0; j < 4; j++)
        C[(size_t)(r0 + rr) * 64 + ccq + 16 * j] = acc[j];
}

// ---------------- causal depthwise conv (k=4) + silu, float4 ------------------
__global__ void conv_silu_kernel(const float* __restrict__ xz,
                                 const float* __restrict__ cw,
                                 const float* __restrict__ cb,
                                 float* __restrict__ xc) {
    int i4 = blockIdx.x * 256 + threadIdx.x;       // over BL*DI/4
    if (i4 >= BL * DI / 4) return;
    int d4 = (i4 & 255) * 4;
    int row = i4 >> 8;
    int l = row & (LQ - 1);

    float4 c0 = *(const float4*)(cw + (d4 + 0) * 4);
    float4 c1 = *(const float4*)(cw + (d4 + 1) * 4);
    float4 c2 = *(const float4*)(cw + (d4 + 2) * 4);
    float4 c3 = *(const float4*)(cw + (d4 + 3) * 4);
    float4 acc = *(const float4*)(cb + d4);

    #pragma unroll
    for (int j = 0; j < 4; j++) {
        if (l - 3 + j >= 0) {
            float4 v = *(const float4*)(xz + (size_t)(row - 3 + j) * 2048 + d4);
            acc.x = fmaf(v.x, (&c0.x)[j], acc.x);
            acc.y = fmaf(v.y, (&c1.x)[j], acc.y);
            acc.z = fmaf(v.z, (&c2.x)[j], acc.z);
            acc.w = fmaf(v.w, (&c3.x)[j], acc.w);
        }
    }
    acc.x *= 1.f / (1.f + __expf(-acc.x));
    acc.y *= 1.f / (1.f + __expf(-acc.y));
    acc.z *= 1.f / (1.f + __expf(-acc.z));
    acc.w *= 1.f / (1.f + __expf(-acc.w));
    *(float4*)(xc + (size_t)row * DI + d4) = acc;
}

// ---------------- chunked scan, pass 1 ---------------------------------------
__global__ __launch_bounds__(256)
void scan1_kernel(const float* __restrict__ delta_sp,
                  const float* __restrict__ xc,
                  const float* __restrict__ dbc,
                  const float* __restrict__ A_log,
                  float* __restrict__ Pout, float* __restrict__ Sout) {
    __shared__ float s_dl[TC][16];
    __shared__ float s_xv[TC][16];
    __shared__ float s_B[TC][16];
    int bx = blockIdx.x;
    int dt = bx & 63;
    int c  = (bx >> 6) & 15;
    int b  = bx >> 10;
    int tid = threadIdx.x;
    int n = tid & 15, dloc = tid >> 4;
    int d = dt * 16 + dloc;
    size_t row0 = (size_t)b * LQ + c * TC;

    #pragma unroll
    for (int i = 0; i < 2; i++) {
        int idx = tid + i * 256;
        int t = idx >> 2, q = idx & 3;
        *(float4*)&s_dl[t][q * 4] = *(const float4*)(delta_sp + (row0 + t) * DI + dt * 16 + q * 4);
        *(float4*)&s_xv[t][q * 4] = *(const float4*)(xc + (row0 + t) * DI + dt * 16 + q * 4);
        *(float4*)&s_B[t][q * 4]  = *(const float4*)(dbc + (row0 + t) * 64 + 32 + q * 4);
    }
    __syncthreads();

    float An = -__expf(A_log[d * DSTATE + n]);
    float h = 0.f, P = 1.f;
    #pragma unroll 4
    for (int t = 0; t < TC; t++) {
        float dl = s_dl[t][dloc];
        float dA = __expf(dl * An);
        h = fmaf(dA, h, dl * s_B[t][n] * s_xv[t][dloc]);
        P *= dA;
    }
    size_t o = (((size_t)b * NCH + c) * DI + (size_t)dt * 16) * DSTATE + tid;
    Pout[o] = P;
    Sout[o] = h;
}

// ---------------- chunked scan: carry -----------------------------------------
__global__ void scan_carry_kernel(const float* __restrict__ P,
                                  const float* __restrict__ S,
                                  float* __restrict__ H) {
    int idx = blockIdx.x * 256 + threadIdx.x;
    int b = idx >> 14;
    int rem = idx & 16383;
    float carry = 0.f;
    #pragma unroll
    for (int c = 0; c < NCH; c++) {
        size_t o = (((size_t)b * NCH + c) << 14) + rem;
        H[o] = carry;
        carry = fmaf(P[o], carry, S[o]);
    }
}

// ---------------- chunked scan, pass 2: fp16 hi/lo out ------------------------
__global__ __launch_bounds__(256)
void scan2_kernel(const float* __restrict__ delta_sp,
                  const float* __restrict__ xc,
                  const float* __restrict__ dbc,
                  const float* __restrict__ xz,
                  const float* __restrict__ A_log,
                  const float* __restrict__ D_param,
                  const float* __restrict__ H,
                  __half* __restrict__ yh,
                  __half* __restrict__ yl) {
    __shared__ float s_dl[TC][16];
    __shared__ float s_xv[TC][16];
    __shared__ float s_B[TC][16];
    __shared__ float s_C[TC][16];
    __shared__ float s_y[TC][16];
    int bx = blockIdx.x;
    int dt = bx & 63;
    int c  = (bx >> 6) & 15;
    int b  = bx >> 10;
    int tid = threadIdx.x;
    int n = tid & 15, dloc = tid >> 4;
    int d = dt * 16 + dloc;
    size_t row0 = (size_t)b * LQ + c * TC;

    #pragma unroll
    for (int i = 0; i < 2; i++) {
        int idx = tid + i * 256;
        int t = idx >> 2, q = idx & 3;
        *(float4*)&s_dl[t][q * 4] = *(const float4*)(delta_sp + (row0 + t) * DI + dt * 16 + q * 4);
        *(float4*)&s_xv[t][q * 4] = *(const float4*)(xc + (row0 + t) * DI + dt * 16 + q * 4);
        *(float4*)&s_B[t][q * 4]  = *(const float4*)(dbc + (row0 + t) * 64 + 32 + q * 4);
        *(float4*)&s_C[t][q * 4]  = *(const float4*)(dbc + (row0 + t) * 64 + 48 + q * 4);
    }
    __syncthreads();

    float An = -__expf(A_log[d * DSTATE + n]);
    float Dp = D_param[d];
    size_t o = (((size_t)b * NCH + c) * DI + (size_t)dt * 16) * DSTATE + tid;
    float h = H[o];

    #pragma unroll 4
    for (int t = 0; t < TC; t++) {
        float dl = s_dl[t][dloc];
        float xv = s_xv[t][dloc];
        float dA = __expf(dl * An);
        h = fmaf(dA, h, dl * s_B[t][n] * xv);
        float p = h * s_C[t][n];
        p += __shfl_xor_sync(0xffffffffu, p, 1);
        p += __shfl_xor_sync(0xffffffffu, p, 2);
        p += __shfl_xor_sync(0xffffffffu, p, 4);
        p += __shfl_xor_sync(0xffffffffu, p, 8);
        if (n == 0) s_y[t][dloc] = p + Dp * xv;
    }
    __syncthreads();

    #pragma unroll
    for (int i = 0; i < 8; i++) {
        int idx = tid + i * 256;
        int t = idx >> 4, dl2 = idx & 15;
        size_t row = row0 + t;
        float zv = xz[row * 2048 + DI + dt * 16 + dl2];
        float sz = zv / (1.f + __expf(-zv));
        float yv = s_y[t][dl2] * sz;
        __half hv = __float2half_rn(yv);
        yh[row * DI + dt * 16 + dl2] = hv;
        yl[row * DI + dt * 16 + dl2] = __float2half_rn(yv - __half2float(hv));
    }
}

// ---------------- KAN basis to fp16 hi/lo (exp identity, vectorized) ----------
// 1 - tanh^2(s) = 4e/(1+e)^2, e = exp(-2|s|)
__global__ void basis_split_kernel(const float* __restrict__ k,
                                   const float* __restrict__ grid,
                                   __half* __restrict__ bh,
                                   __half* __restrict__ bl) {
    int idx = blockIdx.x * 256 + threadIdx.x;      // over BL*DQ
    if (idx >= BL * DQ) return;
    float kv = k[idx];
    int d = idx & 511;
    int row = idx >> 9;
    const float INV = 1.0f / 0.33f;
    __half hs[8], ls[8];
    #pragma unroll
    for (int g = 0; g < 8; g++) {
        float s = fabsf((kv - __ldg(grid + g)) * INV);
        float e = __expf(-2.f * s);
        float op = 1.f + e;
        float v = __fdividef(4.f * e, op * op);
        __half h = __float2half_rn(v);
        hs[g] = h;
        ls[g] = __float2half_rn(v - __half2float(h));
    }
    *(uint4*)(bh + (size_t)row * 4096 + d * 8) = *(uint4*)hs;
    *(uint4*)(bl + (size_t)row * 4096 + d * 8) = *(uint4*)ls;
}

// ---------------- host orchestration ------------------------------------------
extern "C" void kernel_launch(void* const* d_in, const int* in_sizes, int n_in,
                              void* d_out, int out_size) {
    const float* x      = (const float*)d_in[0];
    const float* n1_w   = (const float*)d_in[1];
    const float* n1_b   = (const float*)d_in[2];
    const float* mn_w   = (const float*)d_in[3];
    const float* mn_b   = (const float*)d_in[4];
    const float* in_w   = (const float*)d_in[5];
    const float* in_b   = (const float*)d_in[6];
    const float* conv_w = (const float*)d_in[7];
    const float* conv_b = (const float*)d_in[8];
    const float* xp_w   = (const float*)d_in[9];
    const float* dt_w   = (const float*)d_in[10];
    const float* dt_b   = (const float*)d_in[11];
    const float* A_log  = (const float*)d_in[12];
    const float* D_par  = (const float*)d_in[13];
    const float* out_w  = (const float*)d_in[14];
    const float* out_b  = (const float*)d_in[15];
    const float* n2_w   = (const float*)d_in[16];
    const float* n2_b   = (const float*)d_in[17];
    const float* kn_w   = (const float*)d_in[18];
    const float* kn_b   = (const float*)d_in[19];
    const float* grid   = (const float*)d_in[20];
    const float* spl_w  = (const float*)d_in[21];
    float* out = (float*)d_out;

    float *p_xz, *p_xc, *p_dbc, *p_delta, *p_x2, *p_k, *p_P, *p_S, *p_H;
    __half *p_uh, *p_ul, *p_iwh, *p_yh, *p_yl, *p_owh, *p_bh, *p_bl, *p_swh;
    cudaGetSymbolAddress((void**)&p_xz,    g_xz);
    cudaGetSymbolAddress((void**)&p_xc,    g_xc);
    cudaGetSymbolAddress((void**)&p_dbc,   g_dbc);
    cudaGetSymbolAddress((void**)&p_delta, g_delta);
    cudaGetSymbolAddress((void**)&p_x2,    g_x2);
    cudaGetSymbolAddress((void**)&p_k,     g_k);
    cudaGetSymbolAddress((void**)&p_P,     g_P);
    cudaGetSymbolAddress((void**)&p_S,     g_S);
    cudaGetSymbolAddress((void**)&p_H,     g_H);
    cudaGetSymbolAddress((void**)&p_uh,  g_uh);  cudaGetSymbolAddress((void**)&p_ul,  g_ul);
    cudaGetSymbolAddress((void**)&p_iwh, g_iwh);
    cudaGetSymbolAddress((void**)&p_yh,  g_yh);  cudaGetSymbolAddress((void**)&p_yl,  g_yl);
    cudaGetSymbolAddress((void**)&p_owh, g_owh);
    cudaGetSymbolAddress((void**)&p_bh,  g_bh);  cudaGetSymbolAddress((void**)&p_bl,  g_bl);
    cudaGetSymbolAddress((void**)&p_swh, g_swh);

    const int SM128 = 2 * (2 * MG_A + 128 * MG_STRIDE);  // 61440
    const int SM64  = 2 * (2 * MG_A + 64 * MG_STRIDE);   // 51200
    cudaFuncSetAttribute(mgemm<128, EPI_BIAS>,
                         cudaFuncAttributeMaxDynamicSharedMemorySize, SM128);
    cudaFuncSetAttribute(mgemm<64, EPI_BIAS | EPI_RESID>,
                         cudaFuncAttributeMaxDynamicSharedMemorySize, SM64);
    cudaFuncSetAttribute(mgemm<64, EPI_RESID>,
                         cudaFuncAttributeMaxDynamicSharedMemorySize, SM64);

    // weight rounding to fp16 (hi only)
    split_kernel<<<(2048 * DQ / 4 + 255) / 256, 256>>>(in_w,  p_iwh, nullptr, 2048 * DQ / 4);
    split_kernel<<<(DQ * DI / 4 + 255) / 256, 256>>>(out_w, p_owh, nullptr, DQ * DI / 4);
    split_kernel<<<(DQ * 4096 / 4 + 255) / 256, 256>>>(spl_w, p_swh, nullptr, DQ * 4096 / 4);

    // 1. u = LN(LN(x)) -> fp16 hi/lo
    ln2_kernel<<<BL / 8, 256>>>(x, n1_w, n1_b, mn_w, mn_b, nullptr, p_uh, p_ul);

    // 2. xz = u @ in_w^T + in_b   [4096 x 2048, K=512]
    mgemm<128, EPI_BIAS><<<dim3(2048 / 128, BL / 128), 256, SM128>>>(
        p_uh, p_ul, p_iwh, in_b, nullptr, p_xz, 2048, DQ);

    // 3. conv + silu
    conv_silu_kernel<<<(BL * DI / 4) / 256, 256>>>(p_xz, conv_w, conv_b, p_xc);

    // 4. dbc = xc @ xp_w^T  [4096 x 64, K=1024]
    xproj_kernel<<<BL / 16, 256>>>(p_xc, xp_w, p_dbc);

    // 5. delta = softplus(dt_proj)  [4096 x 1024, K=32]
    sgemm128<EPI_BIAS | EPI_SOFTPLUS><<<dim3(DI / 128, BL / 128), 256>>>(
        p_dbc, dt_w, dt_b, nullptr, p_delta, DI, 32, 64, 32);

    // 6. chunked parallel scan -> y hi/lo
    scan1_kernel<<<BQ * NCH * 64, 256>>>(p_delta, p_xc, p_dbc, A_log, p_P, p_S);
    scan_carry_kernel<<<(BQ * DI * DSTATE) / 256, 256>>>(p_P, p_S, p_H);
    scan2_kernel<<<BQ * NCH * 64, 256>>>(p_delta, p_xc, p_dbc, p_xz, A_log, D_par,
                                         p_H, p_yh, p_yl);

    // 7. x2 = x + y @ out_w^T + out_b  [4096 x 512, K=1024]  (NT=64, 256 CTAs)
    mgemm<64, EPI_BIAS | EPI_RESID><<<dim3(DQ / 64, BL / 128), 256, SM64>>>(
        p_yh, p_yl, p_owh, out_b, x, p_x2, DQ, DI);

    // 8. k = LN(LN(x2)) -> fp32
    ln2_kernel<<<BL / 8, 256>>>(p_x2, n2_w, n2_b, kn_w, kn_b, p_k, nullptr, nullptr);

    // 9. basis -> fp16 hi/lo
    basis_split_kernel<<<(BL * DQ + 255) / 256, 256>>>(p_k, grid, p_bh, p_bl);

    // 10. out = x2 + basis @ spl_w^T  [4096 x 512, K=4096]  (NT=64, 256 CTAs)
    mgemm<64, EPI_RESID><<<dim3(DQ / 64, BL / 128), 256, SM64>>>(
        p_bh, p_bl, p_swh, nullptr, p_x2, out, DQ, 4096);

    (void)in_sizes; (void)n_in; (void)out_size;
}

// round 8
// speedup vs baseline: 6.4863x; 1.3205x over previous
#include <cuda_runtime.h>
#include <cuda_fp16.h>
#include <math.h>
#include <stdint.h>

// Problem constants
#define BQ 2
#define LQ 2048
#define DQ 512
#define DI 1024
#define BL (BQ*LQ)          // 4096 rows
#define DSTATE 16
#define NG 8
#define TC 128              // scan chunk length
#define NCH (LQ/TC)         // 16 chunks

// ---------------- device scratch ---------------------------------------------
__device__ float g_xz[(size_t)BL*2048];      // in_proj output (xm | z), fp32
__device__ float g_xc[(size_t)BL*DI];        // conv+silu
__device__ float g_dbc[BL*64];               // x_proj output
__device__ float g_delta[(size_t)BL*DI];     // softplus(dt_proj)
__device__ float g_x2[BL*DQ];                // x + mix
__device__ float g_k[BL*DQ];                 // LN(LN(x2))

__device__ float g_P[(size_t)BQ*NCH*DI*DSTATE];  // chunk products
__device__ float g_S[(size_t)BQ*NCH*DI*DSTATE];  // chunk local end states
__device__ float g_H[(size_t)BQ*NCH*DI*DSTATE];  // chunk initial states

__device__ __half g_uh[(size_t)BL*DQ];           // ln2(x) fp16
__device__ __half g_iwh[2048*DQ];                // in_w fp16
__device__ __half g_yh[(size_t)BL*DI];           // scan out fp16
__device__ __half g_owh[DQ*DI];                  // out_w fp16
__device__ __half g_bh[(size_t)BL*4096];         // KAN basis fp16
__device__ __half g_swh[DQ*4096];                // spl_w fp16

// ---------------- PTX helpers (sm_80-class, valid on sm_100) ------------------
#define CP_ASYNC16(s, g) \
    asm volatile("cp.async.cg.shared.global [%0], [%1], 16;" :: "r"(s), "l"(g))
#define CP_COMMIT() asm volatile("cp.async.commit_group;" ::: "memory")
#define CP_WAIT(n)  asm volatile("cp.async.wait_group %0;" :: "n"(n) : "memory")

__device__ __forceinline__ void ldsm4(uint32_t* r, uint32_t addr) {
    asm volatile("ldmatrix.sync.aligned.m8n8.x4.shared.b16 {%0,%1,%2,%3}, [%4];"
                 : "=r"(r[0]), "=r"(r[1]), "=r"(r[2]), "=r"(r[3]) : "r"(addr));
}
__device__ __forceinline__ void mma_f16(float* c, const uint32_t* a, const uint32_t* b) {
    asm volatile("mma.sync.aligned.m16n8k16.row.col.f32.f16.f16.f32 "
                 "{%0,%1,%2,%3}, {%4,%5,%6,%7}, {%8,%9}, {%0,%1,%2,%3};"
                 : "+f"(c[0]), "+f"(c[1]), "+f"(c[2]), "+f"(c[3])
                 : "r"(a[0]), "r"(a[1]), "r"(a[2]), "r"(a[3]),
                   "r"(b[0]), "r"(b[1]));
}

// ---------------- epilogue flags ---------------------------------------------
#define EPI_BIAS 1
#define EPI_RESID 2
#define EPI_SOFTPLUS 4

// ---------------- fp16 NT GEMM via mma.sync -----------------------------------
// C[M,N] = A[M,K] * B[N,K]^T, fp32 accum. Block tile 128 x NT, K chunks of 32.
#define MG_STRIDE 80
#define MG_A 10240                 // 128 * 80

template<int NT, int EPI>
__global__ __launch_bounds__(256, 2)
void mgemm(const __half* __restrict__ Ah, const __half* __restrict__ Bh,
           const float* __restrict__ bias, const float* __restrict__ resid,
           float* __restrict__ C, int N, int K) {
    constexpr int MT = (NT == 128) ? 4 : 2;    // m-frags (16 rows) per warp
    constexpr int S_B = NT * MG_STRIDE;
    constexpr int STAGE = MG_A + S_B;

    extern __shared__ __align__(128) char smem[];
    uint32_t sb = (uint32_t)__cvta_generic_to_shared(smem);
    int tid = threadIdx.x;
    int lane = tid & 31, warp = tid >> 5;
    int bm = blockIdx.y * 128, bn = blockIdx.x * NT;
    int wm = (NT == 128) ? (warp >> 2) * 64 : (warp >> 1) * 32;
    int wn = (NT == 128) ? (warp & 3) * 32 : (warp & 1) * 32;

    int nc = K / 32;

    auto issue = [&](int c) {
        int k0 = c * 32;
        uint32_t bufb = sb + (c & 1) * STAGE;
        #pragma unroll
        for (int i = 0; i < 2; i++) {
            int idx = tid + i * 256;
            int row = idx >> 2, seg = idx & 3;
            const __half* g = Ah + (size_t)(bm + row) * K + k0 + seg * 8;
            CP_ASYNC16(bufb + row * MG_STRIDE + seg * 16, g);
        }
        #pragma unroll
        for (int i = 0; i < NT / 64; i++) {
            int idx = tid + i * 256;
            int row = idx >> 2, seg = idx & 3;
            const __half* g = Bh + (size_t)(bn + row) * K + k0 + seg * 8;
            CP_ASYNC16(bufb + MG_A + row * MG_STRIDE + seg * 16, g);
        }
        CP_COMMIT();
    };

    float acc[MT][4][4];
    #pragma unroll
    for (int mt = 0; mt < MT; mt++)
        #pragma unroll
        for (int nt = 0; nt < 4; nt++)
            #pragma unroll
            for (int q = 0; q < 4; q++) acc[mt][nt][q] = 0.f;

    issue(0);
    issue(1);

    for (int c = 0; c < nc; c++) {
        if (c + 1 < nc) { CP_WAIT(1); } else { CP_WAIT(0); }
        __syncthreads();
        uint32_t base = sb + (c & 1) * STAGE;
        uint32_t rsel = (lane & 15) * MG_STRIDE;
        #pragma unroll
        for (int kst = 0; kst < 2; kst++) {
            uint32_t kb = kst * 32 + (lane >> 4) * 16;
            uint32_t bf[4][2], af[MT][4];
            #pragma unroll
            for (int p = 0; p < 2; p++) {
                uint32_t r[4];
                ldsm4(r, base + MG_A + (wn + p * 16) * MG_STRIDE + rsel + kb);
                bf[p*2][0] = r[0]; bf[p*2][1] = r[2];
                bf[p*2+1][0] = r[1]; bf[p*2+1][1] = r[3];
            }
            #pragma unroll
            for (int mt = 0; mt < MT; mt++)
                ldsm4(af[mt], base + (wm + mt * 16) * MG_STRIDE + rsel + kb);
            #pragma unroll
            for (int mt = 0; mt < MT; mt++)
                #pragma unroll
                for (int nt = 0; nt < 4; nt++)
                    mma_f16(acc[mt][nt], af[mt], bf[nt]);
        }
        __syncthreads();
        if (c + 2 < nc) issue(c + 2);
    }

    // epilogue
    int g = lane >> 2, tig = lane & 3;
    #pragma unroll
    for (int mt = 0; mt < MT; mt++) {
        size_t r0 = (size_t)bm + wm + mt * 16 + g;
        size_t r1 = r0 + 8;
        #pragma unroll
        for (int nt = 0; nt < 4; nt++) {
            int col = bn + wn + nt * 8 + tig * 2;
            float2 v0 = make_float2(acc[mt][nt][0], acc[mt][nt][1]);
            float2 v1 = make_float2(acc[mt][nt][2], acc[mt][nt][3]);
            if (EPI & EPI_BIAS) {
                float b0 = bias[col], b1 = bias[col + 1];
                v0.x += b0; v0.y += b1; v1.x += b0; v1.y += b1;
            }
            if (EPI & EPI_RESID) {
                const float* rp0 = resid + r0 * N + col;
                const float* rp1 = resid + r1 * N + col;
                v0.x += rp0[0]; v0.y += rp0[1];
                v1.x += rp1[0]; v1.y += rp1[1];
            }
            *(float2*)(C + r0 * N + col) = v0;
            *(float2*)(C + r1 * N + col) = v1;
        }
    }
}

// ---------------- double layernorm, warp-per-row ------------------------------
__global__ __launch_bounds__(256)
void ln2_kernel(const float* __restrict__ x,
                const float* __restrict__ w1, const float* __restrict__ b1,
                const float* __restrict__ w2, const float* __restrict__ b2,
                float* __restrict__ o32, __half* __restrict__ oh) {
    int lane = threadIdx.x & 31;
    int row = blockIdx.x * 8 + (threadIdx.x >> 5);
    const float4* xr = (const float4*)(x + (size_t)row * DQ);
    float4 v[4];
    float s = 0.f;
    #pragma unroll
    for (int i = 0; i < 4; i++) {
        v[i] = xr[lane + i * 32];
        s += v[i].x + v[i].y + v[i].z + v[i].w;
    }
    #pragma unroll
    for (int o = 16; o > 0; o >>= 1) s += __shfl_xor_sync(0xffffffffu, s, o);
    float mu = s * (1.f / DQ);
    float q = 0.f;
    #pragma unroll
    for (int i = 0; i < 4; i++) {
        float a = v[i].x - mu, b = v[i].y - mu, c = v[i].z - mu, d = v[i].w - mu;
        q += a * a + b * b + c * c + d * d;
    }
    #pragma unroll
    for (int o = 16; o > 0; o >>= 1) q += __shfl_xor_sync(0xffffffffu, q, o);
    float rs = rsqrtf(q * (1.f / DQ) + 1e-5f);
    #pragma unroll
    for (int i = 0; i < 4; i++) {
        float4 w = ((const float4*)w1)[lane + i * 32];
        float4 b = ((const float4*)b1)[lane + i * 32];
        v[i].x = (v[i].x - mu) * rs * w.x + b.x;
        v[i].y = (v[i].y - mu) * rs * w.y + b.y;
        v[i].z = (v[i].z - mu) * rs * w.z + b.z;
        v[i].w = (v[i].w - mu) * rs * w.w + b.w;
    }
    s = 0.f;
    #pragma unroll
    for (int i = 0; i < 4; i++) s += v[i].x + v[i].y + v[i].z + v[i].w;
    #pragma unroll
    for (int o = 16; o > 0; o >>= 1) s += __shfl_xor_sync(0xffffffffu, s, o);
    mu = s * (1.f / DQ);
    q = 0.f;
    #pragma unroll
    for (int i = 0; i < 4; i++) {
        float a = v[i].x - mu, b = v[i].y - mu, c = v[i].z - mu, d = v[i].w - mu;
        q += a * a + b * b + c * c + d * d;
    }
    #pragma unroll
    for (int o = 16; o > 0; o >>= 1) q += __shfl_xor_sync(0xffffffffu, q, o);
    rs = rsqrtf(q * (1.f / DQ) + 1e-5f);
    #pragma unroll
    for (int i = 0; i < 4; i++) {
        float4 w = ((const float4*)w2)[lane + i * 32];
        float4 b = ((const float4*)b2)[lane + i * 32];
        v[i].x = (v[i].x - mu) * rs * w.x + b.x;
        v[i].y = (v[i].y - mu) * rs * w.y + b.y;
        v[i].z = (v[i].z - mu) * rs * w.z + b.z;
        v[i].w = (v[i].w - mu) * rs * w.w + b.w;
    }
    if (o32) {
        float4* orow = (float4*)(o32 + (size_t)row * DQ);
        #pragma unroll
        for (int i = 0; i < 4; i++) orow[lane + i * 32] = v[i];
    }
    if (oh) {
        __half2* hp = (__half2*)(oh + (size_t)row * DQ);
        #pragma unroll
        for (int i = 0; i < 4; i++) {
            int j = (lane + i * 32) * 2;
            hp[j + 0] = __halves2half2(__float2half_rn(v[i].x), __float2half_rn(v[i].y));
            hp[j + 1] = __halves2half2(__float2half_rn(v[i].z), __float2half_rn(v[i].w));
        }
    }
}

// ---------------- fp32 -> fp16 convert ----------------------------------------
__global__ void split_kernel(const float* __restrict__ s,
                             __half* __restrict__ h, int n4) {
    int i = blockIdx.x * 256 + threadIdx.x;
    if (i >= n4) return;
    float4 v = ((const float4*)s)[i];
    __half2* hp = (__half2*)h;
    hp[2 * i + 0] = __halves2half2(__float2half_rn(v.x), __float2half_rn(v.y));
    hp[2 * i + 1] = __halves2half2(__float2half_rn(v.z), __float2half_rn(v.w));
}

// ---------------- fp32 SGEMM 128x128 (dt_proj, K=32) --------------------------
template<int EPI>
__global__ __launch_bounds__(256, 2)
void sgemm128(const float* __restrict__ A, const float* __restrict__ B,
              const float* __restrict__ bias, const float* __restrict__ resid,
              float* __restrict__ C, int N, int K, int lda, int ldb) {
    const int TK = 16;
    __shared__ __align__(16) float As[2][TK][128 + 4];
    __shared__ __align__(16) float Bs[2][TK][128 + 4];

    int tid = threadIdx.x;
    int bm = blockIdx.y * 128;
    int bn = blockIdx.x * 128;
    int arow = tid >> 2;
    int acol = (tid & 3) << 2;
    int tmb = (tid >> 4) << 3;
    int tnb = (tid & 15) << 3;

    const float* Ap0 = A + (size_t)(bm + arow) * lda + acol;
    const float* Ap1 = A + (size_t)(bm + arow + 64) * lda + acol;
    const float* Bp0 = B + (size_t)(bn + arow) * ldb + acol;
    const float* Bp1 = B + (size_t)(bn + arow + 64) * ldb + acol;

    float4 ra0 = *(const float4*)(Ap0);
    float4 ra1 = *(const float4*)(Ap1);
    float4 rb0 = *(const float4*)(Bp0);
    float4 rb1 = *(const float4*)(Bp1);
    As[0][acol+0][arow] = ra0.x; As[0][acol+1][arow] = ra0.y;
    As[0][acol+2][arow] = ra0.z; As[0][acol+3][arow] = ra0.w;
    As[0][acol+0][arow+64] = ra1.x; As[0][acol+1][arow+64] = ra1.y;
    As[0][acol+2][arow+64] = ra1.z; As[0][acol+3][arow+64] = ra1.w;
    Bs[0][acol+0][arow] = rb0.x; Bs[0][acol+1][arow] = rb0.y;
    Bs[0][acol+2][arow] = rb0.z; Bs[0][acol+3][arow] = rb0.w;
    Bs[0][acol+0][arow+64] = rb1.x; Bs[0][acol+1][arow+64] = rb1.y;
    Bs[0][acol+2][arow+64] = rb1.z; Bs[0][acol+3][arow+64] = rb1.w;
    __syncthreads();

    float acc[8][8];
    #pragma unroll
    for (int i = 0; i < 8; i++)
        #pragma unroll
        for (int j = 0; j < 8; j++) acc[i][j] = 0.f;

    int nk = K / TK;
    for (int it = 0; it < nk; it++) {
        int cur = it & 1, nxt = cur ^ 1;
        bool more = (it + 1 < nk);
        if (more) {
            int ko = (it + 1) * TK;
            ra0 = *(const float4*)(Ap0 + ko);
            ra1 = *(const float4*)(Ap1 + ko);
            rb0 = *(const float4*)(Bp0 + ko);
            rb1 = *(const float4*)(Bp1 + ko);
        }
        #pragma unroll
        for (int kk = 0; kk < TK; kk++) {
            float a[8], b[8];
            float4 a0 = *(const float4*)&As[cur][kk][tmb];
            float4 a1 = *(const float4*)&As[cur][kk][tmb + 4];
            float4 b0 = *(const float4*)&Bs[cur][kk][tnb];
            float4 b1 = *(const float4*)&Bs[cur][kk][tnb + 4];
            a[0]=a0.x;a[1]=a0.y;a[2]=a0.z;a[3]=a0.w;a[4]=a1.x;a[5]=a1.y;a[6]=a1.z;a[7]=a1.w;
            b[0]=b0.x;b[1]=b0.y;b[2]=b0.z;b[3]=b0.w;b[4]=b1.x;b[5]=b1.y;b[6]=b1.z;b[7]=b1.w;
            #pragma unroll
            for (int i = 0; i < 8; i++)
                #pragma unroll
                for (int j = 0; j < 8; j++)
                    acc[i][j] = fmaf(a[i], b[j], acc[i][j]);
        }
        if (more) {
            As[nxt][acol+0][arow] = ra0.x; As[nxt][acol+1][arow] = ra0.y;
            As[nxt][acol+2][arow] = ra0.z; As[nxt][acol+3][arow] = ra0.w;
            As[nxt][acol+0][arow+64] = ra1.x; As[nxt][acol+1][arow+64] = ra1.y;
            As[nxt][acol+2][arow+64] = ra1.z; As[nxt][acol+3][arow+64] = ra1.w;
            Bs[nxt][acol+0][arow] = rb0.x; Bs[nxt][acol+1][arow] = rb0.y;
            Bs[nxt][acol+2][arow] = rb0.z; Bs[nxt][acol+3][arow] = rb0.w;
            Bs[nxt][acol+0][arow+64] = rb1.x; Bs[nxt][acol+1][arow+64] = rb1.y;
            Bs[nxt][acol+2][arow+64] = rb1.z; Bs[nxt][acol+3][arow+64] = rb1.w;
        }
        __syncthreads();
    }

    #pragma unroll
    for (int i = 0; i < 8; i++) {
        size_t row = bm + tmb + i;
        #pragma unroll
        for (int j = 0; j < 8; j++) {
            int col = bn + tnb + j;
            float v = acc[i][j];
            if (EPI & EPI_BIAS)     v += bias[col];
            if (EPI & EPI_SOFTPLUS) v = (v > 20.f) ? v : log1pf(__expf(v));
            if (EPI & EPI_RESID)    v += resid[row * N + col];
            C[row * N + col] = v;
        }
    }
}

// ---------------- x_proj: [4096,1024] x [64,1024]^T, 16 rows/CTA --------------
__global__ __launch_bounds__(256)
void xproj_kernel(const float* __restrict__ A, const float* __restrict__ B,
                  float* __restrict__ C) {
    __shared__ float As[16][68];
    __shared__ float Bs[64][68];
    int tid = threadIdx.x;
    int r0 = blockIdx.x * 16;
    int rr = tid >> 4;
    int ccq = tid & 15;
    float acc[4] = {0.f, 0.f, 0.f, 0.f};

    for (int k0 = 0; k0 < 1024; k0 += 64) {
        {
            int row = tid >> 4, seg = tid & 15;
            *(float4*)&As[row][seg * 4] =
                *(const float4*)(A + (size_t)(r0 + row) * 1024 + k0 + seg * 4);
        }
        #pragma unroll
        for (int i = 0; i < 4; i++) {
            int idx = tid + i * 256;
            int row = idx >> 4, seg = idx & 15;
            *(float4*)&Bs[row][seg * 4] =
                *(const float4*)(B + (size_t)row * 1024 + k0 + seg * 4);
        }
        __syncthreads();
        #pragma unroll 4
        for (int kk = 0; kk < 64; kk += 4) {
            float4 a = *(float4*)&As[rr][kk];
            #pragma unroll
            for (int j = 0; j < 4; j++) {
                float4 b = *(float4*)&Bs[ccq + 16 * j][kk];
                acc[j] = fmaf(a.x, b.x, acc[j]);
                acc[j] = fmaf(a.y, b.y, acc[j]);
                acc[j] = fmaf(a.z, b.z, acc[j]);
                acc[j] = fmaf(a.w, b.w, acc[j]);
            }
        }
        __syncthreads();
    }
    #pragma unroll
    for (int j = 0; j < 4; j++)
        C[(size_t)(r0 + rr) * 64 + ccq + 16 * j] = acc[j];
}

// ---------------- causal depthwise conv (k=4) + silu, float4 ------------------
__global__ void conv_silu_kernel(const float* __restrict__ xz,
                                 const float* __restrict__ cw,
                                 const float* __restrict__ cb,
                                 float* __restrict__ xc) {
    int i4 = blockIdx.x * 256 + threadIdx.x;
    if (i4 >= BL * DI / 4) return;
    int d4 = (i4 & 255) * 4;
    int row = i4 >> 8;
    int l = row & (LQ - 1);

    float4 c0 = *(const float4*)(cw + (d4 + 0) * 4);
    float4 c1 = *(const float4*)(cw + (d4 + 1) * 4);
    float4 c2 = *(const float4*)(cw + (d4 + 2) * 4);
    float4 c3 = *(const float4*)(cw + (d4 + 3) * 4);
    float4 acc = *(const float4*)(cb + d4);

    #pragma unroll
    for (int j = 0; j < 4; j++) {
        if (l - 3 + j >= 0) {
            float4 v = *(const float4*)(xz + (size_t)(row - 3 + j) * 2048 + d4);
            acc.x = fmaf(v.x, (&c0.x)[j], acc.x);
            acc.y = fmaf(v.y, (&c1.x)[j], acc.y);
            acc.z = fmaf(v.z, (&c2.x)[j], acc.z);
            acc.w = fmaf(v.w, (&c3.x)[j], acc.w);
        }
    }
    acc.x *= 1.f / (1.f + __expf(-acc.x));
    acc.y *= 1.f / (1.f + __expf(-acc.y));
    acc.z *= 1.f / (1.f + __expf(-acc.z));
    acc.w *= 1.f / (1.f + __expf(-acc.w));
    *(float4*)(xc + (size_t)row * DI + d4) = acc;
}

// ---------------- chunked scan, pass 1 ---------------------------------------
__global__ __launch_bounds__(256)
void scan1_kernel(const float* __restrict__ delta_sp,
                  const float* __restrict__ xc,
                  const float* __restrict__ dbc,
                  const float* __restrict__ A_log,
                  float* __restrict__ Pout, float* __restrict__ Sout) {
    __shared__ float s_dl[TC][16];
    __shared__ float s_xv[TC][16];
    __shared__ float s_B[TC][16];
    int bx = blockIdx.x;
    int dt = bx & 63;
    int c  = (bx >> 6) & 15;
    int b  = bx >> 10;
    int tid = threadIdx.x;
    int n = tid & 15, dloc = tid >> 4;
    int d = dt * 16 + dloc;
    size_t row0 = (size_t)b * LQ + c * TC;

    #pragma unroll
    for (int i = 0; i < 2; i++) {
        int idx = tid + i * 256;
        int t = idx >> 2, q = idx & 3;
        *(float4*)&s_dl[t][q * 4] = *(const float4*)(delta_sp + (row0 + t) * DI + dt * 16 + q * 4);
        *(float4*)&s_xv[t][q * 4] = *(const float4*)(xc + (row0 + t) * DI + dt * 16 + q * 4);
        *(float4*)&s_B[t][q * 4]  = *(const float4*)(dbc + (row0 + t) * 64 + 32 + q * 4);
    }
    __syncthreads();

    float An = -__expf(A_log[d * DSTATE + n]);
    float h = 0.f, P = 1.f;
    #pragma unroll 4
    for (int t = 0; t < TC; t++) {
        float dl = s_dl[t][dloc];
        float dA = __expf(dl * An);
        h = fmaf(dA, h, dl * s_B[t][n] * s_xv[t][dloc]);
        P *= dA;
    }
    size_t o = (((size_t)b * NCH + c) * DI + (size_t)dt * 16) * DSTATE + tid;
    Pout[o] = P;
    Sout[o] = h;
}

// ---------------- chunked scan: carry -----------------------------------------
__global__ void scan_carry_kernel(const float* __restrict__ P,
                                  const float* __restrict__ S,
                                  float* __restrict__ H) {
    int idx = blockIdx.x * 256 + threadIdx.x;
    int b = idx >> 14;
    int rem = idx & 16383;
    float carry = 0.f;
    #pragma unroll
    for (int c = 0; c < NCH; c++) {
        size_t o = (((size_t)b * NCH + c) << 14) + rem;
        H[o] = carry;
        carry = fmaf(P[o], carry, S[o]);
    }
}

// ---------------- chunked scan, pass 2: fp16 out -------------------------------
__global__ __launch_bounds__(256)
void scan2_kernel(const float* __restrict__ delta_sp,
                  const float* __restrict__ xc,
                  const float* __restrict__ dbc,
                  const float* __restrict__ xz,
                  const float* __restrict__ A_log,
                  const float* __restrict__ D_param,
                  const float* __restrict__ H,
                  __half* __restrict__ yh) {
    __shared__ float s_dl[TC][16];
    __shared__ float s_xv[TC][16];
    __shared__ float s_B[TC][16];
    __shared__ float s_C[TC][16];
    __shared__ float s_y[TC][16];
    int bx = blockIdx.x;
    int dt = bx & 63;
    int c  = (bx >> 6) & 15;
    int b  = bx >> 10;
    int tid = threadIdx.x;
    int n = tid & 15, dloc = tid >> 4;
    int d = dt * 16 + dloc;
    size_t row0 = (size_t)b * LQ + c * TC;

    #pragma unroll
    for (int i = 0; i < 2; i++) {
        int idx = tid + i * 256;
        int t = idx >> 2, q = idx & 3;
        *(float4*)&s_dl[t][q * 4] = *(const float4*)(delta_sp + (row0 + t) * DI + dt * 16 + q * 4);
        *(float4*)&s_xv[t][q * 4] = *(const float4*)(xc + (row0 + t) * DI + dt * 16 + q * 4);
        *(float4*)&s_B[t][q * 4]  = *(const float4*)(dbc + (row0 + t) * 64 + 32 + q * 4);
        *(float4*)&s_C[t][q * 4]  = *(const float4*)(dbc + (row0 + t) * 64 + 48 + q * 4);
    }
    __syncthreads();

    float An = -__expf(A_log[d * DSTATE + n]);
    float Dp = D_param[d];
    size_t o = (((size_t)b * NCH + c) * DI + (size_t)dt * 16) * DSTATE + tid;
    float h = H[o];

    #pragma unroll 4
    for (int t = 0; t < TC; t++) {
        float dl = s_dl[t][dloc];
        float xv = s_xv[t][dloc];
        float dA = __expf(dl * An);
        h = fmaf(dA, h, dl * s_B[t][n] * xv);
        float p = h * s_C[t][n];
        p += __shfl_xor_sync(0xffffffffu, p, 1);
        p += __shfl_xor_sync(0xffffffffu, p, 2);
        p += __shfl_xor_sync(0xffffffffu, p, 4);
        p += __shfl_xor_sync(0xffffffffu, p, 8);
        if (n == 0) s_y[t][dloc] = p + Dp * xv;
    }
    __syncthreads();

    #pragma unroll
    for (int i = 0; i < 8; i++) {
        int idx = tid + i * 256;
        int t = idx >> 4, dl2 = idx & 15;
        size_t row = row0 + t;
        float zv = xz[row * 2048 + DI + dt * 16 + dl2];
        float sz = zv / (1.f + __expf(-zv));
        yh[row * DI + dt * 16 + dl2] = __float2half_rn(s_y[t][dl2] * sz);
    }
}

// ---------------- KAN basis to fp16 (exp identity, vectorized) -----------------
__global__ void basis_kernel(const float* __restrict__ k,
                             const float* __restrict__ grid,
                             __half* __restrict__ bh) {
    int idx = blockIdx.x * 256 + threadIdx.x;
    if (idx >= BL * DQ) return;
    float kv = k[idx];
    int d = idx & 511;
    int row = idx >> 9;
    const float INV = 1.0f / 0.33f;
    __half hs[8];
    #pragma unroll
    for (int g = 0; g < 8; g++) {
        float s = fabsf((kv - __ldg(grid + g)) * INV);
        float e = __expf(-2.f * s);
        float op = 1.f + e;
        hs[g] = __float2half_rn(__fdividef(4.f * e, op * op));
    }
    *(uint4*)(bh + (size_t)row * 4096 + d * 8) = *(uint4*)hs;
}

// ---------------- host orchestration ------------------------------------------
extern "C" void kernel_launch(void* const* d_in, const int* in_sizes, int n_in,
                              void* d_out, int out_size) {
    const float* x      = (const float*)d_in[0];
    const float* n1_w   = (const float*)d_in[1];
    const float* n1_b   = (const float*)d_in[2];
    const float* mn_w   = (const float*)d_in[3];
    const float* mn_b   = (const float*)d_in[4];
    const float* in_w   = (const float*)d_in[5];
    const float* in_b   = (const float*)d_in[6];
    const float* conv_w = (const float*)d_in[7];
    const float* conv_b = (const float*)d_in[8];
    const float* xp_w   = (const float*)d_in[9];
    const float* dt_w   = (const float*)d_in[10];
    const float* dt_b   = (const float*)d_in[11];
    const float* A_log  = (const float*)d_in[12];
    const float* D_par  = (const float*)d_in[13];
    const float* out_w  = (const float*)d_in[14];
    const float* out_b  = (const float*)d_in[15];
    const float* n2_w   = (const float*)d_in[16];
    const float* n2_b   = (const float*)d_in[17];
    const float* kn_w   = (const float*)d_in[18];
    const float* kn_b   = (const float*)d_in[19];
    const float* grid   = (const float*)d_in[20];
    const float* spl_w  = (const float*)d_in[21];
    float* out = (float*)d_out;

    float *p_xz, *p_xc, *p_dbc, *p_delta, *p_x2, *p_k, *p_P, *p_S, *p_H;
    __half *p_uh, *p_iwh, *p_yh, *p_owh, *p_bh, *p_swh;
    cudaGetSymbolAddress((void**)&p_xz,    g_xz);
    cudaGetSymbolAddress((void**)&p_xc,    g_xc);
    cudaGetSymbolAddress((void**)&p_dbc,   g_dbc);
    cudaGetSymbolAddress((void**)&p_delta, g_delta);
    cudaGetSymbolAddress((void**)&p_x2,    g_x2);
    cudaGetSymbolAddress((void**)&p_k,     g_k);
    cudaGetSymbolAddress((void**)&p_P,     g_P);
    cudaGetSymbolAddress((void**)&p_S,     g_S);
    cudaGetSymbolAddress((void**)&p_H,     g_H);
    cudaGetSymbolAddress((void**)&p_uh,  g_uh);
    cudaGetSymbolAddress((void**)&p_iwh, g_iwh);
    cudaGetSymbolAddress((void**)&p_yh,  g_yh);
    cudaGetSymbolAddress((void**)&p_owh, g_owh);
    cudaGetSymbolAddress((void**)&p_bh,  g_bh);
    cudaGetSymbolAddress((void**)&p_swh, g_swh);

    const int SM128 = 2 * (MG_A + 128 * MG_STRIDE);  // 40960
    const int SM64  = 2 * (MG_A + 64 * MG_STRIDE);   // 30720
    cudaFuncSetAttribute(mgemm<128, EPI_BIAS>,
                         cudaFuncAttributeMaxDynamicSharedMemorySize, SM128);
    cudaFuncSetAttribute(mgemm<64, EPI_BIAS | EPI_RESID>,
                         cudaFuncAttributeMaxDynamicSharedMemorySize, SM64);
    cudaFuncSetAttribute(mgemm<64, EPI_RESID>,
                         cudaFuncAttributeMaxDynamicSharedMemorySize, SM64);

    // weight conversion to fp16
    split_kernel<<<(2048 * DQ / 4 + 255) / 256, 256>>>(in_w,  p_iwh, 2048 * DQ / 4);
    split_kernel<<<(DQ * DI / 4 + 255) / 256, 256>>>(out_w, p_owh, DQ * DI / 4);
    split_kernel<<<(DQ * 4096 / 4 + 255) / 256, 256>>>(spl_w, p_swh, DQ * 4096 / 4);

    // 1. u = LN(LN(x)) -> fp16
    ln2_kernel<<<BL / 8, 256>>>(x, n1_w, n1_b, mn_w, mn_b, nullptr, p_uh);

    // 2. xz = u @ in_w^T + in_b   [4096 x 2048, K=512]
    mgemm<128, EPI_BIAS><<<dim3(2048 / 128, BL / 128), 256, SM128>>>(
        p_uh, p_iwh, in_b, nullptr, p_xz, 2048, DQ);

    // 3. conv + silu
    conv_silu_kernel<<<(BL * DI / 4) / 256, 256>>>(p_xz, conv_w, conv_b, p_xc);

    // 4. dbc = xc @ xp_w^T  [4096 x 64, K=1024]
    xproj_kernel<<<BL / 16, 256>>>(p_xc, xp_w, p_dbc);

    // 5. delta = softplus(dt_proj)  [4096 x 1024, K=32]
    sgemm128<EPI_BIAS | EPI_SOFTPLUS><<<dim3(DI / 128, BL / 128), 256>>>(
        p_dbc, dt_w, dt_b, nullptr, p_delta, DI, 32, 64, 32);

    // 6. chunked parallel scan -> y fp16
    scan1_kernel<<<BQ * NCH * 64, 256>>>(p_delta, p_xc, p_dbc, A_log, p_P, p_S);
    scan_carry_kernel<<<(BQ * DI * DSTATE) / 256, 256>>>(p_P, p_S, p_H);
    scan2_kernel<<<BQ * NCH * 64, 256>>>(p_delta, p_xc, p_dbc, p_xz, A_log, D_par,
                                         p_H, p_yh);

    // 7. x2 = x + y @ out_w^T + out_b  [4096 x 512, K=1024]
    mgemm<64, EPI_BIAS | EPI_RESID><<<dim3(DQ / 64, BL / 128), 256, SM64>>>(
        p_yh, p_owh, out_b, x, p_x2, DQ, DI);

    // 8. k = LN(LN(x2)) -> fp32
    ln2_kernel<<<BL / 8, 256>>>(p_x2, n2_w, n2_b, kn_w, kn_b, p_k, nullptr);

    // 9. basis -> fp16
    basis_kernel<<<(BL * DQ + 255) / 256, 256>>>(p_k, grid, p_bh);

    // 10. out = x2 + basis @ spl_w^T  [4096 x 512, K=4096]
    mgemm<64, EPI_RESID><<<dim3(DQ / 64, BL / 128), 256, SM64>>>(
        p_bh, p_swh, nullptr, p_x2, out, DQ, 4096);

    (void)in_sizes; (void)n_in; (void)out_size;
}

// round 9
// speedup vs baseline: 6.5301x; 1.0067x over previous
#include <cuda_runtime.h>
#include <cuda_fp16.h>
#include <math.h>
#include <stdint.h>

// Problem constants
#define BQ 2
#define LQ 2048
#define DQ 512
#define DI 1024
#define BL (BQ*LQ)          // 4096 rows
#define DSTATE 16
#define NG 8
#define TC 128              // scan chunk length
#define NCH (LQ/TC)         // 16 chunks

// ---------------- device scratch ---------------------------------------------
__device__ float g_xz[(size_t)BL*2048];      // in_proj output (xm | z), fp32
__device__ float g_xc[(size_t)BL*DI];        // conv+silu
__device__ float g_dbc[BL*64];               // x_proj output
__device__ float g_delta[(size_t)BL*DI];     // softplus(dt_proj)
__device__ float g_x2[BL*DQ];                // x + mix

__device__ float g_P[(size_t)BQ*NCH*DI*DSTATE];  // chunk products
__device__ float g_S[(size_t)BQ*NCH*DI*DSTATE];  // chunk local end states
__device__ float g_H[(size_t)BQ*NCH*DI*DSTATE];  // chunk initial states

__device__ __half g_uh[(size_t)BL*DQ];           // ln2(x) fp16
__device__ __half g_iwh[2048*DQ];                // in_w fp16
__device__ __half g_yh[(size_t)BL*DI];           // scan out fp16
__device__ __half g_owh[DQ*DI];                  // out_w fp16
__device__ __half g_bh[(size_t)BL*4096];         // KAN basis fp16
__device__ __half g_swh[DQ*4096];                // spl_w fp16

// ---------------- PTX helpers (sm_80-class, valid on sm_100) ------------------
#define CP_ASYNC16(s, g) \
    asm volatile("cp.async.cg.shared.global [%0], [%1], 16;" :: "r"(s), "l"(g))
#define CP_COMMIT() asm volatile("cp.async.commit_group;" ::: "memory")
#define CP_WAIT(n)  asm volatile("cp.async.wait_group %0;" :: "n"(n) : "memory")

__device__ __forceinline__ void ldsm4(uint32_t* r, uint32_t addr) {
    asm volatile("ldmatrix.sync.aligned.m8n8.x4.shared.b16 {%0,%1,%2,%3}, [%4];"
                 : "=r"(r[0]), "=r"(r[1]), "=r"(r[2]), "=r"(r[3]) : "r"(addr));
}
__device__ __forceinline__ void mma_f16(float* c, const uint32_t* a, const uint32_t* b) {
    asm volatile("mma.sync.aligned.m16n8k16.row.col.f32.f16.f16.f32 "
                 "{%0,%1,%2,%3}, {%4,%5,%6,%7}, {%8,%9}, {%0,%1,%2,%3};"
                 : "+f"(c[0]), "+f"(c[1]), "+f"(c[2]), "+f"(c[3])
                 : "r"(a[0]), "r"(a[1]), "r"(a[2]), "r"(a[3]),
                   "r"(b[0]), "r"(b[1]));
}

// ---------------- epilogue flags ---------------------------------------------
#define EPI_BIAS 1
#define EPI_RESID 2
#define EPI_SOFTPLUS 4

// ---------------- fp16 NT GEMM via mma.sync, 3-stage pipeline -----------------
// C[M,N] = A[M,K] * B[N,K]^T, fp32 accum. Block tile 128 x 128, K chunks of 32.
#define MG_STRIDE 80
#define MG_A 10240                 // 128 * 80
#define MG_STAGE (2 * MG_A)        // A + B per stage
#define MG_SMEM (3 * MG_STAGE)     // 61440

template<int EPI>
__global__ __launch_bounds__(256, 2)
void mgemm(const __half* __restrict__ Ah, const __half* __restrict__ Bh,
           const float* __restrict__ bias, const float* __restrict__ resid,
           float* __restrict__ C, int N, int K) {
    extern __shared__ __align__(128) char smem[];
    uint32_t sb = (uint32_t)__cvta_generic_to_shared(smem);
    int tid = threadIdx.x;
    int lane = tid & 31, warp = tid >> 5;
    int bm = blockIdx.y * 128, bn = blockIdx.x * 128;
    int wm = (warp >> 2) * 64;
    int wn = (warp & 3) * 32;

    int nc = K / 32;

    auto issue = [&](int c) {
        int k0 = c * 32;
        uint32_t bufb = sb + (uint32_t)(c % 3) * MG_STAGE;
        #pragma unroll
        for (int i = 0; i < 2; i++) {
            int idx = tid + i * 256;
            int row = idx >> 2, seg = idx & 3;
            CP_ASYNC16(bufb + row * MG_STRIDE + seg * 16,
                       Ah + (size_t)(bm + row) * K + k0 + seg * 8);
        }
        #pragma unroll
        for (int i = 0; i < 2; i++) {
            int idx = tid + i * 256;
            int row = idx >> 2, seg = idx & 3;
            CP_ASYNC16(bufb + MG_A + row * MG_STRIDE + seg * 16,
                       Bh + (size_t)(bn + row) * K + k0 + seg * 8);
        }
        CP_COMMIT();
    };

    float acc[4][4][4];
    #pragma unroll
    for (int mt = 0; mt < 4; mt++)
        #pragma unroll
        for (int nt = 0; nt < 4; nt++)
            #pragma unroll
            for (int q = 0; q < 4; q++) acc[mt][nt][q] = 0.f;

    issue(0); issue(1); issue(2);

    for (int c = 0; c < nc; c++) {
        int left = nc - 1 - c;
        if (left >= 2)      { CP_WAIT(2); }
        else if (left == 1) { CP_WAIT(1); }
        else                { CP_WAIT(0); }
        __syncthreads();
        uint32_t base = sb + (uint32_t)(c % 3) * MG_STAGE;
        uint32_t rsel = (lane & 15) * MG_STRIDE;
        #pragma unroll
        for (int kst = 0; kst < 2; kst++) {
            uint32_t kb = kst * 32 + (lane >> 4) * 16;
            uint32_t bf[4][2], af[4][4];
            #pragma unroll
            for (int p = 0; p < 2; p++) {
                uint32_t r[4];
                ldsm4(r, base + MG_A + (wn + p * 16) * MG_STRIDE + rsel + kb);
                bf[p*2][0] = r[0]; bf[p*2][1] = r[2];
                bf[p*2+1][0] = r[1]; bf[p*2+1][1] = r[3];
            }
            #pragma unroll
            for (int mt = 0; mt < 4; mt++)
                ldsm4(af[mt], base + (wm + mt * 16) * MG_STRIDE + rsel + kb);
            #pragma unroll
            for (int mt = 0; mt < 4; mt++)
                #pragma unroll
                for (int nt = 0; nt < 4; nt++)
                    mma_f16(acc[mt][nt], af[mt], bf[nt]);
        }
        __syncthreads();
        if (c + 3 < nc) issue(c + 3);
    }

    // epilogue
    int g = lane >> 2, tig = lane & 3;
    #pragma unroll
    for (int mt = 0; mt < 4; mt++) {
        size_t r0 = (size_t)bm + wm + mt * 16 + g;
        size_t r1 = r0 + 8;
        #pragma unroll
        for (int nt = 0; nt < 4; nt++) {
            int col = bn + wn + nt * 8 + tig * 2;
            float2 v0 = make_float2(acc[mt][nt][0], acc[mt][nt][1]);
            float2 v1 = make_float2(acc[mt][nt][2], acc[mt][nt][3]);
            if (EPI & EPI_BIAS) {
                float b0 = bias[col], b1 = bias[col + 1];
                v0.x += b0; v0.y += b1; v1.x += b0; v1.y += b1;
            }
            if (EPI & EPI_RESID) {
                const float* rp0 = resid + r0 * N + col;
                const float* rp1 = resid + r1 * N + col;
                v0.x += rp0[0]; v0.y += rp0[1];
                v1.x += rp1[0]; v1.y += rp1[1];
            }
            *(float2*)(C + r0 * N + col) = v0;
            *(float2*)(C + r1 * N + col) = v1;
        }
    }
}

// ---------------- double-LN core (warp computes one 512-row in regs) ----------
__device__ __forceinline__ void ln2_core(float4 v[4], int lane,
                                         const float* __restrict__ w1,
                                         const float* __restrict__ b1,
                                         const float* __restrict__ w2,
                                         const float* __restrict__ b2) {
    #pragma unroll
    for (int pass = 0; pass < 2; pass++) {
        const float* wz = pass ? w2 : w1;
        const float* bz = pass ? b2 : b1;
        float s = 0.f;
        #pragma unroll
        for (int i = 0; i < 4; i++) s += v[i].x + v[i].y + v[i].z + v[i].w;
        #pragma unroll
        for (int o = 16; o > 0; o >>= 1) s += __shfl_xor_sync(0xffffffffu, s, o);
        float mu = s * (1.f / DQ);
        float q = 0.f;
        #pragma unroll
        for (int i = 0; i < 4; i++) {
            float a = v[i].x - mu, b = v[i].y - mu, c = v[i].z - mu, d = v[i].w - mu;
            q += a * a + b * b + c * c + d * d;
        }
        #pragma unroll
        for (int o = 16; o > 0; o >>= 1) q += __shfl_xor_sync(0xffffffffu, q, o);
        float rs = rsqrtf(q * (1.f / DQ) + 1e-5f);
        #pragma unroll
        for (int i = 0; i < 4; i++) {
            float4 w = ((const float4*)wz)[lane + i * 32];
            float4 b = ((const float4*)bz)[lane + i * 32];
            v[i].x = (v[i].x - mu) * rs * w.x + b.x;
            v[i].y = (v[i].y - mu) * rs * w.y + b.y;
            v[i].z = (v[i].z - mu) * rs * w.z + b.z;
            v[i].w = (v[i].w - mu) * rs * w.w + b.w;
        }
    }
}

// ---------------- ln2 -> fp16 (for in_proj input) -----------------------------
__global__ __launch_bounds__(256)
void ln2_kernel(const float* __restrict__ x,
                const float* __restrict__ w1, const float* __restrict__ b1,
                const float* __restrict__ w2, const float* __restrict__ b2,
                __half* __restrict__ oh) {
    int lane = threadIdx.x & 31;
    int row = blockIdx.x * 8 + (threadIdx.x >> 5);
    const float4* xr = (const float4*)(x + (size_t)row * DQ);
    float4 v[4];
    #pragma unroll
    for (int i = 0; i < 4; i++) v[i] = xr[lane + i * 32];
    ln2_core(v, lane, w1, b1, w2, b2);
    __half2* hp = (__half2*)(oh + (size_t)row * DQ);
    #pragma unroll
    for (int i = 0; i < 4; i++) {
        int j = (lane + i * 32) * 2;
        hp[j + 0] = __halves2half2(__float2half_rn(v[i].x), __float2half_rn(v[i].y));
        hp[j + 1] = __halves2half2(__float2half_rn(v[i].z), __float2half_rn(v[i].w));
    }
}

// ---------------- fused ln2 + KAN basis -> fp16 -------------------------------
// basis = sech2((k - g)*INV) = 4e/(1+e)^2, e = E*c_g, E = exp(-2k*INV)
__global__ __launch_bounds__(256)
void ln2_basis_kernel(const float* __restrict__ x,
                      const float* __restrict__ w1, const float* __restrict__ b1,
                      const float* __restrict__ w2, const float* __restrict__ b2,
                      const float* __restrict__ grid,
                      __half* __restrict__ bh) {
    const float INV = 1.0f / 0.33f;
    int lane = threadIdx.x & 31;
    int row = blockIdx.x * 8 + (threadIdx.x >> 5);
    const float4* xr = (const float4*)(x + (size_t)row * DQ);
    float4 v[4];
    #pragma unroll
    for (int i = 0; i < 4; i++) v[i] = xr[lane + i * 32];
    ln2_core(v, lane, w1, b1, w2, b2);

    float cg[8];
    #pragma unroll
    for (int g = 0; g < 8; g++) cg[g] = __expf(2.f * __ldg(grid + g) * INV);

    __half* brow = bh + (size_t)row * 4096;
    #pragma unroll
    for (int i = 0; i < 4; i++) {
        float kv4[4] = {v[i].x, v[i].y, v[i].z, v[i].w};
        #pragma unroll
        for (int c = 0; c < 4; c++) {
            float kv = fminf(fmaxf(kv4[c], -14.f), 14.f);
            float E = __expf(-2.f * kv * INV);
            int d = (lane + i * 32) * 4 + c;
            __half hs[8];
            #pragma unroll
            for (int g = 0; g < 8; g++) {
                float e = E * cg[g];
                float op = 1.f + e;
                float val = (e > 1e30f) ? 0.f : __fdividef(4.f * e, op * op);
                hs[g] = __float2half_rn(val);
            }
            *(uint4*)(brow + d * 8) = *(uint4*)hs;
        }
    }
}

// ---------------- merged fp32 -> fp16 weight convert --------------------------
#define W1N (2048*DQ/4)
#define W2N (DQ*DI/4)
#define W3N (DQ*4096/4)
__global__ void wconv_kernel(const float* __restrict__ s1, __half* __restrict__ h1,
                             const float* __restrict__ s2, __half* __restrict__ h2,
                             const float* __restrict__ s3, __half* __restrict__ h3) {
    int i = blockIdx.x * 256 + threadIdx.x;
    const float* s; __half* h; int j;
    if (i < W1N)            { s = s1; h = h1; j = i; }
    else if (i < W1N + W2N) { s = s2; h = h2; j = i - W1N; }
    else if (i < W1N + W2N + W3N) { s = s3; h = h3; j = i - W1N - W2N; }
    else return;
    float4 v = ((const float4*)s)[j];
    __half2* hp = (__half2*)h;
    hp[2 * j + 0] = __halves2half2(__float2half_rn(v.x), __float2half_rn(v.y));
    hp[2 * j + 1] = __halves2half2(__float2half_rn(v.z), __float2half_rn(v.w));
}

// ---------------- fp32 SGEMM 128x128 (dt_proj, K=32) --------------------------
template<int EPI>
__global__ __launch_bounds__(256, 2)
void sgemm128(const float* __restrict__ A, const float* __restrict__ B,
              const float* __restrict__ bias, const float* __restrict__ resid,
              float* __restrict__ C, int N, int K, int lda, int ldb) {
    const int TK = 16;
    __shared__ __align__(16) float As[2][TK][128 + 4];
    __shared__ __align__(16) float Bs[2][TK][128 + 4];

    int tid = threadIdx.x;
    int bm = blockIdx.y * 128;
    int bn = blockIdx.x * 128;
    int arow = tid >> 2;
    int acol = (tid & 3) << 2;
    int tmb = (tid >> 4) << 3;
    int tnb = (tid & 15) << 3;

    const float* Ap0 = A + (size_t)(bm + arow) * lda + acol;
    const float* Ap1 = A + (size_t)(bm + arow + 64) * lda + acol;
    const float* Bp0 = B + (size_t)(bn + arow) * ldb + acol;
    const float* Bp1 = B + (size_t)(bn + arow + 64) * ldb + acol;

    float4 ra0 = *(const float4*)(Ap0);
    float4 ra1 = *(const float4*)(Ap1);
    float4 rb0 = *(const float4*)(Bp0);
    float4 rb1 = *(const float4*)(Bp1);
    As[0][acol+0][arow] = ra0.x; As[0][acol+1][arow] = ra0.y;
    As[0][acol+2][arow] = ra0.z; As[0][acol+3][arow] = ra0.w;
    As[0][acol+0][arow+64] = ra1.x; As[0][acol+1][arow+64] = ra1.y;
    As[0][acol+2][arow+64] = ra1.z; As[0][acol+3][arow+64] = ra1.w;
    Bs[0][acol+0][arow] = rb0.x; Bs[0][acol+1][arow] = rb0.y;
    Bs[0][acol+2][arow] = rb0.z; Bs[0][acol+3][arow] = rb0.w;
    Bs[0][acol+0][arow+64] = rb1.x; Bs[0][acol+1][arow+64] = rb1.y;
    Bs[0][acol+2][arow+64] = rb1.z; Bs[0][acol+3][arow+64] = rb1.w;
    __syncthreads();

    float acc[8][8];
    #pragma unroll
    for (int i = 0; i < 8; i++)
        #pragma unroll
        for (int j = 0; j < 8; j++) acc[i][j] = 0.f;

    int nk = K / TK;
    for (int it = 0; it < nk; it++) {
        int cur = it & 1, nxt = cur ^ 1;
        bool more = (it + 1 < nk);
        if (more) {
            int ko = (it + 1) * TK;
            ra0 = *(const float4*)(Ap0 + ko);
            ra1 = *(const float4*)(Ap1 + ko);
            rb0 = *(const float4*)(Bp0 + ko);
            rb1 = *(const float4*)(Bp1 + ko);
        }
        #pragma unroll
        for (int kk = 0; kk < TK; kk++) {
            float a[8], b[8];
            float4 a0 = *(const float4*)&As[cur][kk][tmb];
            float4 a1 = *(const float4*)&As[cur][kk][tmb + 4];
            float4 b0 = *(const float4*)&Bs[cur][kk][tnb];
            float4 b1 = *(const float4*)&Bs[cur][kk][tnb + 4];
            a[0]=a0.x;a[1]=a0.y;a[2]=a0.z;a[3]=a0.w;a[4]=a1.x;a[5]=a1.y;a[6]=a1.z;a[7]=a1.w;
            b[0]=b0.x;b[1]=b0.y;b[2]=b0.z;b[3]=b0.w;b[4]=b1.x;b[5]=b1.y;b[6]=b1.z;b[7]=b1.w;
            #pragma unroll
            for (int i = 0; i < 8; i++)
                #pragma unroll
                for (int j = 0; j < 8; j++)
                    acc[i][j] = fmaf(a[i], b[j], acc[i][j]);
        }
        if (more) {
            As[nxt][acol+0][arow] = ra0.x; As[nxt][acol+1][arow] = ra0.y;
            As[nxt][acol+2][arow] = ra0.z; As[nxt][acol+3][arow] = ra0.w;
            As[nxt][acol+0][arow+64] = ra1.x; As[nxt][acol+1][arow+64] = ra1.y;
            As[nxt][acol+2][arow+64] = ra1.z; As[nxt][acol+3][arow+64] = ra1.w;
            Bs[nxt][acol+0][arow] = rb0.x; Bs[nxt][acol+1][arow] = rb0.y;
            Bs[nxt][acol+2][arow] = rb0.z; Bs[nxt][acol+3][arow] = rb0.w;
            Bs[nxt][acol+0][arow+64] = rb1.x; Bs[nxt][acol+1][arow+64] = rb1.y;
            Bs[nxt][acol+2][arow+64] = rb1.z; Bs[nxt][acol+3][arow+64] = rb1.w;
        }
        __syncthreads();
    }

    #pragma unroll
    for (int i = 0; i < 8; i++) {
        size_t row = bm + tmb + i;
        #pragma unroll
        for (int j = 0; j < 8; j++) {
            int col = bn + tnb + j;
            float v = acc[i][j];
            if (EPI & EPI_BIAS)     v += bias[col];
            if (EPI & EPI_SOFTPLUS) v = (v > 20.f) ? v : log1pf(__expf(v));
            if (EPI & EPI_RESID)    v += resid[row * N + col];
            C[row * N + col] = v;
        }
    }
}

// ---------------- x_proj: [4096,1024] x [64,1024]^T, 16 rows/CTA --------------
__global__ __launch_bounds__(256)
void xproj_kernel(const float* __restrict__ A, const float* __restrict__ B,
                  float* __restrict__ C) {
    __shared__ float As[16][68];
    __shared__ float Bs[64][68];
    int tid = threadIdx.x;
    int r0 = blockIdx.x * 16;
    int rr = tid >> 4;
    int ccq = tid & 15;
    float acc[4] = {0.f, 0.f, 0.f, 0.f};

    for (int k0 = 0; k0 < 1024; k0 += 64) {
        {
            int row = tid >> 4, seg = tid & 15;
            *(float4*)&As[row][seg * 4] =
                *(const float4*)(A + (size_t)(r0 + row) * 1024 + k0 + seg * 4);
        }
        #pragma unroll
        for (int i = 0; i < 4; i++) {
            int idx = tid + i * 256;
            int row = idx >> 4, seg = idx & 15;
            *(float4*)&Bs[row][seg * 4] =
                *(const float4*)(B + (size_t)row * 1024 + k0 + seg * 4);
        }
        __syncthreads();
        #pragma unroll 4
        for (int kk = 0; kk < 64; kk += 4) {
            float4 a = *(float4*)&As[rr][kk];
            #pragma unroll
            for (int j = 0; j < 4; j++) {
                float4 b = *(float4*)&Bs[ccq + 16 * j][kk];
                acc[j] = fmaf(a.x, b.x, acc[j]);
                acc[j] = fmaf(a.y, b.y, acc[j]);
                acc[j] = fmaf(a.z, b.z, acc[j]);
                acc[j] = fmaf(a.w, b.w, acc[j]);
            }
        }
        __syncthreads();
    }
    #pragma unroll
    for (int j = 0; j < 4; j++)
        C[(size_t)(r0 + rr) * 64 + ccq + 16 * j] = acc[j];
}

// ---------------- causal depthwise conv (k=4) + silu, float4 ------------------
__global__ void conv_silu_kernel(const float* __restrict__ xz,
                                 const float* __restrict__ cw,
                                 const float* __restrict__ cb,
                                 float* __restrict__ xc) {
    int i4 = blockIdx.x * 256 + threadIdx.x;
    if (i4 >= BL * DI / 4) return;
    int d4 = (i4 & 255) * 4;
    int row = i4 >> 8;
    int l = row & (LQ - 1);

    float4 c0 = *(const float4*)(cw + (d4 + 0) * 4);
    float4 c1 = *(const float4*)(cw + (d4 + 1) * 4);
    float4 c2 = *(const float4*)(cw + (d4 + 2) * 4);
    float4 c3 = *(const float4*)(cw + (d4 + 3) * 4);
    float4 acc = *(const float4*)(cb + d4);

    #pragma unroll
    for (int j = 0; j < 4; j++) {
        if (l - 3 + j >= 0) {
            float4 v = *(const float4*)(xz + (size_t)(row - 3 + j) * 2048 + d4);
            acc.x = fmaf(v.x, (&c0.x)[j], acc.x);
            acc.y = fmaf(v.y, (&c1.x)[j], acc.y);
            acc.z = fmaf(v.z, (&c2.x)[j], acc.z);
            acc.w = fmaf(v.w, (&c3.x)[j], acc.w);
        }
    }
    acc.x *= 1.f / (1.f + __expf(-acc.x));
    acc.y *= 1.f / (1.f + __expf(-acc.y));
    acc.z *= 1.f / (1.f + __expf(-acc.z));
    acc.w *= 1.f / (1.f + __expf(-acc.w));
    *(float4*)(xc + (size_t)row * DI + d4) = acc;
}

// ---------------- chunked scan, pass 1 ---------------------------------------
__global__ __launch_bounds__(256)
void scan1_kernel(const float* __restrict__ delta_sp,
                  const float* __restrict__ xc,
                  const float* __restrict__ dbc,
                  const float* __restrict__ A_log,
                  float* __restrict__ Pout, float* __restrict__ Sout) {
    __shared__ float s_dl[TC][16];
    __shared__ float s_xv[TC][16];
    __shared__ float s_B[TC][16];
    int bx = blockIdx.x;
    int dt = bx & 63;
    int c  = (bx >> 6) & 15;
    int b  = bx >> 10;
    int tid = threadIdx.x;
    int n = tid & 15, dloc = tid >> 4;
    int d = dt * 16 + dloc;
    size_t row0 = (size_t)b * LQ + c * TC;

    #pragma unroll
    for (int i = 0; i < 2; i++) {
        int idx = tid + i * 256;
        int t = idx >> 2, q = idx & 3;
        *(float4*)&s_dl[t][q * 4] = *(const float4*)(delta_sp + (row0 + t) * DI + dt * 16 + q * 4);
        *(float4*)&s_xv[t][q * 4] = *(const float4*)(xc + (row0 + t) * DI + dt * 16 + q * 4);
        *(float4*)&s_B[t][q * 4]  = *(const float4*)(dbc + (row0 + t) * 64 + 32 + q * 4);
    }
    __syncthreads();

    float An = -__expf(A_log[d * DSTATE + n]);
    float h = 0.f, P = 1.f;
    #pragma unroll 4
    for (int t = 0; t < TC; t++) {
        float dl = s_dl[t][dloc];
        float dA = __expf(dl * An);
        h = fmaf(dA, h, dl * s_B[t][n] * s_xv[t][dloc]);
        P *= dA;
    }
    size_t o = (((size_t)b * NCH + c) * DI + (size_t)dt * 16) * DSTATE + tid;
    Pout[o] = P;
    Sout[o] = h;
}

// ---------------- chunked scan: carry (prefetched) ----------------------------
__global__ void scan_carry_kernel(const float* __restrict__ P,
                                  const float* __restrict__ S,
                                  float* __restrict__ H) {
    int idx = blockIdx.x * 256 + threadIdx.x;
    int b = idx >> 14;
    int rem = idx & 16383;
    float Pv[NCH], Sv[NCH];
    #pragma unroll
    for (int c = 0; c < NCH; c++) {
        size_t o = (((size_t)b * NCH + c) << 14) + rem;
        Pv[c] = P[o];
        Sv[c] = S[o];
    }
    float carry = 0.f;
    #pragma unroll
    for (int c = 0; c < NCH; c++) {
        size_t o = (((size_t)b * NCH + c) << 14) + rem;
        H[o] = carry;
        carry = fmaf(Pv[c], carry, Sv[c]);
    }
}

// ---------------- chunked scan, pass 2: fp16 out -------------------------------
__global__ __launch_bounds__(256)
void scan2_kernel(const float* __restrict__ delta_sp,
                  const float* __restrict__ xc,
                  const float* __restrict__ dbc,
                  const float* __restrict__ xz,
                  const float* __restrict__ A_log,
                  const float* __restrict__ D_param,
                  const float* __restrict__ H,
                  __half* __restrict__ yh) {
    __shared__ float s_dl[TC][16];
    __shared__ float s_xv[TC][16];
    __shared__ float s_B[TC][16];
    __shared__ float s_C[TC][16];
    __shared__ float s_y[TC][16];
    int bx = blockIdx.x;
    int dt = bx & 63;
    int c  = (bx >> 6) & 15;
    int b  = bx >> 10;
    int tid = threadIdx.x;
    int n = tid & 15, dloc = tid >> 4;
    int d = dt * 16 + dloc;
    size_t row0 = (size_t)b * LQ + c * TC;

    #pragma unroll
    for (int i = 0; i < 2; i++) {
        int idx = tid + i * 256;
        int t = idx >> 2, q = idx & 3;
        *(float4*)&s_dl[t][q * 4] = *(const float4*)(delta_sp + (row0 + t) * DI + dt * 16 + q * 4);
        *(float4*)&s_xv[t][q * 4] = *(const float4*)(xc + (row0 + t) * DI + dt * 16 + q * 4);
        *(float4*)&s_B[t][q * 4]  = *(const float4*)(dbc + (row0 + t) * 64 + 32 + q * 4);
        *(float4*)&s_C[t][q * 4]  = *(const float4*)(dbc + (row0 + t) * 64 + 48 + q * 4);
    }
    __syncthreads();

    float An = -__expf(A_log[d * DSTATE + n]);
    float Dp = D_param[d];
    size_t o = (((size_t)b * NCH + c) * DI + (size_t)dt * 16) * DSTATE + tid;
    float h = H[o];

    #pragma unroll 4
    for (int t = 0; t < TC; t++) {
        float dl = s_dl[t][dloc];
        float xv = s_xv[t][dloc];
        float dA = __expf(dl * An);
        h = fmaf(dA, h, dl * s_B[t][n] * xv);
        float p = h * s_C[t][n];
        p += __shfl_xor_sync(0xffffffffu, p, 1);
        p += __shfl_xor_sync(0xffffffffu, p, 2);
        p += __shfl_xor_sync(0xffffffffu, p, 4);
        p += __shfl_xor_sync(0xffffffffu, p, 8);
        if (n == 0) s_y[t][dloc] = p + Dp * xv;
    }
    __syncthreads();

    #pragma unroll
    for (int i = 0; i < 8; i++) {
        int idx = tid + i * 256;
        int t = idx >> 4, dl2 = idx & 15;
        size_t row = row0 + t;
        float zv = xz[row * 2048 + DI + dt * 16 + dl2];
        float sz = zv / (1.f + __expf(-zv));
        yh[row * DI + dt * 16 + dl2] = __float2half_rn(s_y[t][dl2] * sz);
    }
}

// ---------------- host orchestration ------------------------------------------
extern "C" void kernel_launch(void* const* d_in, const int* in_sizes, int n_in,
                              void* d_out, int out_size) {
    const float* x      = (const float*)d_in[0];
    const float* n1_w   = (const float*)d_in[1];
    const float* n1_b   = (const float*)d_in[2];
    const float* mn_w   = (const float*)d_in[3];
    const float* mn_b   = (const float*)d_in[4];
    const float* in_w   = (const float*)d_in[5];
    const float* in_b   = (const float*)d_in[6];
    const float* conv_w = (const float*)d_in[7];
    const float* conv_b = (const float*)d_in[8];
    const float* xp_w   = (const float*)d_in[9];
    const float* dt_w   = (const float*)d_in[10];
    const float* dt_b   = (const float*)d_in[11];
    const float* A_log  = (const float*)d_in[12];
    const float* D_par  = (const float*)d_in[13];
    const float* out_w  = (const float*)d_in[14];
    const float* out_b  = (const float*)d_in[15];
    const float* n2_w   = (const float*)d_in[16];
    const float* n2_b   = (const float*)d_in[17];
    const float* kn_w   = (const float*)d_in[18];
    const float* kn_b   = (const float*)d_in[19];
    const float* grid   = (const float*)d_in[20];
    const float* spl_w  = (const float*)d_in[21];
    float* out = (float*)d_out;

    float *p_xz, *p_xc, *p_dbc, *p_delta, *p_x2, *p_P, *p_S, *p_H;
    __half *p_uh, *p_iwh, *p_yh, *p_owh, *p_bh, *p_swh;
    cudaGetSymbolAddress((void**)&p_xz,    g_xz);
    cudaGetSymbolAddress((void**)&p_xc,    g_xc);
    cudaGetSymbolAddress((void**)&p_dbc,   g_dbc);
    cudaGetSymbolAddress((void**)&p_delta, g_delta);
    cudaGetSymbolAddress((void**)&p_x2,    g_x2);
    cudaGetSymbolAddress((void**)&p_P,     g_P);
    cudaGetSymbolAddress((void**)&p_S,     g_S);
    cudaGetSymbolAddress((void**)&p_H,     g_H);
    cudaGetSymbolAddress((void**)&p_uh,  g_uh);
    cudaGetSymbolAddress((void**)&p_iwh, g_iwh);
    cudaGetSymbolAddress((void**)&p_yh,  g_yh);
    cudaGetSymbolAddress((void**)&p_owh, g_owh);
    cudaGetSymbolAddress((void**)&p_bh,  g_bh);
    cudaGetSymbolAddress((void**)&p_swh, g_swh);

    cudaFuncSetAttribute(mgemm<EPI_BIAS>,
                         cudaFuncAttributeMaxDynamicSharedMemorySize, MG_SMEM);
    cudaFuncSetAttribute(mgemm<EPI_BIAS | EPI_RESID>,
                         cudaFuncAttributeMaxDynamicSharedMemorySize, MG_SMEM);
    cudaFuncSetAttribute(mgemm<EPI_RESID>,
                         cudaFuncAttributeMaxDynamicSharedMemorySize, MG_SMEM);

    // merged weight conversion (in_w, out_w, spl_w -> fp16)
    wconv_kernel<<<(W1N + W2N + W3N + 255) / 256, 256>>>(
        in_w, p_iwh, out_w, p_owh, spl_w, p_swh);

    // 1. u = LN(LN(x)) -> fp16
    ln2_kernel<<<BL / 8, 256>>>(x, n1_w, n1_b, mn_w, mn_b, p_uh);

    // 2. xz = u @ in_w^T + in_b   [4096 x 2048, K=512]
    mgemm<EPI_BIAS><<<dim3(2048 / 128, BL / 128), 256, MG_SMEM>>>(
        p_uh, p_iwh, in_b, nullptr, p_xz, 2048, DQ);

    // 3. conv + silu
    conv_silu_kernel<<<(BL * DI / 4) / 256, 256>>>(p_xz, conv_w, conv_b, p_xc);

    // 4. dbc = xc @ xp_w^T  [4096 x 64, K=1024]
    xproj_kernel<<<BL / 16, 256>>>(p_xc, xp_w, p_dbc);

    // 5. delta = softplus(dt_proj)  [4096 x 1024, K=32]
    sgemm128<EPI_BIAS | EPI_SOFTPLUS><<<dim3(DI / 128, BL / 128), 256>>>(
        p_dbc, dt_w, dt_b, nullptr, p_delta, DI, 32, 64, 32);

    // 6. chunked parallel scan -> y fp16
    scan1_kernel<<<BQ * NCH * 64, 256>>>(p_delta, p_xc, p_dbc, A_log, p_P, p_S);
    scan_carry_kernel<<<(BQ * DI * DSTATE) / 256, 256>>>(p_P, p_S, p_H);
    scan2_kernel<<<BQ * NCH * 64, 256>>>(p_delta, p_xc, p_dbc, p_xz, A_log, D_par,
                                         p_H, p_yh);

    // 7. x2 = x + y @ out_w^T + out_b  [4096 x 512, K=1024]
    mgemm<EPI_BIAS | EPI_RESID><<<dim3(DQ / 128, BL / 128), 256, MG_SMEM>>>(
        p_yh, p_owh, out_b, x, p_x2, DQ, DI);

    // 8+9. basis = sech2 of LN(LN(x2)) -> fp16 (fused)
    ln2_basis_kernel<<<BL / 8, 256>>>(p_x2, n2_w, n2_b, kn_w, kn_b, grid, p_bh);

    // 10. out = x2 + basis @ spl_w^T  [4096 x 512, K=4096]
    mgemm<EPI_RESID><<<dim3(DQ / 128, BL / 128), 256, MG_SMEM>>>(
        p_bh, p_swh, nullptr, p_x2, out, DQ, 4096);

    (void)in_sizes; (void)n_in; (void)out_size;
}